// round 2
// baseline (speedup 1.0000x reference)
#include <cuda_runtime.h>
#include <math.h>

// Problem constants
#define PB   2
#define PS   2048
#define PHID 2048
#define PH   16
#define PD   128
#define PM   (PB * PS)          // 4096 rows
#define QSCALE 11.313708498984760f   // sqrt(128)

// Scratch (no cudaMalloc allowed)
__device__ float g_q[(size_t)PM * PHID];
__device__ float g_k[(size_t)PM * PHID];
__device__ float g_v[(size_t)PM * PHID];
__device__ float g_ctx[(size_t)PM * PHID];

// ---------------------------------------------------------------------------
// SGEMM: C[M,N] = (A[M,K] @ W[K,N] + bias[N]) * scale      (row-major, fp32)
// 128x128 tile, BK=16, 256 threads, 8x8 per thread.
// ---------------------------------------------------------------------------
__global__ __launch_bounds__(256) void sgemm_bias(
    const float* __restrict__ A, const float* __restrict__ W,
    const float* __restrict__ bias, float* __restrict__ C,
    int M, int N, int K, float scale)
{
    __shared__ float As[16][132];   // transposed A tile: As[k][m]
    __shared__ float Bs[16][128];   // Bs[k][n]

    int tid = threadIdx.x;
    int m0 = blockIdx.y * 128;
    int n0 = blockIdx.x * 128;
    int ty = tid >> 4;          // 0..15
    int tx = tid & 15;          // 0..15

    int arow = tid >> 2;        // 0..63
    int acol = (tid & 3) << 2;  // 0,4,8,12
    int brow = tid >> 5;        // 0..7
    int bcol = (tid & 31) << 2; // 0..124

    float acc[8][8];
#pragma unroll
    for (int i = 0; i < 8; i++)
#pragma unroll
        for (int j = 0; j < 8; j++) acc[i][j] = 0.0f;

    const float* Ap0 = A + (size_t)(m0 + arow) * K + acol;
    const float* Ap1 = A + (size_t)(m0 + arow + 64) * K + acol;

    for (int k0 = 0; k0 < K; k0 += 16) {
        float4 a0 = *(const float4*)(Ap0 + k0);
        float4 a1 = *(const float4*)(Ap1 + k0);
        float4 b0 = *(const float4*)(W + (size_t)(k0 + brow) * N + n0 + bcol);
        float4 b1 = *(const float4*)(W + (size_t)(k0 + brow + 8) * N + n0 + bcol);

        As[acol + 0][arow] = a0.x;
        As[acol + 1][arow] = a0.y;
        As[acol + 2][arow] = a0.z;
        As[acol + 3][arow] = a0.w;
        As[acol + 0][arow + 64] = a1.x;
        As[acol + 1][arow + 64] = a1.y;
        As[acol + 2][arow + 64] = a1.z;
        As[acol + 3][arow + 64] = a1.w;
        *(float4*)&Bs[brow][bcol]     = b0;
        *(float4*)&Bs[brow + 8][bcol] = b1;
        __syncthreads();

#pragma unroll
        for (int kk = 0; kk < 16; kk++) {
            float4 av0 = *(const float4*)&As[kk][ty * 8];
            float4 av1 = *(const float4*)&As[kk][ty * 8 + 4];
            float4 bv0 = *(const float4*)&Bs[kk][tx * 8];
            float4 bv1 = *(const float4*)&Bs[kk][tx * 8 + 4];
            float a8[8] = {av0.x, av0.y, av0.z, av0.w, av1.x, av1.y, av1.z, av1.w};
            float b8[8] = {bv0.x, bv0.y, bv0.z, bv0.w, bv1.x, bv1.y, bv1.z, bv1.w};
#pragma unroll
            for (int i = 0; i < 8; i++)
#pragma unroll
                for (int j = 0; j < 8; j++)
                    acc[i][j] += a8[i] * b8[j];
        }
        __syncthreads();
    }

    float4 bia0 = *(const float4*)(bias + n0 + tx * 8);
    float4 bia1 = *(const float4*)(bias + n0 + tx * 8 + 4);
    float bi[8] = {bia0.x, bia0.y, bia0.z, bia0.w, bia1.x, bia1.y, bia1.z, bia1.w};
#pragma unroll
    for (int i = 0; i < 8; i++) {
        size_t row = (size_t)(m0 + ty * 8 + i);
        float out8[8];
#pragma unroll
        for (int j = 0; j < 8; j++) out8[j] = (acc[i][j] + bi[j]) * scale;
        float4 o0 = make_float4(out8[0], out8[1], out8[2], out8[3]);
        float4 o1 = make_float4(out8[4], out8[5], out8[6], out8[7]);
        *(float4*)(C + row * N + n0 + tx * 8)     = o0;
        *(float4*)(C + row * N + n0 + tx * 8 + 4) = o1;
    }
}

// ---------------------------------------------------------------------------
// Flash-style attention, fp32.
// Block: one (b,h), 64 query rows.  Loops over 64-row K/V tiles with online
// softmax.  Q is pre-scaled by sqrt(D) in the projection GEMM.
// smem: qT[128][72], kT[128][72], v[64][132], p[64][68]  = 124,928 B
// Threads: 256.  Score phase: thread(ty,tx) -> rows ty*4..+4, cols tx*4..+4.
// PV phase:     thread(ty,tx) -> rows ty*4..+4, d cols tx*8..+8.
// ---------------------------------------------------------------------------
#define ATTN_SMEM_FLOATS (128 * 72 * 2 + 64 * 132 + 64 * 68)

__global__ __launch_bounds__(256) void attn_kernel(
    const float* __restrict__ Qg, const float* __restrict__ Kg,
    const float* __restrict__ Vg, const float* __restrict__ Bias,
    float* __restrict__ Ctx)
{
    extern __shared__ float sm[];
    float* qT = sm;                    // [128][72]  (d-major, row minor)
    float* kT = qT + 128 * 72;         // [128][72]
    float* vs = kT + 128 * 72;         // [64][132]
    float* ps = vs + 64 * 132;         // [64][68]

    int tid = threadIdx.x;
    int ty = tid >> 4;                 // 0..15
    int tx = tid & 15;                 // 0..15
    int ty4 = ty * 4, tx4 = tx * 4, tx8 = tx * 8;

    int bh = blockIdx.y;               // 0..31
    int b  = bh >> 4;
    int h  = bh & 15;
    int q0 = blockIdx.x * 64;

    const float* qbase = Qg + (size_t)b * PS * PHID + h * PD;
    const float* kbase = Kg + (size_t)b * PS * PHID + h * PD;
    const float* vbase = Vg + (size_t)b * PS * PHID + h * PD;
    const float* biasbase = Bias + ((size_t)bh * PS + q0) * PS;

    // Load Q tile transposed into smem
    for (int idx = tid; idx < 64 * 32; idx += 256) {
        int r = idx >> 5;
        int d = (idx & 31) << 2;
        float4 t = *(const float4*)(qbase + (size_t)(q0 + r) * PHID + d);
        qT[(d + 0) * 72 + r] = t.x;
        qT[(d + 1) * 72 + r] = t.y;
        qT[(d + 2) * 72 + r] = t.z;
        qT[(d + 3) * 72 + r] = t.w;
    }

    float m_r[4], l_r[4], o[4][8];
#pragma unroll
    for (int i = 0; i < 4; i++) {
        m_r[i] = -1e30f;
        l_r[i] = 0.0f;
#pragma unroll
        for (int d = 0; d < 8; d++) o[i][d] = 0.0f;
    }

    for (int k0 = 0; k0 < PS; k0 += 64) {
        __syncthreads();   // prior-iteration consumers done (and qT ready, iter 0)

        // Load K tile (transposed) and V tile
        for (int idx = tid; idx < 64 * 32; idx += 256) {
            int r = idx >> 5;
            int d = (idx & 31) << 2;
            float4 t = *(const float4*)(kbase + (size_t)(k0 + r) * PHID + d);
            kT[(d + 0) * 72 + r] = t.x;
            kT[(d + 1) * 72 + r] = t.y;
            kT[(d + 2) * 72 + r] = t.z;
            kT[(d + 3) * 72 + r] = t.w;
            float4 u = *(const float4*)(vbase + (size_t)(k0 + r) * PHID + d);
            *(float4*)&vs[r * 132 + d] = u;
        }
        __syncthreads();

        // Scores: s = q·k + bias   (q pre-scaled)
        float s[4][4];
#pragma unroll
        for (int i = 0; i < 4; i++) {
            float4 bb = *(const float4*)(biasbase + (size_t)(ty4 + i) * PS + k0 + tx4);
            s[i][0] = bb.x; s[i][1] = bb.y; s[i][2] = bb.z; s[i][3] = bb.w;
        }
#pragma unroll 8
        for (int kk = 0; kk < 128; kk++) {
            float4 a  = *(const float4*)&qT[kk * 72 + ty4];
            float4 bb = *(const float4*)&kT[kk * 72 + tx4];
            float av[4] = {a.x, a.y, a.z, a.w};
            float bv[4] = {bb.x, bb.y, bb.z, bb.w};
#pragma unroll
            for (int i = 0; i < 4; i++)
#pragma unroll
                for (int j = 0; j < 4; j++)
                    s[i][j] += av[i] * bv[j];
        }

        // Online softmax update (rows shared by 16 lanes of a half-warp)
        float alpha[4];
#pragma unroll
        for (int i = 0; i < 4; i++) {
            float mx = fmaxf(fmaxf(s[i][0], s[i][1]), fmaxf(s[i][2], s[i][3]));
#pragma unroll
            for (int off = 8; off >= 1; off >>= 1)
                mx = fmaxf(mx, __shfl_xor_sync(0xffffffffu, mx, off));
            float mnew = fmaxf(m_r[i], mx);
            alpha[i] = __expf(m_r[i] - mnew);
            m_r[i] = mnew;
            float lsum = 0.0f;
#pragma unroll
            for (int j = 0; j < 4; j++) {
                s[i][j] = __expf(s[i][j] - mnew);
                lsum += s[i][j];
            }
#pragma unroll
            for (int off = 8; off >= 1; off >>= 1)
                lsum += __shfl_xor_sync(0xffffffffu, lsum, off);
            l_r[i] = l_r[i] * alpha[i] + lsum;
            *(float4*)&ps[(ty4 + i) * 68 + tx4] =
                make_float4(s[i][0], s[i][1], s[i][2], s[i][3]);
        }
        __syncthreads();

#pragma unroll
        for (int i = 0; i < 4; i++)
#pragma unroll
            for (int d = 0; d < 8; d++) o[i][d] *= alpha[i];

        // O += P @ V
#pragma unroll 2
        for (int j = 0; j < 64; j += 4) {
            float pr[4][4];
#pragma unroll
            for (int i = 0; i < 4; i++) {
                float4 t = *(const float4*)&ps[(ty4 + i) * 68 + j];
                pr[i][0] = t.x; pr[i][1] = t.y; pr[i][2] = t.z; pr[i][3] = t.w;
            }
#pragma unroll
            for (int jj = 0; jj < 4; jj++) {
                float4 va = *(const float4*)&vs[(j + jj) * 132 + tx8];
                float4 vb = *(const float4*)&vs[(j + jj) * 132 + tx8 + 4];
                float v8[8] = {va.x, va.y, va.z, va.w, vb.x, vb.y, vb.z, vb.w};
#pragma unroll
                for (int i = 0; i < 4; i++) {
                    float p = pr[i][jj];
#pragma unroll
                    for (int d = 0; d < 8; d++) o[i][d] += p * v8[d];
                }
            }
        }
    }

    // Normalize and write ctx[b, q, h, d]
#pragma unroll
    for (int i = 0; i < 4; i++) {
        float inv = 1.0f / l_r[i];
        size_t row = (size_t)b * PS + q0 + ty4 + i;
        float* dst = Ctx + row * PHID + h * PD + tx8;
        float4 o0 = make_float4(o[i][0] * inv, o[i][1] * inv, o[i][2] * inv, o[i][3] * inv);
        float4 o1 = make_float4(o[i][4] * inv, o[i][5] * inv, o[i][6] * inv, o[i][7] * inv);
        *(float4*)dst       = o0;
        *(float4*)(dst + 4) = o1;
    }
}

// ---------------------------------------------------------------------------
extern "C" void kernel_launch(void* const* d_in, const int* in_sizes, int n_in,
                              void* d_out, int out_size)
{
    (void)in_sizes; (void)n_in; (void)out_size;
    const float* x    = (const float*)d_in[0];
    const float* bias = (const float*)d_in[1];
    const float* Wq   = (const float*)d_in[2];
    const float* bq   = (const float*)d_in[3];
    const float* Wk   = (const float*)d_in[4];
    const float* bk   = (const float*)d_in[5];
    const float* Wv   = (const float*)d_in[6];
    const float* bv   = (const float*)d_in[7];
    const float* Wo   = (const float*)d_in[8];
    const float* bo   = (const float*)d_in[9];
    float* out = (float*)d_out;

    float *q, *k, *v, *ctx;
    cudaGetSymbolAddress((void**)&q,   g_q);
    cudaGetSymbolAddress((void**)&k,   g_k);
    cudaGetSymbolAddress((void**)&v,   g_v);
    cudaGetSymbolAddress((void**)&ctx, g_ctx);

    static bool attr_set = false;
    if (!attr_set) {
        cudaFuncSetAttribute(attn_kernel,
                             cudaFuncAttributeMaxDynamicSharedMemorySize,
                             ATTN_SMEM_FLOATS * (int)sizeof(float));
        attr_set = true;
    }

    dim3 ggrid(PHID / 128, PM / 128);   // (16, 32)
    sgemm_bias<<<ggrid, 256>>>(x, Wq, bq, q, PM, PHID, PHID, QSCALE);
    sgemm_bias<<<ggrid, 256>>>(x, Wk, bk, k, PM, PHID, PHID, 1.0f);
    sgemm_bias<<<ggrid, 256>>>(x, Wv, bv, v, PM, PHID, PHID, 1.0f);

    dim3 agrid(PS / 64, PB * PH);       // (32, 32)
    attn_kernel<<<agrid, 256, ATTN_SMEM_FLOATS * sizeof(float)>>>(q, k, v, bias, ctx);

    sgemm_bias<<<ggrid, 256>>>(ctx, Wo, bo, out, PM, PHID, PHID, 1.0f);
}

// round 4
// speedup vs baseline: 1.4134x; 1.4134x over previous
#include <cuda_runtime.h>
#include <cuda_bf16.h>
#include <math.h>
#include <stdint.h>

// Problem constants
#define PB   2
#define PS   2048
#define PHID 2048
#define PH   16
#define PD   128
#define PM   (PB * PS)          // 4096 rows
#define QSCALE 11.313708498984760f   // sqrt(128)

// ---------------------------------------------------------------------------
// Scratch (no cudaMalloc allowed)
// ---------------------------------------------------------------------------
__device__ float g_q[(size_t)PM * PHID];
__device__ float g_k[(size_t)PM * PHID];
__device__ float g_v[(size_t)PM * PHID];
__device__ float g_ctx[(size_t)PM * PHID];

// split-bf16 activations (row-major [M,K])
__device__ __nv_bfloat16 g_xh[(size_t)PM * PHID];
__device__ __nv_bfloat16 g_xl[(size_t)PM * PHID];
__device__ __nv_bfloat16 g_ch[(size_t)PM * PHID];
__device__ __nv_bfloat16 g_cl[(size_t)PM * PHID];

// split-bf16 transposed weights [N,K]
__device__ __nv_bfloat16 g_wqh[(size_t)PHID * PHID];
__device__ __nv_bfloat16 g_wql[(size_t)PHID * PHID];
__device__ __nv_bfloat16 g_wkh[(size_t)PHID * PHID];
__device__ __nv_bfloat16 g_wkl[(size_t)PHID * PHID];
__device__ __nv_bfloat16 g_wvh[(size_t)PHID * PHID];
__device__ __nv_bfloat16 g_wvl[(size_t)PHID * PHID];
__device__ __nv_bfloat16 g_woh[(size_t)PHID * PHID];
__device__ __nv_bfloat16 g_wol[(size_t)PHID * PHID];

// ---------------------------------------------------------------------------
// Helpers
// ---------------------------------------------------------------------------
__device__ __forceinline__ uint32_t smem_u32(const void* p) {
    uint32_t a;
    asm("{ .reg .u64 t; cvta.to.shared.u64 t, %1; cvt.u32.u64 %0, t; }"
        : "=r"(a) : "l"(p));
    return a;
}

__device__ __forceinline__ void cp16(uint32_t s, const void* g) {
    asm volatile("cp.async.cg.shared.global [%0], [%1], 16;" :: "r"(s), "l"(g));
}
#define CP_COMMIT() asm volatile("cp.async.commit_group;" ::: "memory")
#define CP_WAIT(n)  asm volatile("cp.async.wait_group %0;" :: "n"(n) : "memory")

__device__ __forceinline__ void ldm_x4(uint32_t* r, uint32_t addr) {
    asm volatile("ldmatrix.sync.aligned.m8n8.x4.shared.b16 {%0,%1,%2,%3}, [%4];"
                 : "=r"(r[0]), "=r"(r[1]), "=r"(r[2]), "=r"(r[3]) : "r"(addr));
}
__device__ __forceinline__ void ldm_x2(uint32_t* r, uint32_t addr) {
    asm volatile("ldmatrix.sync.aligned.m8n8.x2.shared.b16 {%0,%1}, [%2];"
                 : "=r"(r[0]), "=r"(r[1]) : "r"(addr));
}
__device__ __forceinline__ void mma_bf16(float* c, const uint32_t* a, const uint32_t* b) {
    asm volatile(
        "mma.sync.aligned.m16n8k16.row.col.f32.bf16.bf16.f32 "
        "{%0,%1,%2,%3}, {%4,%5,%6,%7}, {%8,%9}, {%0,%1,%2,%3};"
        : "+f"(c[0]), "+f"(c[1]), "+f"(c[2]), "+f"(c[3])
        : "r"(a[0]), "r"(a[1]), "r"(a[2]), "r"(a[3]), "r"(b[0]), "r"(b[1]));
}

// ---------------------------------------------------------------------------
// Conversion kernels: fp32 -> split bf16 (hi + lo)
// ---------------------------------------------------------------------------
__global__ void split_bf16_kernel(const float* __restrict__ in,
                                  __nv_bfloat16* __restrict__ hi,
                                  __nv_bfloat16* __restrict__ lo, int n4)
{
    int i = blockIdx.x * blockDim.x + threadIdx.x;
    if (i >= n4) return;
    float4 v = ((const float4*)in)[i];
    float vv[4] = {v.x, v.y, v.z, v.w};
    __nv_bfloat16 h[4], l[4];
#pragma unroll
    for (int j = 0; j < 4; j++) {
        h[j] = __float2bfloat16(vv[j]);
        l[j] = __float2bfloat16(vv[j] - __bfloat162float(h[j]));
    }
    ((__nv_bfloat162*)hi)[2*i]   = __halves2bfloat162(h[0], h[1]);
    ((__nv_bfloat162*)hi)[2*i+1] = __halves2bfloat162(h[2], h[3]);
    ((__nv_bfloat162*)lo)[2*i]   = __halves2bfloat162(l[0], l[1]);
    ((__nv_bfloat162*)lo)[2*i+1] = __halves2bfloat162(l[2], l[3]);
}

// W[K,N] fp32 -> transposed split bf16 [N,K]
__global__ void transpose_split_kernel(const float* __restrict__ W,
                                       __nv_bfloat16* __restrict__ Th,
                                       __nv_bfloat16* __restrict__ Tl)
{
    __shared__ float t[32][33];
    int n0 = blockIdx.x * 32, k0 = blockIdx.y * 32;
    int tx = threadIdx.x, ty0 = threadIdx.y;   // 32 x 8
#pragma unroll
    for (int j = 0; j < 32; j += 8)
        t[ty0 + j][tx] = W[(size_t)(k0 + ty0 + j) * PHID + n0 + tx];
    __syncthreads();
#pragma unroll
    for (int j = 0; j < 32; j += 8) {
        int n = ty0 + j;
        float v = t[tx][n];                    // W[k0+tx][n0+n]
        __nv_bfloat16 h = __float2bfloat16(v);
        __nv_bfloat16 l = __float2bfloat16(v - __bfloat162float(h));
        size_t o = (size_t)(n0 + n) * PHID + k0 + tx;
        Th[o] = h;
        Tl[o] = l;
    }
}

// ---------------------------------------------------------------------------
// split-bf16 tensor-core GEMM via mma.sync (HMMA path, legal on sm_103 base):
// C[M,N] = (A @ W + bias) * scale, fp32-accurate via hh + hl + lh combos.
// A as Ah/Al [M,K] bf16; W transposed as Bh/Bl [N,K] bf16.
// CTA 128x128, BK=32, 8 warps (2x4), warp tile 64x32 (4x4 m16n8k16 frags).
// Smem: per stage 4 tiles of [128][40] bf16 (80B rows, ldmatrix conflict-free),
// double buffered with cp.async.cg = 81920 B dynamic.
// ---------------------------------------------------------------------------
#define LDT   40                 // padded row length in bf16 elems (80 bytes)
#define TILE_B (128 * LDT * 2)   // 10240 bytes per tile
#define OFF_AH 0
#define OFF_AL (TILE_B)
#define OFF_BH (2 * TILE_B)
#define OFF_BL (3 * TILE_B)
#define STAGE_B (4 * TILE_B)     // 40960
#define GSMEM  (2 * STAGE_B)     // 81920

__global__ __launch_bounds__(256, 1) void gemm_split_mma(
    const __nv_bfloat16* __restrict__ Ah, const __nv_bfloat16* __restrict__ Al,
    const __nv_bfloat16* __restrict__ Bh, const __nv_bfloat16* __restrict__ Bl,
    const float* __restrict__ bias, float* __restrict__ C, float scale)
{
    extern __shared__ char smem[];
    const uint32_t sb = smem_u32(smem);
    const int tid  = threadIdx.x;
    const int lane = tid & 31;
    const int warp = tid >> 5;
    const int wm = warp >> 2;         // 0..1
    const int wn = warp & 3;          // 0..3
    const int m0 = blockIdx.y * 128;
    const int n0 = blockIdx.x * 128;

    const __nv_bfloat16* pAh = Ah + (size_t)m0 * PHID;
    const __nv_bfloat16* pAl = Al + (size_t)m0 * PHID;
    const __nv_bfloat16* pBh = Bh + (size_t)n0 * PHID;
    const __nv_bfloat16* pBl = Bl + (size_t)n0 * PHID;

    // loader mapping: 512 16B-chunks per tile; thread handles 2 per tile
    const int r0 = tid >> 2;            // 0..63
    const int c0 = (tid & 3) * 8;       // elem col
    const uint32_t so0 = (uint32_t)(r0 * 80 + (tid & 3) * 16);
    const uint32_t so1 = (uint32_t)((r0 + 64) * 80 + (tid & 3) * 16);

    // ldmatrix fragment offsets (bytes within a tile)
    const uint32_t a_off = (uint32_t)((wm * 64 + (lane & 15)) * 80 + ((lane >> 4) << 4));
    const uint32_t b_off = (uint32_t)((wn * 32 + (lane & 7)) * 80 + ((lane & 8) ? 16 : 0));

    float acc[4][4][4];
#pragma unroll
    for (int mi = 0; mi < 4; mi++)
#pragma unroll
        for (int ni = 0; ni < 4; ni++)
#pragma unroll
            for (int j = 0; j < 4; j++) acc[mi][ni][j] = 0.0f;

    auto load_stage = [&](int stage, int kc) {
        const uint32_t st = sb + stage * STAGE_B;
        const size_t g0 = (size_t)r0 * PHID + kc * 32 + c0;
        const size_t g1 = (size_t)(r0 + 64) * PHID + kc * 32 + c0;
        cp16(st + OFF_AH + so0, pAh + g0);
        cp16(st + OFF_AH + so1, pAh + g1);
        cp16(st + OFF_AL + so0, pAl + g0);
        cp16(st + OFF_AL + so1, pAl + g1);
        cp16(st + OFF_BH + so0, pBh + g0);
        cp16(st + OFF_BH + so1, pBh + g1);
        cp16(st + OFF_BL + so0, pBl + g0);
        cp16(st + OFF_BL + so1, pBl + g1);
    };

    auto compute_stage = [&](int stage) {
        const uint32_t st = sb + stage * STAGE_B;
#pragma unroll
        for (int ks = 0; ks < 2; ks++) {
            const uint32_t k32 = ks * 32;
            uint32_t bh[4][2], bl[4][2], a[4][4];
#pragma unroll
            for (int ni = 0; ni < 4; ni++)
                ldm_x2(bh[ni], st + OFF_BH + b_off + ni * 640 + k32);
#pragma unroll
            for (int ni = 0; ni < 4; ni++)
                ldm_x2(bl[ni], st + OFF_BL + b_off + ni * 640 + k32);
#pragma unroll
            for (int mi = 0; mi < 4; mi++)
                ldm_x4(a[mi], st + OFF_AH + a_off + mi * 1280 + k32);
#pragma unroll
            for (int mi = 0; mi < 4; mi++)
#pragma unroll
                for (int ni = 0; ni < 4; ni++)
                    mma_bf16(acc[mi][ni], a[mi], bh[ni]);
#pragma unroll
            for (int mi = 0; mi < 4; mi++)
#pragma unroll
                for (int ni = 0; ni < 4; ni++)
                    mma_bf16(acc[mi][ni], a[mi], bl[ni]);
#pragma unroll
            for (int mi = 0; mi < 4; mi++)
                ldm_x4(a[mi], st + OFF_AL + a_off + mi * 1280 + k32);
#pragma unroll
            for (int mi = 0; mi < 4; mi++)
#pragma unroll
                for (int ni = 0; ni < 4; ni++)
                    mma_bf16(acc[mi][ni], a[mi], bh[ni]);
        }
    };

    load_stage(0, 0);
    CP_COMMIT();
    const int NKC = PHID / 32;   // 64
    for (int kc = 0; kc < NKC; kc++) {
        if (kc + 1 < NKC) {
            load_stage((kc + 1) & 1, kc + 1);
            CP_COMMIT();
            CP_WAIT(1);
        } else {
            CP_WAIT(0);
        }
        __syncthreads();
        compute_stage(kc & 1);
        __syncthreads();
    }

    // Epilogue: write 4x4 fragments
#pragma unroll
    for (int mi = 0; mi < 4; mi++) {
        const int row = m0 + wm * 64 + mi * 16 + (lane >> 2);
#pragma unroll
        for (int ni = 0; ni < 4; ni++) {
            const int col = n0 + wn * 32 + ni * 8 + (lane & 3) * 2;
            const float b0 = bias[col], b1 = bias[col + 1];
            float2 v0 = make_float2((acc[mi][ni][0] + b0) * scale,
                                    (acc[mi][ni][1] + b1) * scale);
            float2 v1 = make_float2((acc[mi][ni][2] + b0) * scale,
                                    (acc[mi][ni][3] + b1) * scale);
            *(float2*)(C + (size_t)row * PHID + col)       = v0;
            *(float2*)(C + (size_t)(row + 8) * PHID + col) = v1;
        }
    }
}

// ---------------------------------------------------------------------------
// Flash-style attention, fp32 (unchanged).
// ---------------------------------------------------------------------------
#define ATTN_SMEM_FLOATS (128 * 72 * 2 + 64 * 132 + 64 * 68)

__global__ __launch_bounds__(256) void attn_kernel(
    const float* __restrict__ Qg, const float* __restrict__ Kg,
    const float* __restrict__ Vg, const float* __restrict__ Bias,
    float* __restrict__ Ctx)
{
    extern __shared__ float sm[];
    float* qT = sm;                    // [128][72]
    float* kT = qT + 128 * 72;         // [128][72]
    float* vs = kT + 128 * 72;         // [64][132]
    float* ps = vs + 64 * 132;         // [64][68]

    int tid = threadIdx.x;
    int ty = tid >> 4;
    int tx = tid & 15;
    int ty4 = ty * 4, tx4 = tx * 4, tx8 = tx * 8;

    int bh = blockIdx.y;
    int b  = bh >> 4;
    int h  = bh & 15;
    int q0 = blockIdx.x * 64;

    const float* qbase = Qg + (size_t)b * PS * PHID + h * PD;
    const float* kbase = Kg + (size_t)b * PS * PHID + h * PD;
    const float* vbase = Vg + (size_t)b * PS * PHID + h * PD;
    const float* biasbase = Bias + ((size_t)bh * PS + q0) * PS;

    for (int idx = tid; idx < 64 * 32; idx += 256) {
        int r = idx >> 5;
        int d = (idx & 31) << 2;
        float4 t = *(const float4*)(qbase + (size_t)(q0 + r) * PHID + d);
        qT[(d + 0) * 72 + r] = t.x;
        qT[(d + 1) * 72 + r] = t.y;
        qT[(d + 2) * 72 + r] = t.z;
        qT[(d + 3) * 72 + r] = t.w;
    }

    float m_r[4], l_r[4], o[4][8];
#pragma unroll
    for (int i = 0; i < 4; i++) {
        m_r[i] = -1e30f;
        l_r[i] = 0.0f;
#pragma unroll
        for (int d = 0; d < 8; d++) o[i][d] = 0.0f;
    }

    for (int k0 = 0; k0 < PS; k0 += 64) {
        __syncthreads();

        for (int idx = tid; idx < 64 * 32; idx += 256) {
            int r = idx >> 5;
            int d = (idx & 31) << 2;
            float4 t = *(const float4*)(kbase + (size_t)(k0 + r) * PHID + d);
            kT[(d + 0) * 72 + r] = t.x;
            kT[(d + 1) * 72 + r] = t.y;
            kT[(d + 2) * 72 + r] = t.z;
            kT[(d + 3) * 72 + r] = t.w;
            float4 u = *(const float4*)(vbase + (size_t)(k0 + r) * PHID + d);
            *(float4*)&vs[r * 132 + d] = u;
        }
        __syncthreads();

        float s[4][4];
#pragma unroll
        for (int i = 0; i < 4; i++) {
            float4 bb = *(const float4*)(biasbase + (size_t)(ty4 + i) * PS + k0 + tx4);
            s[i][0] = bb.x; s[i][1] = bb.y; s[i][2] = bb.z; s[i][3] = bb.w;
        }
#pragma unroll 8
        for (int kk = 0; kk < 128; kk++) {
            float4 a  = *(const float4*)&qT[kk * 72 + ty4];
            float4 bb = *(const float4*)&kT[kk * 72 + tx4];
            float av[4] = {a.x, a.y, a.z, a.w};
            float bv[4] = {bb.x, bb.y, bb.z, bb.w};
#pragma unroll
            for (int i = 0; i < 4; i++)
#pragma unroll
                for (int j = 0; j < 4; j++)
                    s[i][j] += av[i] * bv[j];
        }

        float alpha[4];
#pragma unroll
        for (int i = 0; i < 4; i++) {
            float mx = fmaxf(fmaxf(s[i][0], s[i][1]), fmaxf(s[i][2], s[i][3]));
#pragma unroll
            for (int off = 8; off >= 1; off >>= 1)
                mx = fmaxf(mx, __shfl_xor_sync(0xffffffffu, mx, off));
            float mnew = fmaxf(m_r[i], mx);
            alpha[i] = __expf(m_r[i] - mnew);
            m_r[i] = mnew;
            float lsum = 0.0f;
#pragma unroll
            for (int j = 0; j < 4; j++) {
                s[i][j] = __expf(s[i][j] - mnew);
                lsum += s[i][j];
            }
#pragma unroll
            for (int off = 8; off >= 1; off >>= 1)
                lsum += __shfl_xor_sync(0xffffffffu, lsum, off);
            l_r[i] = l_r[i] * alpha[i] + lsum;
            *(float4*)&ps[(ty4 + i) * 68 + tx4] =
                make_float4(s[i][0], s[i][1], s[i][2], s[i][3]);
        }
        __syncthreads();

#pragma unroll
        for (int i = 0; i < 4; i++)
#pragma unroll
            for (int d = 0; d < 8; d++) o[i][d] *= alpha[i];

#pragma unroll 2
        for (int j = 0; j < 64; j += 4) {
            float pr[4][4];
#pragma unroll
            for (int i = 0; i < 4; i++) {
                float4 t = *(const float4*)&ps[(ty4 + i) * 68 + j];
                pr[i][0] = t.x; pr[i][1] = t.y; pr[i][2] = t.z; pr[i][3] = t.w;
            }
#pragma unroll
            for (int jj = 0; jj < 4; jj++) {
                float4 va = *(const float4*)&vs[(j + jj) * 132 + tx8];
                float4 vb = *(const float4*)&vs[(j + jj) * 132 + tx8 + 4];
                float v8[8] = {va.x, va.y, va.z, va.w, vb.x, vb.y, vb.z, vb.w};
#pragma unroll
                for (int i = 0; i < 4; i++) {
                    float p = pr[i][jj];
#pragma unroll
                    for (int d = 0; d < 8; d++) o[i][d] += p * v8[d];
                }
            }
        }
    }

#pragma unroll
    for (int i = 0; i < 4; i++) {
        float inv = 1.0f / l_r[i];
        size_t row = (size_t)b * PS + q0 + ty4 + i;
        float* dst = Ctx + row * PHID + h * PD + tx8;
        float4 o0 = make_float4(o[i][0] * inv, o[i][1] * inv, o[i][2] * inv, o[i][3] * inv);
        float4 o1 = make_float4(o[i][4] * inv, o[i][5] * inv, o[i][6] * inv, o[i][7] * inv);
        *(float4*)dst       = o0;
        *(float4*)(dst + 4) = o1;
    }
}

// ---------------------------------------------------------------------------
extern "C" void kernel_launch(void* const* d_in, const int* in_sizes, int n_in,
                              void* d_out, int out_size)
{
    (void)in_sizes; (void)n_in; (void)out_size;
    const float* x    = (const float*)d_in[0];
    const float* bias = (const float*)d_in[1];
    const float* Wq   = (const float*)d_in[2];
    const float* bq   = (const float*)d_in[3];
    const float* Wk   = (const float*)d_in[4];
    const float* bk   = (const float*)d_in[5];
    const float* Wv   = (const float*)d_in[6];
    const float* bv   = (const float*)d_in[7];
    const float* Wo   = (const float*)d_in[8];
    const float* bo   = (const float*)d_in[9];
    float* out = (float*)d_out;

    float *q, *k, *v, *ctx;
    cudaGetSymbolAddress((void**)&q,   g_q);
    cudaGetSymbolAddress((void**)&k,   g_k);
    cudaGetSymbolAddress((void**)&v,   g_v);
    cudaGetSymbolAddress((void**)&ctx, g_ctx);

    __nv_bfloat16 *xh, *xl, *ch, *cl;
    __nv_bfloat16 *wqh, *wql, *wkh, *wkl, *wvh, *wvl, *woh, *wol;
    cudaGetSymbolAddress((void**)&xh, g_xh);
    cudaGetSymbolAddress((void**)&xl, g_xl);
    cudaGetSymbolAddress((void**)&ch, g_ch);
    cudaGetSymbolAddress((void**)&cl, g_cl);
    cudaGetSymbolAddress((void**)&wqh, g_wqh);
    cudaGetSymbolAddress((void**)&wql, g_wql);
    cudaGetSymbolAddress((void**)&wkh, g_wkh);
    cudaGetSymbolAddress((void**)&wkl, g_wkl);
    cudaGetSymbolAddress((void**)&wvh, g_wvh);
    cudaGetSymbolAddress((void**)&wvl, g_wvl);
    cudaGetSymbolAddress((void**)&woh, g_woh);
    cudaGetSymbolAddress((void**)&wol, g_wol);

    static bool attr_set = false;
    if (!attr_set) {
        cudaFuncSetAttribute(attn_kernel,
                             cudaFuncAttributeMaxDynamicSharedMemorySize,
                             ATTN_SMEM_FLOATS * (int)sizeof(float));
        cudaFuncSetAttribute(gemm_split_mma,
                             cudaFuncAttributeMaxDynamicSharedMemorySize, GSMEM);
        attr_set = true;
    }

    // 1) convert inputs to split-bf16
    {
        int n4 = PM * PHID / 4;
        split_bf16_kernel<<<(n4 + 255) / 256, 256>>>(x, xh, xl, n4);
        dim3 tg(PHID / 32, PHID / 32);
        dim3 tb(32, 8);
        transpose_split_kernel<<<tg, tb>>>(Wq, wqh, wql);
        transpose_split_kernel<<<tg, tb>>>(Wk, wkh, wkl);
        transpose_split_kernel<<<tg, tb>>>(Wv, wvh, wvl);
        transpose_split_kernel<<<tg, tb>>>(Wo, woh, wol);
    }

    // 2) Q/K/V projections on tensor cores (fp32-accurate split-bf16)
    dim3 ggrid(PHID / 128, PM / 128);   // (16, 32)
    gemm_split_mma<<<ggrid, 256, GSMEM>>>(xh, xl, wqh, wql, bq, q, QSCALE);
    gemm_split_mma<<<ggrid, 256, GSMEM>>>(xh, xl, wkh, wkl, bk, k, 1.0f);
    gemm_split_mma<<<ggrid, 256, GSMEM>>>(xh, xl, wvh, wvl, bv, v, 1.0f);

    // 3) attention (fp32)
    dim3 agrid(PS / 64, PB * PH);       // (32, 32)
    attn_kernel<<<agrid, 256, ATTN_SMEM_FLOATS * sizeof(float)>>>(q, k, v, bias, ctx);

    // 4) output projection
    {
        int n4 = PM * PHID / 4;
        split_bf16_kernel<<<(n4 + 255) / 256, 256>>>(ctx, ch, cl, n4);
    }
    gemm_split_mma<<<ggrid, 256, GSMEM>>>(ch, cl, woh, wol, bo, out, 1.0f);
}

// round 5
// speedup vs baseline: 2.9588x; 2.0933x over previous
#include <cuda_runtime.h>
#include <cuda_bf16.h>
#include <math.h>
#include <stdint.h>

// Problem constants
#define PB   2
#define PS   2048
#define PHID 2048
#define PH   16
#define PD   128
#define PM   (PB * PS)          // 4096 rows
#define QSCALE 11.313708498984760f   // sqrt(128)

// ---------------------------------------------------------------------------
// Scratch (no cudaMalloc allowed) — all split-bf16 now
// ---------------------------------------------------------------------------
__device__ __nv_bfloat16 g_xh[(size_t)PM * PHID];
__device__ __nv_bfloat16 g_xl[(size_t)PM * PHID];
__device__ __nv_bfloat16 g_qh[(size_t)PM * PHID];
__device__ __nv_bfloat16 g_ql[(size_t)PM * PHID];
__device__ __nv_bfloat16 g_kh[(size_t)PM * PHID];
__device__ __nv_bfloat16 g_kl[(size_t)PM * PHID];
__device__ __nv_bfloat16 g_vh[(size_t)PM * PHID];
__device__ __nv_bfloat16 g_vl[(size_t)PM * PHID];
__device__ __nv_bfloat16 g_ch[(size_t)PM * PHID];
__device__ __nv_bfloat16 g_cl[(size_t)PM * PHID];

// split-bf16 transposed weights [N,K]
__device__ __nv_bfloat16 g_wqh[(size_t)PHID * PHID];
__device__ __nv_bfloat16 g_wql[(size_t)PHID * PHID];
__device__ __nv_bfloat16 g_wkh[(size_t)PHID * PHID];
__device__ __nv_bfloat16 g_wkl[(size_t)PHID * PHID];
__device__ __nv_bfloat16 g_wvh[(size_t)PHID * PHID];
__device__ __nv_bfloat16 g_wvl[(size_t)PHID * PHID];
__device__ __nv_bfloat16 g_woh[(size_t)PHID * PHID];
__device__ __nv_bfloat16 g_wol[(size_t)PHID * PHID];

// ---------------------------------------------------------------------------
// Helpers
// ---------------------------------------------------------------------------
__device__ __forceinline__ uint32_t smem_u32(const void* p) {
    uint32_t a;
    asm("{ .reg .u64 t; cvta.to.shared.u64 t, %1; cvt.u32.u64 %0, t; }"
        : "=r"(a) : "l"(p));
    return a;
}

__device__ __forceinline__ void cp16(uint32_t s, const void* g) {
    asm volatile("cp.async.cg.shared.global [%0], [%1], 16;" :: "r"(s), "l"(g));
}
#define CP_COMMIT() asm volatile("cp.async.commit_group;" ::: "memory")
#define CP_WAIT(n)  asm volatile("cp.async.wait_group %0;" :: "n"(n) : "memory")

__device__ __forceinline__ void ldm_x4(uint32_t* r, uint32_t addr) {
    asm volatile("ldmatrix.sync.aligned.m8n8.x4.shared.b16 {%0,%1,%2,%3}, [%4];"
                 : "=r"(r[0]), "=r"(r[1]), "=r"(r[2]), "=r"(r[3]) : "r"(addr));
}
__device__ __forceinline__ void ldm_x2(uint32_t* r, uint32_t addr) {
    asm volatile("ldmatrix.sync.aligned.m8n8.x2.shared.b16 {%0,%1}, [%2];"
                 : "=r"(r[0]), "=r"(r[1]) : "r"(addr));
}
__device__ __forceinline__ void ldm_x2t(uint32_t* r, uint32_t addr) {
    asm volatile("ldmatrix.sync.aligned.m8n8.x2.trans.shared.b16 {%0,%1}, [%2];"
                 : "=r"(r[0]), "=r"(r[1]) : "r"(addr));
}
__device__ __forceinline__ void mma_bf16(float* c, const uint32_t* a, const uint32_t* b) {
    asm volatile(
        "mma.sync.aligned.m16n8k16.row.col.f32.bf16.bf16.f32 "
        "{%0,%1,%2,%3}, {%4,%5,%6,%7}, {%8,%9}, {%0,%1,%2,%3};"
        : "+f"(c[0]), "+f"(c[1]), "+f"(c[2]), "+f"(c[3])
        : "r"(a[0]), "r"(a[1]), "r"(a[2]), "r"(a[3]), "r"(b[0]), "r"(b[1]));
}

// pack two floats into split bf16x2 (hi-part word, lo-part word)
__device__ __forceinline__ void packsplit(float a, float b, uint32_t& hp, uint32_t& lp) {
    __nv_bfloat16 ha = __float2bfloat16(a), hb = __float2bfloat16(b);
    float la = a - __bfloat162float(ha);
    float lb = b - __bfloat162float(hb);
    __nv_bfloat162 hv = __halves2bfloat162(ha, hb);
    __nv_bfloat162 lv = __halves2bfloat162(__float2bfloat16(la), __float2bfloat16(lb));
    hp = *reinterpret_cast<uint32_t*>(&hv);
    lp = *reinterpret_cast<uint32_t*>(&lv);
}

// ---------------------------------------------------------------------------
// Conversion kernels
// ---------------------------------------------------------------------------
__global__ void split_bf16_kernel(const float* __restrict__ in,
                                  __nv_bfloat16* __restrict__ hi,
                                  __nv_bfloat16* __restrict__ lo, int n4)
{
    int i = blockIdx.x * blockDim.x + threadIdx.x;
    if (i >= n4) return;
    float4 v = ((const float4*)in)[i];
    float vv[4] = {v.x, v.y, v.z, v.w};
    __nv_bfloat16 h[4], l[4];
#pragma unroll
    for (int j = 0; j < 4; j++) {
        h[j] = __float2bfloat16(vv[j]);
        l[j] = __float2bfloat16(vv[j] - __bfloat162float(h[j]));
    }
    ((__nv_bfloat162*)hi)[2*i]   = __halves2bfloat162(h[0], h[1]);
    ((__nv_bfloat162*)hi)[2*i+1] = __halves2bfloat162(h[2], h[3]);
    ((__nv_bfloat162*)lo)[2*i]   = __halves2bfloat162(l[0], l[1]);
    ((__nv_bfloat162*)lo)[2*i+1] = __halves2bfloat162(l[2], l[3]);
}

__global__ void transpose_split_kernel(const float* __restrict__ W,
                                       __nv_bfloat16* __restrict__ Th,
                                       __nv_bfloat16* __restrict__ Tl)
{
    __shared__ float t[32][33];
    int n0 = blockIdx.x * 32, k0 = blockIdx.y * 32;
    int tx = threadIdx.x, ty0 = threadIdx.y;   // 32 x 8
#pragma unroll
    for (int j = 0; j < 32; j += 8)
        t[ty0 + j][tx] = W[(size_t)(k0 + ty0 + j) * PHID + n0 + tx];
    __syncthreads();
#pragma unroll
    for (int j = 0; j < 32; j += 8) {
        int n = ty0 + j;
        float v = t[tx][n];
        __nv_bfloat16 h = __float2bfloat16(v);
        __nv_bfloat16 l = __float2bfloat16(v - __bfloat162float(h));
        size_t o = (size_t)(n0 + n) * PHID + k0 + tx;
        Th[o] = h;
        Tl[o] = l;
    }
}

// ---------------------------------------------------------------------------
// split-bf16 tensor-core GEMM via mma.sync.
// C mode (C!=null): fp32 out.  Split mode: writes (Oh,Ol) split-bf16.
// ---------------------------------------------------------------------------
#define LDT   40
#define TILE_B (128 * LDT * 2)   // 10240
#define OFF_AH 0
#define OFF_AL (TILE_B)
#define OFF_BH (2 * TILE_B)
#define OFF_BL (3 * TILE_B)
#define STAGE_B (4 * TILE_B)     // 40960
#define GSMEM  (2 * STAGE_B)     // 81920

__global__ __launch_bounds__(256, 1) void gemm_split_mma(
    const __nv_bfloat16* __restrict__ Ah, const __nv_bfloat16* __restrict__ Al,
    const __nv_bfloat16* __restrict__ Bh, const __nv_bfloat16* __restrict__ Bl,
    const float* __restrict__ bias, float* __restrict__ C,
    __nv_bfloat16* __restrict__ Oh, __nv_bfloat16* __restrict__ Ol, float scale)
{
    extern __shared__ char smem[];
    const uint32_t sb = smem_u32(smem);
    const int tid  = threadIdx.x;
    const int lane = tid & 31;
    const int warp = tid >> 5;
    const int wm = warp >> 2;
    const int wn = warp & 3;
    const int m0 = blockIdx.y * 128;
    const int n0 = blockIdx.x * 128;

    const __nv_bfloat16* pAh = Ah + (size_t)m0 * PHID;
    const __nv_bfloat16* pAl = Al + (size_t)m0 * PHID;
    const __nv_bfloat16* pBh = Bh + (size_t)n0 * PHID;
    const __nv_bfloat16* pBl = Bl + (size_t)n0 * PHID;

    const int r0 = tid >> 2;
    const int c0 = (tid & 3) * 8;
    const uint32_t so0 = (uint32_t)(r0 * 80 + (tid & 3) * 16);
    const uint32_t so1 = (uint32_t)((r0 + 64) * 80 + (tid & 3) * 16);

    const uint32_t a_off = (uint32_t)((wm * 64 + (lane & 15)) * 80 + ((lane >> 4) << 4));
    const uint32_t b_off = (uint32_t)((wn * 32 + (lane & 7)) * 80 + ((lane & 8) ? 16 : 0));

    float acc[4][4][4];
#pragma unroll
    for (int mi = 0; mi < 4; mi++)
#pragma unroll
        for (int ni = 0; ni < 4; ni++)
#pragma unroll
            for (int j = 0; j < 4; j++) acc[mi][ni][j] = 0.0f;

    auto load_stage = [&](int stage, int kc) {
        const uint32_t st = sb + stage * STAGE_B;
        const size_t g0 = (size_t)r0 * PHID + kc * 32 + c0;
        const size_t g1 = (size_t)(r0 + 64) * PHID + kc * 32 + c0;
        cp16(st + OFF_AH + so0, pAh + g0);
        cp16(st + OFF_AH + so1, pAh + g1);
        cp16(st + OFF_AL + so0, pAl + g0);
        cp16(st + OFF_AL + so1, pAl + g1);
        cp16(st + OFF_BH + so0, pBh + g0);
        cp16(st + OFF_BH + so1, pBh + g1);
        cp16(st + OFF_BL + so0, pBl + g0);
        cp16(st + OFF_BL + so1, pBl + g1);
    };

    auto compute_stage = [&](int stage) {
        const uint32_t st = sb + stage * STAGE_B;
#pragma unroll
        for (int ks = 0; ks < 2; ks++) {
            const uint32_t k32 = ks * 32;
            uint32_t bh[4][2], bl[4][2], a[4][4];
#pragma unroll
            for (int ni = 0; ni < 4; ni++)
                ldm_x2(bh[ni], st + OFF_BH + b_off + ni * 640 + k32);
#pragma unroll
            for (int ni = 0; ni < 4; ni++)
                ldm_x2(bl[ni], st + OFF_BL + b_off + ni * 640 + k32);
#pragma unroll
            for (int mi = 0; mi < 4; mi++)
                ldm_x4(a[mi], st + OFF_AH + a_off + mi * 1280 + k32);
#pragma unroll
            for (int mi = 0; mi < 4; mi++)
#pragma unroll
                for (int ni = 0; ni < 4; ni++)
                    mma_bf16(acc[mi][ni], a[mi], bh[ni]);
#pragma unroll
            for (int mi = 0; mi < 4; mi++)
#pragma unroll
                for (int ni = 0; ni < 4; ni++)
                    mma_bf16(acc[mi][ni], a[mi], bl[ni]);
#pragma unroll
            for (int mi = 0; mi < 4; mi++)
                ldm_x4(a[mi], st + OFF_AL + a_off + mi * 1280 + k32);
#pragma unroll
            for (int mi = 0; mi < 4; mi++)
#pragma unroll
                for (int ni = 0; ni < 4; ni++)
                    mma_bf16(acc[mi][ni], a[mi], bh[ni]);
        }
    };

    load_stage(0, 0);
    CP_COMMIT();
    const int NKC = PHID / 32;
    for (int kc = 0; kc < NKC; kc++) {
        if (kc + 1 < NKC) {
            load_stage((kc + 1) & 1, kc + 1);
            CP_COMMIT();
            CP_WAIT(1);
        } else {
            CP_WAIT(0);
        }
        __syncthreads();
        compute_stage(kc & 1);
        __syncthreads();
    }

#pragma unroll
    for (int mi = 0; mi < 4; mi++) {
        const int row = m0 + wm * 64 + mi * 16 + (lane >> 2);
#pragma unroll
        for (int ni = 0; ni < 4; ni++) {
            const int col = n0 + wn * 32 + ni * 8 + (lane & 3) * 2;
            const float b0 = bias[col], b1 = bias[col + 1];
            float v00 = (acc[mi][ni][0] + b0) * scale;
            float v01 = (acc[mi][ni][1] + b1) * scale;
            float v10 = (acc[mi][ni][2] + b0) * scale;
            float v11 = (acc[mi][ni][3] + b1) * scale;
            if (C) {
                *(float2*)(C + (size_t)row * PHID + col)       = make_float2(v00, v01);
                *(float2*)(C + (size_t)(row + 8) * PHID + col) = make_float2(v10, v11);
            } else {
                uint32_t hp, lp;
                packsplit(v00, v01, hp, lp);
                *(uint32_t*)(Oh + (size_t)row * PHID + col) = hp;
                *(uint32_t*)(Ol + (size_t)row * PHID + col) = lp;
                packsplit(v10, v11, hp, lp);
                *(uint32_t*)(Oh + (size_t)(row + 8) * PHID + col) = hp;
                *(uint32_t*)(Ol + (size_t)(row + 8) * PHID + col) = lp;
            }
        }
    }
}

// ---------------------------------------------------------------------------
// Tensor-core flash attention (split-bf16, mma.sync).
// CTA: 128 q-rows x one (b,h); 8 warps, each 16 q-rows.
// K-loop: 64-key tiles, double-buffered cp.async.
// Smem rows padded to 136 elems (272B) -> conflict-free ldmatrix.
// ---------------------------------------------------------------------------
#define AT_LDB  272
#define AT_QH   0
#define AT_QL   (128 * AT_LDB)            // 34816
#define AT_ST0  (2 * 128 * AT_LDB)        // 69632
#define AT_TILE (64 * AT_LDB)             // 17408
#define AT_STAGE (4 * AT_TILE)            // 69632
#define AT_SMEM (AT_ST0 + 2 * AT_STAGE)   // 208896

__global__ __launch_bounds__(256, 1) void attn_mma(
    const __nv_bfloat16* __restrict__ Qh, const __nv_bfloat16* __restrict__ Ql,
    const __nv_bfloat16* __restrict__ Kh, const __nv_bfloat16* __restrict__ Kl,
    const __nv_bfloat16* __restrict__ Vh, const __nv_bfloat16* __restrict__ Vl,
    const float* __restrict__ Bias,
    __nv_bfloat16* __restrict__ Ch, __nv_bfloat16* __restrict__ Cl)
{
    extern __shared__ char smem[];
    const uint32_t sb = smem_u32(smem);
    const int tid = threadIdx.x;
    const int lane = tid & 31;
    const int warp = tid >> 5;
    const int bh = blockIdx.y;
    const int b  = bh >> 4;
    const int h  = bh & 15;
    const int q0 = blockIdx.x * 128;

    const size_t base = (size_t)b * PS * PHID + (size_t)h * PD;
    const __nv_bfloat16* pQh = Qh + base + (size_t)q0 * PHID;
    const __nv_bfloat16* pQl = Ql + base + (size_t)q0 * PHID;
    const __nv_bfloat16* pKh = Kh + base;
    const __nv_bfloat16* pKl = Kl + base;
    const __nv_bfloat16* pVh = Vh + base;
    const __nv_bfloat16* pVl = Vl + base;

    // Q loader: per array 2048 16B chunks / 256 thr = 8 each
    {
        const int r = tid >> 1;
        const int ce = (tid & 1) * 64;                  // elem col
        const uint32_t so = (uint32_t)(r * AT_LDB + (tid & 1) * 128);
#pragma unroll
        for (int i = 0; i < 8; i++) {
            cp16(sb + AT_QH + so + i * 16, pQh + (size_t)r * PHID + ce + i * 8);
            cp16(sb + AT_QL + so + i * 16, pQl + (size_t)r * PHID + ce + i * 8);
        }
    }

    // K/V stage loader
    const int kvr  = tid >> 2;
    const int kvce = (tid & 3) * 32;
    const uint32_t kvso = (uint32_t)(kvr * AT_LDB + (tid & 3) * 64);
    auto load_stage = [&](int stage, int t) {
        const uint32_t st = sb + AT_ST0 + stage * AT_STAGE;
        const size_t g = (size_t)(t * 64 + kvr) * PHID + kvce;
#pragma unroll
        for (int i = 0; i < 4; i++) {
            cp16(st + kvso + i * 16,               pKh + g + i * 8);
            cp16(st + AT_TILE + kvso + i * 16,     pKl + g + i * 8);
            cp16(st + 2 * AT_TILE + kvso + i * 16, pVh + g + i * 8);
            cp16(st + 3 * AT_TILE + kvso + i * 16, pVl + g + i * 8);
        }
    };

    load_stage(0, 0);
    CP_COMMIT();
    load_stage(1, 1);
    CP_COMMIT();

    // per-warp ldmatrix base offsets
    const uint32_t q_off = (uint32_t)((warp * 16 + (lane & 15)) * AT_LDB + ((lane >> 4) << 4));
    const uint32_t k_off = (uint32_t)((lane & 7) * AT_LDB + ((lane & 8) ? 16 : 0));
    const uint32_t v_off = (uint32_t)((lane & 15) * AT_LDB);

    // bias row pointers for this thread
    const float* biasR0 = Bias + ((size_t)bh * PS + q0 + warp * 16 + (lane >> 2)) * PS;
    const float* biasR1 = biasR0 + 8 * PS;
    const int bcol = (lane & 3) * 2;

    float o[16][4];
#pragma unroll
    for (int nd = 0; nd < 16; nd++)
#pragma unroll
        for (int j = 0; j < 4; j++) o[nd][j] = 0.0f;
    float m0 = -1e30f, m1 = -1e30f, l0 = 0.0f, l1 = 0.0f;

    const int NT = PS / 64;   // 32
    for (int t = 0; t < NT; t++) {
        if (t < NT - 2) CP_WAIT(1); else CP_WAIT(0);
        __syncthreads();

        const uint32_t st = sb + AT_ST0 + (t & 1) * AT_STAGE;
        const int k0 = t * 64;

        // ---- scores = bias + Q K^T (split 3-combo) ----
        float sc[8][4];
#pragma unroll
        for (int nf = 0; nf < 8; nf++) {
            float2 t0 = *(const float2*)(biasR0 + k0 + nf * 8 + bcol);
            float2 t1 = *(const float2*)(biasR1 + k0 + nf * 8 + bcol);
            sc[nf][0] = t0.x; sc[nf][1] = t0.y; sc[nf][2] = t1.x; sc[nf][3] = t1.y;
        }
#pragma unroll
        for (int ks = 0; ks < 8; ks++) {
            uint32_t qa[4], qla[4];
            ldm_x4(qa,  sb + AT_QH + q_off + ks * 32);
            ldm_x4(qla, sb + AT_QL + q_off + ks * 32);
#pragma unroll
            for (int nf = 0; nf < 8; nf++) {
                uint32_t kbh[2], kbl[2];
                ldm_x2(kbh, st + k_off + nf * 8 * AT_LDB + ks * 32);
                ldm_x2(kbl, st + AT_TILE + k_off + nf * 8 * AT_LDB + ks * 32);
                mma_bf16(sc[nf], qa,  kbh);
                mma_bf16(sc[nf], qa,  kbl);
                mma_bf16(sc[nf], qla, kbh);
            }
        }

        // ---- online softmax ----
        float mx0 = sc[0][0], mx1 = sc[0][2];
#pragma unroll
        for (int nf = 0; nf < 8; nf++) {
            mx0 = fmaxf(mx0, fmaxf(sc[nf][0], sc[nf][1]));
            mx1 = fmaxf(mx1, fmaxf(sc[nf][2], sc[nf][3]));
        }
        mx0 = fmaxf(mx0, __shfl_xor_sync(0xffffffffu, mx0, 1));
        mx0 = fmaxf(mx0, __shfl_xor_sync(0xffffffffu, mx0, 2));
        mx1 = fmaxf(mx1, __shfl_xor_sync(0xffffffffu, mx1, 1));
        mx1 = fmaxf(mx1, __shfl_xor_sync(0xffffffffu, mx1, 2));
        const float mn0 = fmaxf(m0, mx0), mn1 = fmaxf(m1, mx1);
        const float al0 = __expf(m0 - mn0), al1 = __expf(m1 - mn1);
        m0 = mn0; m1 = mn1;
        float s0 = 0.0f, s1 = 0.0f;
#pragma unroll
        for (int nf = 0; nf < 8; nf++) {
            sc[nf][0] = __expf(sc[nf][0] - mn0);
            sc[nf][1] = __expf(sc[nf][1] - mn0);
            sc[nf][2] = __expf(sc[nf][2] - mn1);
            sc[nf][3] = __expf(sc[nf][3] - mn1);
            s0 += sc[nf][0] + sc[nf][1];
            s1 += sc[nf][2] + sc[nf][3];
        }
        s0 += __shfl_xor_sync(0xffffffffu, s0, 1);
        s0 += __shfl_xor_sync(0xffffffffu, s0, 2);
        s1 += __shfl_xor_sync(0xffffffffu, s1, 1);
        s1 += __shfl_xor_sync(0xffffffffu, s1, 2);
        l0 = l0 * al0 + s0;
        l1 = l1 * al1 + s1;
#pragma unroll
        for (int nd = 0; nd < 16; nd++) {
            o[nd][0] *= al0; o[nd][1] *= al0;
            o[nd][2] *= al1; o[nd][3] *= al1;
        }

        // ---- P fragments (split) from score registers ----
        uint32_t pha[4][4], pla[4][4];
#pragma unroll
        for (int j2 = 0; j2 < 4; j2++) {
            const int f0 = 2 * j2, f1 = f0 + 1;
            packsplit(sc[f0][0], sc[f0][1], pha[j2][0], pla[j2][0]);
            packsplit(sc[f0][2], sc[f0][3], pha[j2][1], pla[j2][1]);
            packsplit(sc[f1][0], sc[f1][1], pha[j2][2], pla[j2][2]);
            packsplit(sc[f1][2], sc[f1][3], pha[j2][3], pla[j2][3]);
        }

        // ---- O += P V (split 3-combo), V via ldmatrix.trans ----
#pragma unroll
        for (int j2 = 0; j2 < 4; j2++) {
            const uint32_t vrow = st + 2 * AT_TILE + v_off + j2 * 16 * AT_LDB;
#pragma unroll
            for (int nd = 0; nd < 16; nd++) {
                uint32_t vbh[2], vbl[2];
                ldm_x2t(vbh, vrow + nd * 16);
                ldm_x2t(vbl, vrow + AT_TILE + nd * 16);
                mma_bf16(o[nd], pha[j2], vbh);
                mma_bf16(o[nd], pha[j2], vbl);
                mma_bf16(o[nd], pla[j2], vbh);
            }
        }

        __syncthreads();
        if (t + 2 < NT) {
            load_stage(t & 1, t + 2);
            CP_COMMIT();
        }
    }

    // ---- epilogue: normalize, split, store ctx ----
    const float inv0 = 1.0f / l0, inv1 = 1.0f / l1;
    const int rg0 = q0 + warp * 16 + (lane >> 2);
    __nv_bfloat16* och = Ch + base;
    __nv_bfloat16* ocl = Cl + base;
#pragma unroll
    for (int nd = 0; nd < 16; nd++) {
        const int col = nd * 8 + (lane & 3) * 2;
        uint32_t hp, lp;
        packsplit(o[nd][0] * inv0, o[nd][1] * inv0, hp, lp);
        *(uint32_t*)(och + (size_t)rg0 * PHID + col) = hp;
        *(uint32_t*)(ocl + (size_t)rg0 * PHID + col) = lp;
        packsplit(o[nd][2] * inv1, o[nd][3] * inv1, hp, lp);
        *(uint32_t*)(och + (size_t)(rg0 + 8) * PHID + col) = hp;
        *(uint32_t*)(ocl + (size_t)(rg0 + 8) * PHID + col) = lp;
    }
}

// ---------------------------------------------------------------------------
extern "C" void kernel_launch(void* const* d_in, const int* in_sizes, int n_in,
                              void* d_out, int out_size)
{
    (void)in_sizes; (void)n_in; (void)out_size;
    const float* x    = (const float*)d_in[0];
    const float* bias = (const float*)d_in[1];
    const float* Wq   = (const float*)d_in[2];
    const float* bq   = (const float*)d_in[3];
    const float* Wk   = (const float*)d_in[4];
    const float* bk   = (const float*)d_in[5];
    const float* Wv   = (const float*)d_in[6];
    const float* bv   = (const float*)d_in[7];
    const float* Wo   = (const float*)d_in[8];
    const float* bo   = (const float*)d_in[9];
    float* out = (float*)d_out;

    __nv_bfloat16 *xh, *xl, *qh, *ql, *kh, *kl, *vh, *vl, *ch, *cl;
    __nv_bfloat16 *wqh, *wql, *wkh, *wkl, *wvh, *wvl, *woh, *wol;
    cudaGetSymbolAddress((void**)&xh, g_xh);
    cudaGetSymbolAddress((void**)&xl, g_xl);
    cudaGetSymbolAddress((void**)&qh, g_qh);
    cudaGetSymbolAddress((void**)&ql, g_ql);
    cudaGetSymbolAddress((void**)&kh, g_kh);
    cudaGetSymbolAddress((void**)&kl, g_kl);
    cudaGetSymbolAddress((void**)&vh, g_vh);
    cudaGetSymbolAddress((void**)&vl, g_vl);
    cudaGetSymbolAddress((void**)&ch, g_ch);
    cudaGetSymbolAddress((void**)&cl, g_cl);
    cudaGetSymbolAddress((void**)&wqh, g_wqh);
    cudaGetSymbolAddress((void**)&wql, g_wql);
    cudaGetSymbolAddress((void**)&wkh, g_wkh);
    cudaGetSymbolAddress((void**)&wkl, g_wkl);
    cudaGetSymbolAddress((void**)&wvh, g_wvh);
    cudaGetSymbolAddress((void**)&wvl, g_wvl);
    cudaGetSymbolAddress((void**)&woh, g_woh);
    cudaGetSymbolAddress((void**)&wol, g_wol);

    static bool attr_set = false;
    if (!attr_set) {
        cudaFuncSetAttribute(gemm_split_mma,
                             cudaFuncAttributeMaxDynamicSharedMemorySize, GSMEM);
        cudaFuncSetAttribute(attn_mma,
                             cudaFuncAttributeMaxDynamicSharedMemorySize, AT_SMEM);
        attr_set = true;
    }

    // 1) conversions
    {
        int n4 = PM * PHID / 4;
        split_bf16_kernel<<<(n4 + 255) / 256, 256>>>(x, xh, xl, n4);
        dim3 tg(PHID / 32, PHID / 32);
        dim3 tb(32, 8);
        transpose_split_kernel<<<tg, tb>>>(Wq, wqh, wql);
        transpose_split_kernel<<<tg, tb>>>(Wk, wkh, wkl);
        transpose_split_kernel<<<tg, tb>>>(Wv, wvh, wvl);
        transpose_split_kernel<<<tg, tb>>>(Wo, woh, wol);
    }

    // 2) projections -> split bf16 q/k/v directly
    dim3 ggrid(PHID / 128, PM / 128);
    gemm_split_mma<<<ggrid, 256, GSMEM>>>(xh, xl, wqh, wql, bq, nullptr, qh, ql, QSCALE);
    gemm_split_mma<<<ggrid, 256, GSMEM>>>(xh, xl, wkh, wkl, bk, nullptr, kh, kl, 1.0f);
    gemm_split_mma<<<ggrid, 256, GSMEM>>>(xh, xl, wvh, wvl, bv, nullptr, vh, vl, 1.0f);

    // 3) tensor-core attention -> split bf16 ctx
    dim3 agrid(PS / 128, PB * PH);      // (16, 32)
    attn_mma<<<agrid, 256, AT_SMEM>>>(qh, ql, kh, kl, vh, vl, bias, ch, cl);

    // 4) output projection -> fp32 out
    gemm_split_mma<<<ggrid, 256, GSMEM>>>(ch, cl, woh, wol, bo, out, nullptr, nullptr, 1.0f);
}

// round 6
// speedup vs baseline: 3.1327x; 1.0588x over previous
#include <cuda_runtime.h>
#include <cuda_bf16.h>
#include <math.h>
#include <stdint.h>

// Problem constants
#define PB   2
#define PS   2048
#define PHID 2048
#define PH   16
#define PD   128
#define PM   (PB * PS)          // 4096 rows
#define QSCALE 11.313708498984760f   // sqrt(128)

// ---------------------------------------------------------------------------
// Scratch (no cudaMalloc allowed) — all split-bf16
// ---------------------------------------------------------------------------
__device__ __nv_bfloat16 g_xh[(size_t)PM * PHID];
__device__ __nv_bfloat16 g_xl[(size_t)PM * PHID];
__device__ __nv_bfloat16 g_qh[(size_t)PM * PHID];
__device__ __nv_bfloat16 g_ql[(size_t)PM * PHID];
__device__ __nv_bfloat16 g_kh[(size_t)PM * PHID];
__device__ __nv_bfloat16 g_kl[(size_t)PM * PHID];
__device__ __nv_bfloat16 g_vh[(size_t)PM * PHID];
__device__ __nv_bfloat16 g_vl[(size_t)PM * PHID];
__device__ __nv_bfloat16 g_ch[(size_t)PM * PHID];
__device__ __nv_bfloat16 g_cl[(size_t)PM * PHID];

// split-bf16 transposed weights [N,K]
__device__ __nv_bfloat16 g_wqh[(size_t)PHID * PHID];
__device__ __nv_bfloat16 g_wql[(size_t)PHID * PHID];
__device__ __nv_bfloat16 g_wkh[(size_t)PHID * PHID];
__device__ __nv_bfloat16 g_wkl[(size_t)PHID * PHID];
__device__ __nv_bfloat16 g_wvh[(size_t)PHID * PHID];
__device__ __nv_bfloat16 g_wvl[(size_t)PHID * PHID];
__device__ __nv_bfloat16 g_woh[(size_t)PHID * PHID];
__device__ __nv_bfloat16 g_wol[(size_t)PHID * PHID];

// ---------------------------------------------------------------------------
// Helpers
// ---------------------------------------------------------------------------
__device__ __forceinline__ uint32_t smem_u32(const void* p) {
    uint32_t a;
    asm("{ .reg .u64 t; cvta.to.shared.u64 t, %1; cvt.u32.u64 %0, t; }"
        : "=r"(a) : "l"(p));
    return a;
}

__device__ __forceinline__ void cp16(uint32_t s, const void* g) {
    asm volatile("cp.async.cg.shared.global [%0], [%1], 16;" :: "r"(s), "l"(g));
}
#define CP_COMMIT() asm volatile("cp.async.commit_group;" ::: "memory")
#define CP_WAIT(n)  asm volatile("cp.async.wait_group %0;" :: "n"(n) : "memory")

__device__ __forceinline__ void ldm_x4(uint32_t* r, uint32_t addr) {
    asm volatile("ldmatrix.sync.aligned.m8n8.x4.shared.b16 {%0,%1,%2,%3}, [%4];"
                 : "=r"(r[0]), "=r"(r[1]), "=r"(r[2]), "=r"(r[3]) : "r"(addr));
}
__device__ __forceinline__ void ldm_x2(uint32_t* r, uint32_t addr) {
    asm volatile("ldmatrix.sync.aligned.m8n8.x2.shared.b16 {%0,%1}, [%2];"
                 : "=r"(r[0]), "=r"(r[1]) : "r"(addr));
}
__device__ __forceinline__ void ldm_x2t(uint32_t* r, uint32_t addr) {
    asm volatile("ldmatrix.sync.aligned.m8n8.x2.trans.shared.b16 {%0,%1}, [%2];"
                 : "=r"(r[0]), "=r"(r[1]) : "r"(addr));
}
__device__ __forceinline__ void mma_bf16(float* c, const uint32_t* a, const uint32_t* b) {
    asm volatile(
        "mma.sync.aligned.m16n8k16.row.col.f32.bf16.bf16.f32 "
        "{%0,%1,%2,%3}, {%4,%5,%6,%7}, {%8,%9}, {%0,%1,%2,%3};"
        : "+f"(c[0]), "+f"(c[1]), "+f"(c[2]), "+f"(c[3])
        : "r"(a[0]), "r"(a[1]), "r"(a[2]), "r"(a[3]), "r"(b[0]), "r"(b[1]));
}

// Fast RNE split of two floats into (hi bf16x2, lo bf16x2). 6 ops, exact RNE.
__device__ __forceinline__ void packsplit(float a, float b, uint32_t& hp, uint32_t& lp) {
    asm("cvt.rn.bf16x2.f32 %0, %1, %2;" : "=r"(hp) : "f"(b), "f"(a));
    float ah = __uint_as_float(hp << 16);
    float bh = __uint_as_float(hp & 0xFFFF0000u);
    float la = a - ah;
    float lb = b - bh;
    asm("cvt.rn.bf16x2.f32 %0, %1, %2;" : "=r"(lp) : "f"(lb), "f"(la));
}

// ---------------------------------------------------------------------------
// Conversion kernels
// ---------------------------------------------------------------------------
__global__ void split_bf16_kernel(const float* __restrict__ in,
                                  __nv_bfloat16* __restrict__ hi,
                                  __nv_bfloat16* __restrict__ lo, int n4)
{
    int i = blockIdx.x * blockDim.x + threadIdx.x;
    if (i >= n4) return;
    float4 v = ((const float4*)in)[i];
    uint32_t h0, l0, h1, l1;
    packsplit(v.x, v.y, h0, l0);
    packsplit(v.z, v.w, h1, l1);
    ((uint32_t*)hi)[2*i]   = h0;
    ((uint32_t*)hi)[2*i+1] = h1;
    ((uint32_t*)lo)[2*i]   = l0;
    ((uint32_t*)lo)[2*i+1] = l1;
}

__global__ void transpose_split_kernel(const float* __restrict__ W,
                                       __nv_bfloat16* __restrict__ Th,
                                       __nv_bfloat16* __restrict__ Tl)
{
    __shared__ float t[32][33];
    int n0 = blockIdx.x * 32, k0 = blockIdx.y * 32;
    int tx = threadIdx.x, ty0 = threadIdx.y;   // 32 x 8
#pragma unroll
    for (int j = 0; j < 32; j += 8)
        t[ty0 + j][tx] = W[(size_t)(k0 + ty0 + j) * PHID + n0 + tx];
    __syncthreads();
#pragma unroll
    for (int j = 0; j < 32; j += 8) {
        int n = ty0 + j;
        float v = t[tx][n];
        __nv_bfloat16 h = __float2bfloat16(v);
        __nv_bfloat16 l = __float2bfloat16(v - __bfloat162float(h));
        size_t o = (size_t)(n0 + n) * PHID + k0 + tx;
        Th[o] = h;
        Tl[o] = l;
    }
}

// ---------------------------------------------------------------------------
// split-bf16 tensor-core GEMM via mma.sync.
// C mode (C!=null): fp32 out.  Split mode: writes (Oh,Ol) split-bf16.
// 2 CTAs/SM (80KB smem each) to hide sync/load latency.
// ---------------------------------------------------------------------------
#define LDT   40
#define TILE_B (128 * LDT * 2)   // 10240
#define OFF_AH 0
#define OFF_AL (TILE_B)
#define OFF_BH (2 * TILE_B)
#define OFF_BL (3 * TILE_B)
#define STAGE_B (4 * TILE_B)     // 40960
#define GSMEM  (2 * STAGE_B)     // 81920

__global__ __launch_bounds__(256, 2) void gemm_split_mma(
    const __nv_bfloat16* __restrict__ Ah, const __nv_bfloat16* __restrict__ Al,
    const __nv_bfloat16* __restrict__ Bh, const __nv_bfloat16* __restrict__ Bl,
    const float* __restrict__ bias, float* __restrict__ C,
    __nv_bfloat16* __restrict__ Oh, __nv_bfloat16* __restrict__ Ol, float scale)
{
    extern __shared__ char smem[];
    const uint32_t sb = smem_u32(smem);
    const int tid  = threadIdx.x;
    const int lane = tid & 31;
    const int warp = tid >> 5;
    const int wm = warp >> 2;
    const int wn = warp & 3;
    const int m0 = blockIdx.y * 128;
    const int n0 = blockIdx.x * 128;

    const __nv_bfloat16* pAh = Ah + (size_t)m0 * PHID;
    const __nv_bfloat16* pAl = Al + (size_t)m0 * PHID;
    const __nv_bfloat16* pBh = Bh + (size_t)n0 * PHID;
    const __nv_bfloat16* pBl = Bl + (size_t)n0 * PHID;

    const int r0 = tid >> 2;
    const int c0 = (tid & 3) * 8;
    const uint32_t so0 = (uint32_t)(r0 * 80 + (tid & 3) * 16);
    const uint32_t so1 = (uint32_t)((r0 + 64) * 80 + (tid & 3) * 16);

    const uint32_t a_off = (uint32_t)((wm * 64 + (lane & 15)) * 80 + ((lane >> 4) << 4));
    const uint32_t b_off = (uint32_t)((wn * 32 + (lane & 7)) * 80 + ((lane & 8) ? 16 : 0));

    float acc[4][4][4];
#pragma unroll
    for (int mi = 0; mi < 4; mi++)
#pragma unroll
        for (int ni = 0; ni < 4; ni++)
#pragma unroll
            for (int j = 0; j < 4; j++) acc[mi][ni][j] = 0.0f;

    auto load_stage = [&](int stage, int kc) {
        const uint32_t st = sb + stage * STAGE_B;
        const size_t g0 = (size_t)r0 * PHID + kc * 32 + c0;
        const size_t g1 = (size_t)(r0 + 64) * PHID + kc * 32 + c0;
        cp16(st + OFF_AH + so0, pAh + g0);
        cp16(st + OFF_AH + so1, pAh + g1);
        cp16(st + OFF_AL + so0, pAl + g0);
        cp16(st + OFF_AL + so1, pAl + g1);
        cp16(st + OFF_BH + so0, pBh + g0);
        cp16(st + OFF_BH + so1, pBh + g1);
        cp16(st + OFF_BL + so0, pBl + g0);
        cp16(st + OFF_BL + so1, pBl + g1);
    };

    auto compute_stage = [&](int stage) {
        const uint32_t st = sb + stage * STAGE_B;
#pragma unroll
        for (int ks = 0; ks < 2; ks++) {
            const uint32_t k32 = ks * 32;
            uint32_t bh[4][2], bl[4][2], a[4][4];
#pragma unroll
            for (int ni = 0; ni < 4; ni++)
                ldm_x2(bh[ni], st + OFF_BH + b_off + ni * 640 + k32);
#pragma unroll
            for (int ni = 0; ni < 4; ni++)
                ldm_x2(bl[ni], st + OFF_BL + b_off + ni * 640 + k32);
#pragma unroll
            for (int mi = 0; mi < 4; mi++)
                ldm_x4(a[mi], st + OFF_AH + a_off + mi * 1280 + k32);
#pragma unroll
            for (int mi = 0; mi < 4; mi++)
#pragma unroll
                for (int ni = 0; ni < 4; ni++)
                    mma_bf16(acc[mi][ni], a[mi], bh[ni]);
#pragma unroll
            for (int mi = 0; mi < 4; mi++)
#pragma unroll
                for (int ni = 0; ni < 4; ni++)
                    mma_bf16(acc[mi][ni], a[mi], bl[ni]);
#pragma unroll
            for (int mi = 0; mi < 4; mi++)
                ldm_x4(a[mi], st + OFF_AL + a_off + mi * 1280 + k32);
#pragma unroll
            for (int mi = 0; mi < 4; mi++)
#pragma unroll
                for (int ni = 0; ni < 4; ni++)
                    mma_bf16(acc[mi][ni], a[mi], bh[ni]);
        }
    };

    load_stage(0, 0);
    CP_COMMIT();
    const int NKC = PHID / 32;
    for (int kc = 0; kc < NKC; kc++) {
        if (kc + 1 < NKC) {
            load_stage((kc + 1) & 1, kc + 1);
            CP_COMMIT();
            CP_WAIT(1);
        } else {
            CP_WAIT(0);
        }
        __syncthreads();
        compute_stage(kc & 1);
        __syncthreads();
    }

#pragma unroll
    for (int mi = 0; mi < 4; mi++) {
        const int row = m0 + wm * 64 + mi * 16 + (lane >> 2);
#pragma unroll
        for (int ni = 0; ni < 4; ni++) {
            const int col = n0 + wn * 32 + ni * 8 + (lane & 3) * 2;
            const float b0 = bias[col], b1 = bias[col + 1];
            float v00 = (acc[mi][ni][0] + b0) * scale;
            float v01 = (acc[mi][ni][1] + b1) * scale;
            float v10 = (acc[mi][ni][2] + b0) * scale;
            float v11 = (acc[mi][ni][3] + b1) * scale;
            if (C) {
                *(float2*)(C + (size_t)row * PHID + col)       = make_float2(v00, v01);
                *(float2*)(C + (size_t)(row + 8) * PHID + col) = make_float2(v10, v11);
            } else {
                uint32_t hp, lp;
                packsplit(v00, v01, hp, lp);
                *(uint32_t*)(Oh + (size_t)row * PHID + col) = hp;
                *(uint32_t*)(Ol + (size_t)row * PHID + col) = lp;
                packsplit(v10, v11, hp, lp);
                *(uint32_t*)(Oh + (size_t)(row + 8) * PHID + col) = hp;
                *(uint32_t*)(Ol + (size_t)(row + 8) * PHID + col) = lp;
            }
        }
    }
}

// ---------------------------------------------------------------------------
// Tensor-core flash attention (split-bf16, mma.sync) with bias prefetch.
// ---------------------------------------------------------------------------
#define AT_LDB  272
#define AT_QH   0
#define AT_QL   (128 * AT_LDB)            // 34816
#define AT_ST0  (2 * 128 * AT_LDB)        // 69632
#define AT_TILE (64 * AT_LDB)             // 17408
#define AT_STAGE (4 * AT_TILE)            // 69632
#define AT_SMEM (AT_ST0 + 2 * AT_STAGE)   // 208896

__global__ __launch_bounds__(256, 1) void attn_mma(
    const __nv_bfloat16* __restrict__ Qh, const __nv_bfloat16* __restrict__ Ql,
    const __nv_bfloat16* __restrict__ Kh, const __nv_bfloat16* __restrict__ Kl,
    const __nv_bfloat16* __restrict__ Vh, const __nv_bfloat16* __restrict__ Vl,
    const float* __restrict__ Bias,
    __nv_bfloat16* __restrict__ Ch, __nv_bfloat16* __restrict__ Cl)
{
    extern __shared__ char smem[];
    const uint32_t sb = smem_u32(smem);
    const int tid = threadIdx.x;
    const int lane = tid & 31;
    const int warp = tid >> 5;
    const int bh = blockIdx.y;
    const int b  = bh >> 4;
    const int h  = bh & 15;
    const int q0 = blockIdx.x * 128;

    const size_t base = (size_t)b * PS * PHID + (size_t)h * PD;
    const __nv_bfloat16* pQh = Qh + base + (size_t)q0 * PHID;
    const __nv_bfloat16* pQl = Ql + base + (size_t)q0 * PHID;
    const __nv_bfloat16* pKh = Kh + base;
    const __nv_bfloat16* pKl = Kl + base;
    const __nv_bfloat16* pVh = Vh + base;
    const __nv_bfloat16* pVl = Vl + base;

    // Q loader
    {
        const int r = tid >> 1;
        const int ce = (tid & 1) * 64;
        const uint32_t so = (uint32_t)(r * AT_LDB + (tid & 1) * 128);
#pragma unroll
        for (int i = 0; i < 8; i++) {
            cp16(sb + AT_QH + so + i * 16, pQh + (size_t)r * PHID + ce + i * 8);
            cp16(sb + AT_QL + so + i * 16, pQl + (size_t)r * PHID + ce + i * 8);
        }
    }

    // K/V stage loader
    const int kvr  = tid >> 2;
    const int kvce = (tid & 3) * 32;
    const uint32_t kvso = (uint32_t)(kvr * AT_LDB + (tid & 3) * 64);
    auto load_stage = [&](int stage, int t) {
        const uint32_t st = sb + AT_ST0 + stage * AT_STAGE;
        const size_t g = (size_t)(t * 64 + kvr) * PHID + kvce;
#pragma unroll
        for (int i = 0; i < 4; i++) {
            cp16(st + kvso + i * 16,               pKh + g + i * 8);
            cp16(st + AT_TILE + kvso + i * 16,     pKl + g + i * 8);
            cp16(st + 2 * AT_TILE + kvso + i * 16, pVh + g + i * 8);
            cp16(st + 3 * AT_TILE + kvso + i * 16, pVl + g + i * 8);
        }
    };

    load_stage(0, 0);
    CP_COMMIT();
    load_stage(1, 1);
    CP_COMMIT();

    const uint32_t q_off = (uint32_t)((warp * 16 + (lane & 15)) * AT_LDB + ((lane >> 4) << 4));
    const uint32_t k_off = (uint32_t)((lane & 7) * AT_LDB + ((lane & 8) ? 16 : 0));
    const uint32_t v_off = (uint32_t)((lane & 15) * AT_LDB);

    const float* biasR0 = Bias + ((size_t)bh * PS + q0 + warp * 16 + (lane >> 2)) * PS;
    const float* biasR1 = biasR0 + 8 * PS;
    const int bcol = (lane & 3) * 2;

    float o[16][4];
#pragma unroll
    for (int nd = 0; nd < 16; nd++)
#pragma unroll
        for (int j = 0; j < 4; j++) o[nd][j] = 0.0f;
    float m0 = -1e30f, m1 = -1e30f, l0 = 0.0f, l1 = 0.0f;

    // bias prefetch registers
    float2 nb0[8], nb1[8];
#pragma unroll
    for (int nf = 0; nf < 8; nf++) {
        nb0[nf] = *(const float2*)(biasR0 + nf * 8 + bcol);
        nb1[nf] = *(const float2*)(biasR1 + nf * 8 + bcol);
    }

    const int NT = PS / 64;   // 32
    for (int t = 0; t < NT; t++) {
        if (t < NT - 2) CP_WAIT(1); else CP_WAIT(0);
        __syncthreads();

        const uint32_t st = sb + AT_ST0 + (t & 1) * AT_STAGE;

        // consume prefetched bias, then prefetch next tile's bias
        float sc[8][4];
#pragma unroll
        for (int nf = 0; nf < 8; nf++) {
            sc[nf][0] = nb0[nf].x; sc[nf][1] = nb0[nf].y;
            sc[nf][2] = nb1[nf].x; sc[nf][3] = nb1[nf].y;
        }
        if (t + 1 < NT) {
            const int k1 = (t + 1) * 64;
#pragma unroll
            for (int nf = 0; nf < 8; nf++) {
                nb0[nf] = *(const float2*)(biasR0 + k1 + nf * 8 + bcol);
                nb1[nf] = *(const float2*)(biasR1 + k1 + nf * 8 + bcol);
            }
        }

        // ---- scores += Q K^T (split 3-combo) ----
#pragma unroll
        for (int ks = 0; ks < 8; ks++) {
            uint32_t qa[4], qla[4];
            ldm_x4(qa,  sb + AT_QH + q_off + ks * 32);
            ldm_x4(qla, sb + AT_QL + q_off + ks * 32);
#pragma unroll
            for (int nf = 0; nf < 8; nf++) {
                uint32_t kbh[2], kbl[2];
                ldm_x2(kbh, st + k_off + nf * 8 * AT_LDB + ks * 32);
                ldm_x2(kbl, st + AT_TILE + k_off + nf * 8 * AT_LDB + ks * 32);
                mma_bf16(sc[nf], qa,  kbh);
                mma_bf16(sc[nf], qa,  kbl);
                mma_bf16(sc[nf], qla, kbh);
            }
        }

        // ---- online softmax ----
        float mx0 = sc[0][0], mx1 = sc[0][2];
#pragma unroll
        for (int nf = 0; nf < 8; nf++) {
            mx0 = fmaxf(mx0, fmaxf(sc[nf][0], sc[nf][1]));
            mx1 = fmaxf(mx1, fmaxf(sc[nf][2], sc[nf][3]));
        }
        mx0 = fmaxf(mx0, __shfl_xor_sync(0xffffffffu, mx0, 1));
        mx0 = fmaxf(mx0, __shfl_xor_sync(0xffffffffu, mx0, 2));
        mx1 = fmaxf(mx1, __shfl_xor_sync(0xffffffffu, mx1, 1));
        mx1 = fmaxf(mx1, __shfl_xor_sync(0xffffffffu, mx1, 2));
        const float mn0 = fmaxf(m0, mx0), mn1 = fmaxf(m1, mx1);
        const float al0 = __expf(m0 - mn0), al1 = __expf(m1 - mn1);
        m0 = mn0; m1 = mn1;
        float s0 = 0.0f, s1 = 0.0f;
#pragma unroll
        for (int nf = 0; nf < 8; nf++) {
            sc[nf][0] = __expf(sc[nf][0] - mn0);
            sc[nf][1] = __expf(sc[nf][1] - mn0);
            sc[nf][2] = __expf(sc[nf][2] - mn1);
            sc[nf][3] = __expf(sc[nf][3] - mn1);
            s0 += sc[nf][0] + sc[nf][1];
            s1 += sc[nf][2] + sc[nf][3];
        }
        s0 += __shfl_xor_sync(0xffffffffu, s0, 1);
        s0 += __shfl_xor_sync(0xffffffffu, s0, 2);
        s1 += __shfl_xor_sync(0xffffffffu, s1, 1);
        s1 += __shfl_xor_sync(0xffffffffu, s1, 2);
        l0 = l0 * al0 + s0;
        l1 = l1 * al1 + s1;
#pragma unroll
        for (int nd = 0; nd < 16; nd++) {
            o[nd][0] *= al0; o[nd][1] *= al0;
            o[nd][2] *= al1; o[nd][3] *= al1;
        }

        // ---- P fragments (split) from score registers ----
        uint32_t pha[4][4], pla[4][4];
#pragma unroll
        for (int j2 = 0; j2 < 4; j2++) {
            const int f0 = 2 * j2, f1 = f0 + 1;
            packsplit(sc[f0][0], sc[f0][1], pha[j2][0], pla[j2][0]);
            packsplit(sc[f0][2], sc[f0][3], pha[j2][1], pla[j2][1]);
            packsplit(sc[f1][0], sc[f1][1], pha[j2][2], pla[j2][2]);
            packsplit(sc[f1][2], sc[f1][3], pha[j2][3], pla[j2][3]);
        }

        // ---- O += P V (split 3-combo), V via ldmatrix.trans ----
#pragma unroll
        for (int j2 = 0; j2 < 4; j2++) {
            const uint32_t vrow = st + 2 * AT_TILE + v_off + j2 * 16 * AT_LDB;
#pragma unroll
            for (int nd = 0; nd < 16; nd++) {
                uint32_t vbh[2], vbl[2];
                ldm_x2t(vbh, vrow + nd * 16);
                ldm_x2t(vbl, vrow + AT_TILE + nd * 16);
                mma_bf16(o[nd], pha[j2], vbh);
                mma_bf16(o[nd], pha[j2], vbl);
                mma_bf16(o[nd], pla[j2], vbh);
            }
        }

        __syncthreads();
        if (t + 2 < NT) {
            load_stage(t & 1, t + 2);
            CP_COMMIT();
        }
    }

    // ---- epilogue: normalize, split, store ctx ----
    const float inv0 = 1.0f / l0, inv1 = 1.0f / l1;
    const int rg0 = q0 + warp * 16 + (lane >> 2);
    __nv_bfloat16* och = Ch + base;
    __nv_bfloat16* ocl = Cl + base;
#pragma unroll
    for (int nd = 0; nd < 16; nd++) {
        const int col = nd * 8 + (lane & 3) * 2;
        uint32_t hp, lp;
        packsplit(o[nd][0] * inv0, o[nd][1] * inv0, hp, lp);
        *(uint32_t*)(och + (size_t)rg0 * PHID + col) = hp;
        *(uint32_t*)(ocl + (size_t)rg0 * PHID + col) = lp;
        packsplit(o[nd][2] * inv1, o[nd][3] * inv1, hp, lp);
        *(uint32_t*)(och + (size_t)(rg0 + 8) * PHID + col) = hp;
        *(uint32_t*)(ocl + (size_t)(rg0 + 8) * PHID + col) = lp;
    }
}

// ---------------------------------------------------------------------------
extern "C" void kernel_launch(void* const* d_in, const int* in_sizes, int n_in,
                              void* d_out, int out_size)
{
    (void)in_sizes; (void)n_in; (void)out_size;
    const float* x    = (const float*)d_in[0];
    const float* bias = (const float*)d_in[1];
    const float* Wq   = (const float*)d_in[2];
    const float* bq   = (const float*)d_in[3];
    const float* Wk   = (const float*)d_in[4];
    const float* bk   = (const float*)d_in[5];
    const float* Wv   = (const float*)d_in[6];
    const float* bv   = (const float*)d_in[7];
    const float* Wo   = (const float*)d_in[8];
    const float* bo   = (const float*)d_in[9];
    float* out = (float*)d_out;

    __nv_bfloat16 *xh, *xl, *qh, *ql, *kh, *kl, *vh, *vl, *ch, *cl;
    __nv_bfloat16 *wqh, *wql, *wkh, *wkl, *wvh, *wvl, *woh, *wol;
    cudaGetSymbolAddress((void**)&xh, g_xh);
    cudaGetSymbolAddress((void**)&xl, g_xl);
    cudaGetSymbolAddress((void**)&qh, g_qh);
    cudaGetSymbolAddress((void**)&ql, g_ql);
    cudaGetSymbolAddress((void**)&kh, g_kh);
    cudaGetSymbolAddress((void**)&kl, g_kl);
    cudaGetSymbolAddress((void**)&vh, g_vh);
    cudaGetSymbolAddress((void**)&vl, g_vl);
    cudaGetSymbolAddress((void**)&ch, g_ch);
    cudaGetSymbolAddress((void**)&cl, g_cl);
    cudaGetSymbolAddress((void**)&wqh, g_wqh);
    cudaGetSymbolAddress((void**)&wql, g_wql);
    cudaGetSymbolAddress((void**)&wkh, g_wkh);
    cudaGetSymbolAddress((void**)&wkl, g_wkl);
    cudaGetSymbolAddress((void**)&wvh, g_wvh);
    cudaGetSymbolAddress((void**)&wvl, g_wvl);
    cudaGetSymbolAddress((void**)&woh, g_woh);
    cudaGetSymbolAddress((void**)&wol, g_wol);

    static bool attr_set = false;
    if (!attr_set) {
        cudaFuncSetAttribute(gemm_split_mma,
                             cudaFuncAttributeMaxDynamicSharedMemorySize, GSMEM);
        cudaFuncSetAttribute(attn_mma,
                             cudaFuncAttributeMaxDynamicSharedMemorySize, AT_SMEM);
        attr_set = true;
    }

    // 1) conversions
    {
        int n4 = PM * PHID / 4;
        split_bf16_kernel<<<(n4 + 255) / 256, 256>>>(x, xh, xl, n4);
        dim3 tg(PHID / 32, PHID / 32);
        dim3 tb(32, 8);
        transpose_split_kernel<<<tg, tb>>>(Wq, wqh, wql);
        transpose_split_kernel<<<tg, tb>>>(Wk, wkh, wkl);
        transpose_split_kernel<<<tg, tb>>>(Wv, wvh, wvl);
        transpose_split_kernel<<<tg, tb>>>(Wo, woh, wol);
    }

    // 2) projections -> split bf16 q/k/v directly
    dim3 ggrid(PHID / 128, PM / 128);
    gemm_split_mma<<<ggrid, 256, GSMEM>>>(xh, xl, wqh, wql, bq, nullptr, qh, ql, QSCALE);
    gemm_split_mma<<<ggrid, 256, GSMEM>>>(xh, xl, wkh, wkl, bk, nullptr, kh, kl, 1.0f);
    gemm_split_mma<<<ggrid, 256, GSMEM>>>(xh, xl, wvh, wvl, bv, nullptr, vh, vl, 1.0f);

    // 3) tensor-core attention -> split bf16 ctx
    dim3 agrid(PS / 128, PB * PH);      // (16, 32)
    attn_mma<<<agrid, 256, AT_SMEM>>>(qh, ql, kh, kl, vh, vl, bias, ch, cl);

    // 4) output projection -> fp32 out
    gemm_split_mma<<<ggrid, 256, GSMEM>>>(ch, cl, woh, wol, bo, out, nullptr, nullptr, 1.0f);
}

// round 7
// speedup vs baseline: 3.2729x; 1.0447x over previous
#include <cuda_runtime.h>
#include <cuda_bf16.h>
#include <cuda_fp16.h>
#include <math.h>
#include <stdint.h>

// Problem constants
#define PB   2
#define PS   2048
#define PHID 2048
#define PH   16
#define PD   128
#define PM   (PB * PS)          // 4096 rows
#define QSCALE 11.313708498984760f   // sqrt(128)

// ---------------------------------------------------------------------------
// Scratch (no cudaMalloc allowed)
// ---------------------------------------------------------------------------
__device__ __nv_bfloat16 g_xh[(size_t)PM * PHID];
__device__ __nv_bfloat16 g_xl[(size_t)PM * PHID];
__device__ __nv_bfloat16 g_qh[(size_t)PM * PHID];
__device__ __nv_bfloat16 g_ql[(size_t)PM * PHID];
__device__ __nv_bfloat16 g_kh[(size_t)PM * PHID];
__device__ __nv_bfloat16 g_kl[(size_t)PM * PHID];
__device__ __half        g_vhf[(size_t)PM * PHID];   // V hi, fp16
__device__ __half        g_vlf[(size_t)PM * PHID];   // V lo, fp16
__device__ __nv_bfloat16 g_ch[(size_t)PM * PHID];
__device__ __nv_bfloat16 g_cl[(size_t)PM * PHID];

// split-bf16 transposed weights [N,K]
__device__ __nv_bfloat16 g_wqh[(size_t)PHID * PHID];
__device__ __nv_bfloat16 g_wql[(size_t)PHID * PHID];
__device__ __nv_bfloat16 g_wkh[(size_t)PHID * PHID];
__device__ __nv_bfloat16 g_wkl[(size_t)PHID * PHID];
__device__ __nv_bfloat16 g_wvh[(size_t)PHID * PHID];
__device__ __nv_bfloat16 g_wvl[(size_t)PHID * PHID];
__device__ __nv_bfloat16 g_woh[(size_t)PHID * PHID];
__device__ __nv_bfloat16 g_wol[(size_t)PHID * PHID];

// ---------------------------------------------------------------------------
// Helpers
// ---------------------------------------------------------------------------
__device__ __forceinline__ uint32_t smem_u32(const void* p) {
    uint32_t a;
    asm("{ .reg .u64 t; cvta.to.shared.u64 t, %1; cvt.u32.u64 %0, t; }"
        : "=r"(a) : "l"(p));
    return a;
}

__device__ __forceinline__ void cp16(uint32_t s, const void* g) {
    asm volatile("cp.async.cg.shared.global [%0], [%1], 16;" :: "r"(s), "l"(g));
}
#define CP_COMMIT() asm volatile("cp.async.commit_group;" ::: "memory")
#define CP_WAIT(n)  asm volatile("cp.async.wait_group %0;" :: "n"(n) : "memory")

__device__ __forceinline__ void ldm_x4(uint32_t* r, uint32_t addr) {
    asm volatile("ldmatrix.sync.aligned.m8n8.x4.shared.b16 {%0,%1,%2,%3}, [%4];"
                 : "=r"(r[0]), "=r"(r[1]), "=r"(r[2]), "=r"(r[3]) : "r"(addr));
}
__device__ __forceinline__ void ldm_x2(uint32_t* r, uint32_t addr) {
    asm volatile("ldmatrix.sync.aligned.m8n8.x2.shared.b16 {%0,%1}, [%2];"
                 : "=r"(r[0]), "=r"(r[1]) : "r"(addr));
}
__device__ __forceinline__ void ldm_x2t(uint32_t* r, uint32_t addr) {
    asm volatile("ldmatrix.sync.aligned.m8n8.x2.trans.shared.b16 {%0,%1}, [%2];"
                 : "=r"(r[0]), "=r"(r[1]) : "r"(addr));
}
__device__ __forceinline__ void mma_bf16(float* c, const uint32_t* a, const uint32_t* b) {
    asm volatile(
        "mma.sync.aligned.m16n8k16.row.col.f32.bf16.bf16.f32 "
        "{%0,%1,%2,%3}, {%4,%5,%6,%7}, {%8,%9}, {%0,%1,%2,%3};"
        : "+f"(c[0]), "+f"(c[1]), "+f"(c[2]), "+f"(c[3])
        : "r"(a[0]), "r"(a[1]), "r"(a[2]), "r"(a[3]), "r"(b[0]), "r"(b[1]));
}
__device__ __forceinline__ void mma_f16(float* c, const uint32_t* a, const uint32_t* b) {
    asm volatile(
        "mma.sync.aligned.m16n8k16.row.col.f32.f16.f16.f32 "
        "{%0,%1,%2,%3}, {%4,%5,%6,%7}, {%8,%9}, {%0,%1,%2,%3};"
        : "+f"(c[0]), "+f"(c[1]), "+f"(c[2]), "+f"(c[3])
        : "r"(a[0]), "r"(a[1]), "r"(a[2]), "r"(a[3]), "r"(b[0]), "r"(b[1]));
}

// Fast RNE split of two floats into (hi bf16x2, lo bf16x2).
__device__ __forceinline__ void packsplit(float a, float b, uint32_t& hp, uint32_t& lp) {
    asm("cvt.rn.bf16x2.f32 %0, %1, %2;" : "=r"(hp) : "f"(b), "f"(a));
    float ah = __uint_as_float(hp << 16);
    float bh = __uint_as_float(hp & 0xFFFF0000u);
    float la = a - ah;
    float lb = b - bh;
    asm("cvt.rn.bf16x2.f32 %0, %1, %2;" : "=r"(lp) : "f"(lb), "f"(la));
}

// RNE split of two floats into (hi f16x2, lo f16x2).
__device__ __forceinline__ void packsplit_f16(float a, float b, uint32_t& hp, uint32_t& lp) {
    __half2 h = __floats2half2_rn(a, b);
    float la = a - __half2float(__low2half(h));
    float lb = b - __half2float(__high2half(h));
    __half2 l = __floats2half2_rn(la, lb);
    hp = *reinterpret_cast<uint32_t*>(&h);
    lp = *reinterpret_cast<uint32_t*>(&l);
}

// ---------------------------------------------------------------------------
// Conversion kernels
// ---------------------------------------------------------------------------
__global__ void split_bf16_kernel(const float* __restrict__ in,
                                  __nv_bfloat16* __restrict__ hi,
                                  __nv_bfloat16* __restrict__ lo, int n4)
{
    int i = blockIdx.x * blockDim.x + threadIdx.x;
    if (i >= n4) return;
    float4 v = ((const float4*)in)[i];
    uint32_t h0, l0, h1, l1;
    packsplit(v.x, v.y, h0, l0);
    packsplit(v.z, v.w, h1, l1);
    ((uint32_t*)hi)[2*i]   = h0;
    ((uint32_t*)hi)[2*i+1] = h1;
    ((uint32_t*)lo)[2*i]   = l0;
    ((uint32_t*)lo)[2*i+1] = l1;
}

__global__ void transpose_split_kernel(const float* __restrict__ W,
                                       __nv_bfloat16* __restrict__ Th,
                                       __nv_bfloat16* __restrict__ Tl)
{
    __shared__ float t[32][33];
    int n0 = blockIdx.x * 32, k0 = blockIdx.y * 32;
    int tx = threadIdx.x, ty0 = threadIdx.y;   // 32 x 8
#pragma unroll
    for (int j = 0; j < 32; j += 8)
        t[ty0 + j][tx] = W[(size_t)(k0 + ty0 + j) * PHID + n0 + tx];
    __syncthreads();
#pragma unroll
    for (int j = 0; j < 32; j += 8) {
        int n = ty0 + j;
        float v = t[tx][n];
        __nv_bfloat16 h = __float2bfloat16(v);
        __nv_bfloat16 l = __float2bfloat16(v - __bfloat162float(h));
        size_t o = (size_t)(n0 + n) * PHID + k0 + tx;
        Th[o] = h;
        Tl[o] = l;
    }
}

// ---------------------------------------------------------------------------
// Shared GEMM tile config
// ---------------------------------------------------------------------------
#define LDT   40
#define TILE_B (128 * LDT * 2)   // 10240
#define OFF_AH 0
#define OFF_AL (TILE_B)
#define OFF_BH (2 * TILE_B)
#define OFF_BL (3 * TILE_B)
#define STAGE_B (4 * TILE_B)     // 40960
#define GSMEM  (2 * STAGE_B)     // 81920

// ---------------------------------------------------------------------------
// Merged QKV projection GEMM: one launch, sel = blockIdx.x>>4 picks Q/K/V.
// Q,K epilogue -> split bf16; V epilogue -> split fp16.
// ---------------------------------------------------------------------------
__global__ __launch_bounds__(256, 2) void gemm_qkv(
    const __nv_bfloat16* __restrict__ Ah, const __nv_bfloat16* __restrict__ Al,
    const __nv_bfloat16* __restrict__ Wqh, const __nv_bfloat16* __restrict__ Wql,
    const __nv_bfloat16* __restrict__ Wkh, const __nv_bfloat16* __restrict__ Wkl,
    const __nv_bfloat16* __restrict__ Wvh, const __nv_bfloat16* __restrict__ Wvl,
    const float* __restrict__ bq, const float* __restrict__ bk,
    const float* __restrict__ bv,
    __nv_bfloat16* __restrict__ Qh, __nv_bfloat16* __restrict__ Ql,
    __nv_bfloat16* __restrict__ Kh, __nv_bfloat16* __restrict__ Kl,
    __half* __restrict__ Vh, __half* __restrict__ Vl)
{
    extern __shared__ char smem[];
    const uint32_t sb = smem_u32(smem);
    const int tid  = threadIdx.x;
    const int lane = tid & 31;
    const int warp = tid >> 5;
    const int wm = warp >> 2;
    const int wn = warp & 3;
    const int sel = blockIdx.x >> 4;            // 0=Q 1=K 2=V
    const int n0  = (blockIdx.x & 15) * 128;
    const int m0  = blockIdx.y * 128;

    const __nv_bfloat16* Bh = (sel == 0) ? Wqh : (sel == 1) ? Wkh : Wvh;
    const __nv_bfloat16* Bl = (sel == 0) ? Wql : (sel == 1) ? Wkl : Wvl;
    const float* bias = (sel == 0) ? bq : (sel == 1) ? bk : bv;
    const float scale = (sel == 0) ? QSCALE : 1.0f;

    const __nv_bfloat16* pAh = Ah + (size_t)m0 * PHID;
    const __nv_bfloat16* pAl = Al + (size_t)m0 * PHID;
    const __nv_bfloat16* pBh = Bh + (size_t)n0 * PHID;
    const __nv_bfloat16* pBl = Bl + (size_t)n0 * PHID;

    const int r0 = tid >> 2;
    const int c0 = (tid & 3) * 8;
    const uint32_t so0 = (uint32_t)(r0 * 80 + (tid & 3) * 16);
    const uint32_t so1 = (uint32_t)((r0 + 64) * 80 + (tid & 3) * 16);

    const uint32_t a_off = (uint32_t)((wm * 64 + (lane & 15)) * 80 + ((lane >> 4) << 4));
    const uint32_t b_off = (uint32_t)((wn * 32 + (lane & 7)) * 80 + ((lane & 8) ? 16 : 0));

    float acc[4][4][4];
#pragma unroll
    for (int mi = 0; mi < 4; mi++)
#pragma unroll
        for (int ni = 0; ni < 4; ni++)
#pragma unroll
            for (int j = 0; j < 4; j++) acc[mi][ni][j] = 0.0f;

    auto load_stage = [&](int stage, int kc) {
        const uint32_t st = sb + stage * STAGE_B;
        const size_t g0 = (size_t)r0 * PHID + kc * 32 + c0;
        const size_t g1 = (size_t)(r0 + 64) * PHID + kc * 32 + c0;
        cp16(st + OFF_AH + so0, pAh + g0);
        cp16(st + OFF_AH + so1, pAh + g1);
        cp16(st + OFF_AL + so0, pAl + g0);
        cp16(st + OFF_AL + so1, pAl + g1);
        cp16(st + OFF_BH + so0, pBh + g0);
        cp16(st + OFF_BH + so1, pBh + g1);
        cp16(st + OFF_BL + so0, pBl + g0);
        cp16(st + OFF_BL + so1, pBl + g1);
    };

    auto compute_stage = [&](int stage) {
        const uint32_t st = sb + stage * STAGE_B;
#pragma unroll
        for (int ks = 0; ks < 2; ks++) {
            const uint32_t k32 = ks * 32;
            uint32_t bhf[4][2], blf[4][2], a[4][4];
#pragma unroll
            for (int ni = 0; ni < 4; ni++)
                ldm_x2(bhf[ni], st + OFF_BH + b_off + ni * 640 + k32);
#pragma unroll
            for (int ni = 0; ni < 4; ni++)
                ldm_x2(blf[ni], st + OFF_BL + b_off + ni * 640 + k32);
#pragma unroll
            for (int mi = 0; mi < 4; mi++)
                ldm_x4(a[mi], st + OFF_AH + a_off + mi * 1280 + k32);
#pragma unroll
            for (int mi = 0; mi < 4; mi++)
#pragma unroll
                for (int ni = 0; ni < 4; ni++)
                    mma_bf16(acc[mi][ni], a[mi], bhf[ni]);
#pragma unroll
            for (int mi = 0; mi < 4; mi++)
#pragma unroll
                for (int ni = 0; ni < 4; ni++)
                    mma_bf16(acc[mi][ni], a[mi], blf[ni]);
#pragma unroll
            for (int mi = 0; mi < 4; mi++)
                ldm_x4(a[mi], st + OFF_AL + a_off + mi * 1280 + k32);
#pragma unroll
            for (int mi = 0; mi < 4; mi++)
#pragma unroll
                for (int ni = 0; ni < 4; ni++)
                    mma_bf16(acc[mi][ni], a[mi], bhf[ni]);
        }
    };

    load_stage(0, 0);
    CP_COMMIT();
    const int NKC = PHID / 32;
    for (int kc = 0; kc < NKC; kc++) {
        if (kc + 1 < NKC) {
            load_stage((kc + 1) & 1, kc + 1);
            CP_COMMIT();
            CP_WAIT(1);
        } else {
            CP_WAIT(0);
        }
        __syncthreads();
        compute_stage(kc & 1);
        __syncthreads();
    }

#pragma unroll
    for (int mi = 0; mi < 4; mi++) {
        const int row = m0 + wm * 64 + mi * 16 + (lane >> 2);
#pragma unroll
        for (int ni = 0; ni < 4; ni++) {
            const int col = n0 + wn * 32 + ni * 8 + (lane & 3) * 2;
            const float b0 = bias[col], b1 = bias[col + 1];
            float v00 = (acc[mi][ni][0] + b0) * scale;
            float v01 = (acc[mi][ni][1] + b1) * scale;
            float v10 = (acc[mi][ni][2] + b0) * scale;
            float v11 = (acc[mi][ni][3] + b1) * scale;
            uint32_t hp, lp;
            if (sel == 2) {
                packsplit_f16(v00, v01, hp, lp);
                *(uint32_t*)(Vh + (size_t)row * PHID + col) = hp;
                *(uint32_t*)(Vl + (size_t)row * PHID + col) = lp;
                packsplit_f16(v10, v11, hp, lp);
                *(uint32_t*)(Vh + (size_t)(row + 8) * PHID + col) = hp;
                *(uint32_t*)(Vl + (size_t)(row + 8) * PHID + col) = lp;
            } else {
                __nv_bfloat16* Oh = (sel == 0) ? Qh : Kh;
                __nv_bfloat16* Ol = (sel == 0) ? Ql : Kl;
                packsplit(v00, v01, hp, lp);
                *(uint32_t*)(Oh + (size_t)row * PHID + col) = hp;
                *(uint32_t*)(Ol + (size_t)row * PHID + col) = lp;
                packsplit(v10, v11, hp, lp);
                *(uint32_t*)(Oh + (size_t)(row + 8) * PHID + col) = hp;
                *(uint32_t*)(Ol + (size_t)(row + 8) * PHID + col) = lp;
            }
        }
    }
}

// ---------------------------------------------------------------------------
// Output projection GEMM (split-bf16 in, fp32 out).
// ---------------------------------------------------------------------------
__global__ __launch_bounds__(256, 2) void gemm_split_mma(
    const __nv_bfloat16* __restrict__ Ah, const __nv_bfloat16* __restrict__ Al,
    const __nv_bfloat16* __restrict__ Bh, const __nv_bfloat16* __restrict__ Bl,
    const float* __restrict__ bias, float* __restrict__ C)
{
    extern __shared__ char smem[];
    const uint32_t sb = smem_u32(smem);
    const int tid  = threadIdx.x;
    const int lane = tid & 31;
    const int warp = tid >> 5;
    const int wm = warp >> 2;
    const int wn = warp & 3;
    const int m0 = blockIdx.y * 128;
    const int n0 = blockIdx.x * 128;

    const __nv_bfloat16* pAh = Ah + (size_t)m0 * PHID;
    const __nv_bfloat16* pAl = Al + (size_t)m0 * PHID;
    const __nv_bfloat16* pBh = Bh + (size_t)n0 * PHID;
    const __nv_bfloat16* pBl = Bl + (size_t)n0 * PHID;

    const int r0 = tid >> 2;
    const int c0 = (tid & 3) * 8;
    const uint32_t so0 = (uint32_t)(r0 * 80 + (tid & 3) * 16);
    const uint32_t so1 = (uint32_t)((r0 + 64) * 80 + (tid & 3) * 16);

    const uint32_t a_off = (uint32_t)((wm * 64 + (lane & 15)) * 80 + ((lane >> 4) << 4));
    const uint32_t b_off = (uint32_t)((wn * 32 + (lane & 7)) * 80 + ((lane & 8) ? 16 : 0));

    float acc[4][4][4];
#pragma unroll
    for (int mi = 0; mi < 4; mi++)
#pragma unroll
        for (int ni = 0; ni < 4; ni++)
#pragma unroll
            for (int j = 0; j < 4; j++) acc[mi][ni][j] = 0.0f;

    auto load_stage = [&](int stage, int kc) {
        const uint32_t st = sb + stage * STAGE_B;
        const size_t g0 = (size_t)r0 * PHID + kc * 32 + c0;
        const size_t g1 = (size_t)(r0 + 64) * PHID + kc * 32 + c0;
        cp16(st + OFF_AH + so0, pAh + g0);
        cp16(st + OFF_AH + so1, pAh + g1);
        cp16(st + OFF_AL + so0, pAl + g0);
        cp16(st + OFF_AL + so1, pAl + g1);
        cp16(st + OFF_BH + so0, pBh + g0);
        cp16(st + OFF_BH + so1, pBh + g1);
        cp16(st + OFF_BL + so0, pBl + g0);
        cp16(st + OFF_BL + so1, pBl + g1);
    };

    auto compute_stage = [&](int stage) {
        const uint32_t st = sb + stage * STAGE_B;
#pragma unroll
        for (int ks = 0; ks < 2; ks++) {
            const uint32_t k32 = ks * 32;
            uint32_t bhf[4][2], blf[4][2], a[4][4];
#pragma unroll
            for (int ni = 0; ni < 4; ni++)
                ldm_x2(bhf[ni], st + OFF_BH + b_off + ni * 640 + k32);
#pragma unroll
            for (int ni = 0; ni < 4; ni++)
                ldm_x2(blf[ni], st + OFF_BL + b_off + ni * 640 + k32);
#pragma unroll
            for (int mi = 0; mi < 4; mi++)
                ldm_x4(a[mi], st + OFF_AH + a_off + mi * 1280 + k32);
#pragma unroll
            for (int mi = 0; mi < 4; mi++)
#pragma unroll
                for (int ni = 0; ni < 4; ni++)
                    mma_bf16(acc[mi][ni], a[mi], bhf[ni]);
#pragma unroll
            for (int mi = 0; mi < 4; mi++)
#pragma unroll
                for (int ni = 0; ni < 4; ni++)
                    mma_bf16(acc[mi][ni], a[mi], blf[ni]);
#pragma unroll
            for (int mi = 0; mi < 4; mi++)
                ldm_x4(a[mi], st + OFF_AL + a_off + mi * 1280 + k32);
#pragma unroll
            for (int mi = 0; mi < 4; mi++)
#pragma unroll
                for (int ni = 0; ni < 4; ni++)
                    mma_bf16(acc[mi][ni], a[mi], bhf[ni]);
        }
    };

    load_stage(0, 0);
    CP_COMMIT();
    const int NKC = PHID / 32;
    for (int kc = 0; kc < NKC; kc++) {
        if (kc + 1 < NKC) {
            load_stage((kc + 1) & 1, kc + 1);
            CP_COMMIT();
            CP_WAIT(1);
        } else {
            CP_WAIT(0);
        }
        __syncthreads();
        compute_stage(kc & 1);
        __syncthreads();
    }

#pragma unroll
    for (int mi = 0; mi < 4; mi++) {
        const int row = m0 + wm * 64 + mi * 16 + (lane >> 2);
#pragma unroll
        for (int ni = 0; ni < 4; ni++) {
            const int col = n0 + wn * 32 + ni * 8 + (lane & 3) * 2;
            const float b0 = bias[col], b1 = bias[col + 1];
            *(float2*)(C + (size_t)row * PHID + col) =
                make_float2(acc[mi][ni][0] + b0, acc[mi][ni][1] + b1);
            *(float2*)(C + (size_t)(row + 8) * PHID + col) =
                make_float2(acc[mi][ni][2] + b0, acc[mi][ni][3] + b1);
        }
    }
}

// ---------------------------------------------------------------------------
// Tensor-core flash attention: QK split-bf16 (3 combos), PV fp16
// (P single-fp16, V split-fp16, 2 combos).
// ---------------------------------------------------------------------------
#define AT_LDB  272
#define AT_QH   0
#define AT_QL   (128 * AT_LDB)            // 34816
#define AT_ST0  (2 * 128 * AT_LDB)        // 69632
#define AT_TILE (64 * AT_LDB)             // 17408
#define AT_STAGE (4 * AT_TILE)            // 69632
#define AT_SMEM (AT_ST0 + 2 * AT_STAGE)   // 208896

__global__ __launch_bounds__(256, 1) void attn_mma(
    const __nv_bfloat16* __restrict__ Qh, const __nv_bfloat16* __restrict__ Ql,
    const __nv_bfloat16* __restrict__ Kh, const __nv_bfloat16* __restrict__ Kl,
    const __half* __restrict__ Vh, const __half* __restrict__ Vl,
    const float* __restrict__ Bias,
    __nv_bfloat16* __restrict__ Ch, __nv_bfloat16* __restrict__ Cl)
{
    extern __shared__ char smem[];
    const uint32_t sb = smem_u32(smem);
    const int tid = threadIdx.x;
    const int lane = tid & 31;
    const int warp = tid >> 5;
    const int bh = blockIdx.y;
    const int b  = bh >> 4;
    const int h  = bh & 15;
    const int q0 = blockIdx.x * 128;

    const size_t base = (size_t)b * PS * PHID + (size_t)h * PD;
    const __nv_bfloat16* pQh = Qh + base + (size_t)q0 * PHID;
    const __nv_bfloat16* pQl = Ql + base + (size_t)q0 * PHID;
    const __nv_bfloat16* pKh = Kh + base;
    const __nv_bfloat16* pKl = Kl + base;
    const __half* pVh = Vh + base;
    const __half* pVl = Vl + base;

    // Q loader
    {
        const int r = tid >> 1;
        const int ce = (tid & 1) * 64;
        const uint32_t so = (uint32_t)(r * AT_LDB + (tid & 1) * 128);
#pragma unroll
        for (int i = 0; i < 8; i++) {
            cp16(sb + AT_QH + so + i * 16, pQh + (size_t)r * PHID + ce + i * 8);
            cp16(sb + AT_QL + so + i * 16, pQl + (size_t)r * PHID + ce + i * 8);
        }
    }

    // K/V stage loader
    const int kvr  = tid >> 2;
    const int kvce = (tid & 3) * 32;
    const uint32_t kvso = (uint32_t)(kvr * AT_LDB + (tid & 3) * 64);
    auto load_stage = [&](int stage, int t) {
        const uint32_t st = sb + AT_ST0 + stage * AT_STAGE;
        const size_t g = (size_t)(t * 64 + kvr) * PHID + kvce;
#pragma unroll
        for (int i = 0; i < 4; i++) {
            cp16(st + kvso + i * 16,               pKh + g + i * 8);
            cp16(st + AT_TILE + kvso + i * 16,     pKl + g + i * 8);
            cp16(st + 2 * AT_TILE + kvso + i * 16, pVh + g + i * 8);
            cp16(st + 3 * AT_TILE + kvso + i * 16, pVl + g + i * 8);
        }
    };

    load_stage(0, 0);
    CP_COMMIT();
    load_stage(1, 1);
    CP_COMMIT();

    const uint32_t q_off = (uint32_t)((warp * 16 + (lane & 15)) * AT_LDB + ((lane >> 4) << 4));
    const uint32_t k_off = (uint32_t)((lane & 7) * AT_LDB + ((lane & 8) ? 16 : 0));
    const uint32_t v_off = (uint32_t)((lane & 15) * AT_LDB);

    const float* biasR0 = Bias + ((size_t)bh * PS + q0 + warp * 16 + (lane >> 2)) * PS;
    const float* biasR1 = biasR0 + 8 * PS;
    const int bcol = (lane & 3) * 2;

    float o[16][4];
#pragma unroll
    for (int nd = 0; nd < 16; nd++)
#pragma unroll
        for (int j = 0; j < 4; j++) o[nd][j] = 0.0f;
    float m0 = -1e30f, m1 = -1e30f, l0 = 0.0f, l1 = 0.0f;

    // bias prefetch registers
    float2 nb0[8], nb1[8];
#pragma unroll
    for (int nf = 0; nf < 8; nf++) {
        nb0[nf] = *(const float2*)(biasR0 + nf * 8 + bcol);
        nb1[nf] = *(const float2*)(biasR1 + nf * 8 + bcol);
    }

    const int NT = PS / 64;   // 32
    for (int t = 0; t < NT; t++) {
        if (t < NT - 2) CP_WAIT(1); else CP_WAIT(0);
        __syncthreads();

        const uint32_t st = sb + AT_ST0 + (t & 1) * AT_STAGE;

        // consume prefetched bias, then prefetch next tile's bias
        float sc[8][4];
#pragma unroll
        for (int nf = 0; nf < 8; nf++) {
            sc[nf][0] = nb0[nf].x; sc[nf][1] = nb0[nf].y;
            sc[nf][2] = nb1[nf].x; sc[nf][3] = nb1[nf].y;
        }
        if (t + 1 < NT) {
            const int k1 = (t + 1) * 64;
#pragma unroll
            for (int nf = 0; nf < 8; nf++) {
                nb0[nf] = *(const float2*)(biasR0 + k1 + nf * 8 + bcol);
                nb1[nf] = *(const float2*)(biasR1 + k1 + nf * 8 + bcol);
            }
        }

        // ---- scores += Q K^T (split 3-combo) ----
#pragma unroll
        for (int ks = 0; ks < 8; ks++) {
            uint32_t qa[4], qla[4];
            ldm_x4(qa,  sb + AT_QH + q_off + ks * 32);
            ldm_x4(qla, sb + AT_QL + q_off + ks * 32);
#pragma unroll
            for (int nf = 0; nf < 8; nf++) {
                uint32_t kbh[2], kbl[2];
                ldm_x2(kbh, st + k_off + nf * 8 * AT_LDB + ks * 32);
                ldm_x2(kbl, st + AT_TILE + k_off + nf * 8 * AT_LDB + ks * 32);
                mma_bf16(sc[nf], qa,  kbh);
                mma_bf16(sc[nf], qa,  kbl);
                mma_bf16(sc[nf], qla, kbh);
            }
        }

        // ---- online softmax ----
        float mx0 = sc[0][0], mx1 = sc[0][2];
#pragma unroll
        for (int nf = 0; nf < 8; nf++) {
            mx0 = fmaxf(mx0, fmaxf(sc[nf][0], sc[nf][1]));
            mx1 = fmaxf(mx1, fmaxf(sc[nf][2], sc[nf][3]));
        }
        mx0 = fmaxf(mx0, __shfl_xor_sync(0xffffffffu, mx0, 1));
        mx0 = fmaxf(mx0, __shfl_xor_sync(0xffffffffu, mx0, 2));
        mx1 = fmaxf(mx1, __shfl_xor_sync(0xffffffffu, mx1, 1));
        mx1 = fmaxf(mx1, __shfl_xor_sync(0xffffffffu, mx1, 2));
        const float mn0 = fmaxf(m0, mx0), mn1 = fmaxf(m1, mx1);
        const float al0 = __expf(m0 - mn0), al1 = __expf(m1 - mn1);
        m0 = mn0; m1 = mn1;
        float s0 = 0.0f, s1 = 0.0f;
#pragma unroll
        for (int nf = 0; nf < 8; nf++) {
            sc[nf][0] = __expf(sc[nf][0] - mn0);
            sc[nf][1] = __expf(sc[nf][1] - mn0);
            sc[nf][2] = __expf(sc[nf][2] - mn1);
            sc[nf][3] = __expf(sc[nf][3] - mn1);
            s0 += sc[nf][0] + sc[nf][1];
            s1 += sc[nf][2] + sc[nf][3];
        }
        s0 += __shfl_xor_sync(0xffffffffu, s0, 1);
        s0 += __shfl_xor_sync(0xffffffffu, s0, 2);
        s1 += __shfl_xor_sync(0xffffffffu, s1, 1);
        s1 += __shfl_xor_sync(0xffffffffu, s1, 2);
        l0 = l0 * al0 + s0;
        l1 = l1 * al1 + s1;
#pragma unroll
        for (int nd = 0; nd < 16; nd++) {
            o[nd][0] *= al0; o[nd][1] *= al0;
            o[nd][2] *= al1; o[nd][3] *= al1;
        }

        // ---- P fragments (single fp16) from score registers ----
        uint32_t pf[4][4];
#pragma unroll
        for (int j2 = 0; j2 < 4; j2++) {
            const int f0 = 2 * j2, f1 = f0 + 1;
            __half2 h0 = __floats2half2_rn(sc[f0][0], sc[f0][1]);
            __half2 h1 = __floats2half2_rn(sc[f0][2], sc[f0][3]);
            __half2 h2 = __floats2half2_rn(sc[f1][0], sc[f1][1]);
            __half2 h3 = __floats2half2_rn(sc[f1][2], sc[f1][3]);
            pf[j2][0] = *reinterpret_cast<uint32_t*>(&h0);
            pf[j2][1] = *reinterpret_cast<uint32_t*>(&h1);
            pf[j2][2] = *reinterpret_cast<uint32_t*>(&h2);
            pf[j2][3] = *reinterpret_cast<uint32_t*>(&h3);
        }

        // ---- O += P V (fp16, 2 combos), V via ldmatrix.trans ----
#pragma unroll
        for (int j2 = 0; j2 < 4; j2++) {
            const uint32_t vrow = st + 2 * AT_TILE + v_off + j2 * 16 * AT_LDB;
#pragma unroll
            for (int nd = 0; nd < 16; nd++) {
                uint32_t vbh[2], vbl[2];
                ldm_x2t(vbh, vrow + nd * 16);
                ldm_x2t(vbl, vrow + AT_TILE + nd * 16);
                mma_f16(o[nd], pf[j2], vbh);
                mma_f16(o[nd], pf[j2], vbl);
            }
        }

        __syncthreads();
        if (t + 2 < NT) {
            load_stage(t & 1, t + 2);
            CP_COMMIT();
        }
    }

    // ---- epilogue: normalize, split, store ctx ----
    const float inv0 = 1.0f / l0, inv1 = 1.0f / l1;
    const int rg0 = q0 + warp * 16 + (lane >> 2);
    __nv_bfloat16* och = Ch + base;
    __nv_bfloat16* ocl = Cl + base;
#pragma unroll
    for (int nd = 0; nd < 16; nd++) {
        const int col = nd * 8 + (lane & 3) * 2;
        uint32_t hp, lp;
        packsplit(o[nd][0] * inv0, o[nd][1] * inv0, hp, lp);
        *(uint32_t*)(och + (size_t)rg0 * PHID + col) = hp;
        *(uint32_t*)(ocl + (size_t)rg0 * PHID + col) = lp;
        packsplit(o[nd][2] * inv1, o[nd][3] * inv1, hp, lp);
        *(uint32_t*)(och + (size_t)(rg0 + 8) * PHID + col) = hp;
        *(uint32_t*)(ocl + (size_t)(rg0 + 8) * PHID + col) = lp;
    }
}

// ---------------------------------------------------------------------------
extern "C" void kernel_launch(void* const* d_in, const int* in_sizes, int n_in,
                              void* d_out, int out_size)
{
    (void)in_sizes; (void)n_in; (void)out_size;
    const float* x    = (const float*)d_in[0];
    const float* bias = (const float*)d_in[1];
    const float* Wq   = (const float*)d_in[2];
    const float* bq   = (const float*)d_in[3];
    const float* Wk   = (const float*)d_in[4];
    const float* bk   = (const float*)d_in[5];
    const float* Wv   = (const float*)d_in[6];
    const float* bv   = (const float*)d_in[7];
    const float* Wo   = (const float*)d_in[8];
    const float* bo   = (const float*)d_in[9];
    float* out = (float*)d_out;

    __nv_bfloat16 *xh, *xl, *qh, *ql, *kh, *kl, *ch, *cl;
    __half *vhf, *vlf;
    __nv_bfloat16 *wqh, *wql, *wkh, *wkl, *wvh, *wvl, *woh, *wol;
    cudaGetSymbolAddress((void**)&xh, g_xh);
    cudaGetSymbolAddress((void**)&xl, g_xl);
    cudaGetSymbolAddress((void**)&qh, g_qh);
    cudaGetSymbolAddress((void**)&ql, g_ql);
    cudaGetSymbolAddress((void**)&kh, g_kh);
    cudaGetSymbolAddress((void**)&kl, g_kl);
    cudaGetSymbolAddress((void**)&vhf, g_vhf);
    cudaGetSymbolAddress((void**)&vlf, g_vlf);
    cudaGetSymbolAddress((void**)&ch, g_ch);
    cudaGetSymbolAddress((void**)&cl, g_cl);
    cudaGetSymbolAddress((void**)&wqh, g_wqh);
    cudaGetSymbolAddress((void**)&wql, g_wql);
    cudaGetSymbolAddress((void**)&wkh, g_wkh);
    cudaGetSymbolAddress((void**)&wkl, g_wkl);
    cudaGetSymbolAddress((void**)&wvh, g_wvh);
    cudaGetSymbolAddress((void**)&wvl, g_wvl);
    cudaGetSymbolAddress((void**)&woh, g_woh);
    cudaGetSymbolAddress((void**)&wol, g_wol);

    static bool attr_set = false;
    if (!attr_set) {
        cudaFuncSetAttribute(gemm_qkv,
                             cudaFuncAttributeMaxDynamicSharedMemorySize, GSMEM);
        cudaFuncSetAttribute(gemm_split_mma,
                             cudaFuncAttributeMaxDynamicSharedMemorySize, GSMEM);
        cudaFuncSetAttribute(attn_mma,
                             cudaFuncAttributeMaxDynamicSharedMemorySize, AT_SMEM);
        attr_set = true;
    }

    // 1) conversions
    {
        int n4 = PM * PHID / 4;
        split_bf16_kernel<<<(n4 + 255) / 256, 256>>>(x, xh, xl, n4);
        dim3 tg(PHID / 32, PHID / 32);
        dim3 tb(32, 8);
        transpose_split_kernel<<<tg, tb>>>(Wq, wqh, wql);
        transpose_split_kernel<<<tg, tb>>>(Wk, wkh, wkl);
        transpose_split_kernel<<<tg, tb>>>(Wv, wvh, wvl);
        transpose_split_kernel<<<tg, tb>>>(Wo, woh, wol);
    }

    // 2) merged QKV projections (Q/K -> split bf16, V -> split fp16)
    dim3 qkvgrid(3 * PHID / 128, PM / 128);   // (48, 32)
    gemm_qkv<<<qkvgrid, 256, GSMEM>>>(xh, xl, wqh, wql, wkh, wkl, wvh, wvl,
                                      bq, bk, bv, qh, ql, kh, kl, vhf, vlf);

    // 3) tensor-core attention -> split bf16 ctx
    dim3 agrid(PS / 128, PB * PH);      // (16, 32)
    attn_mma<<<agrid, 256, AT_SMEM>>>(qh, ql, kh, kl, vhf, vlf, bias, ch, cl);

    // 4) output projection -> fp32 out
    dim3 ggrid(PHID / 128, PM / 128);
    gemm_split_mma<<<ggrid, 256, GSMEM>>>(ch, cl, woh, wol, bo, out);
}

// round 8
// speedup vs baseline: 3.3304x; 1.0176x over previous
#include <cuda_runtime.h>
#include <cuda_bf16.h>
#include <cuda_fp16.h>
#include <math.h>
#include <stdint.h>

// Problem constants
#define PB   2
#define PS   2048
#define PHID 2048
#define PH   16
#define PD   128
#define PM   (PB * PS)          // 4096 rows
#define QSCALE 11.313708498984760f   // sqrt(128)

// ---------------------------------------------------------------------------
// Scratch (no cudaMalloc allowed)
// ---------------------------------------------------------------------------
__device__ __nv_bfloat16 g_xh[(size_t)PM * PHID];
__device__ __nv_bfloat16 g_xl[(size_t)PM * PHID];
__device__ __nv_bfloat16 g_qh[(size_t)PM * PHID];
__device__ __nv_bfloat16 g_ql[(size_t)PM * PHID];
__device__ __nv_bfloat16 g_kh[(size_t)PM * PHID];
__device__ __nv_bfloat16 g_kl[(size_t)PM * PHID];
__device__ __half        g_vhf[(size_t)PM * PHID];   // V hi, fp16
__device__ __half        g_vlf[(size_t)PM * PHID];   // V lo, fp16
__device__ __nv_bfloat16 g_ch[(size_t)PM * PHID];
__device__ __nv_bfloat16 g_cl[(size_t)PM * PHID];

// split-bf16 transposed weights [N,K]
__device__ __nv_bfloat16 g_wqh[(size_t)PHID * PHID];
__device__ __nv_bfloat16 g_wql[(size_t)PHID * PHID];
__device__ __nv_bfloat16 g_wkh[(size_t)PHID * PHID];
__device__ __nv_bfloat16 g_wkl[(size_t)PHID * PHID];
__device__ __nv_bfloat16 g_wvh[(size_t)PHID * PHID];
__device__ __nv_bfloat16 g_wvl[(size_t)PHID * PHID];
__device__ __nv_bfloat16 g_woh[(size_t)PHID * PHID];
__device__ __nv_bfloat16 g_wol[(size_t)PHID * PHID];

// ---------------------------------------------------------------------------
// Helpers
// ---------------------------------------------------------------------------
__device__ __forceinline__ uint32_t smem_u32(const void* p) {
    uint32_t a;
    asm("{ .reg .u64 t; cvta.to.shared.u64 t, %1; cvt.u32.u64 %0, t; }"
        : "=r"(a) : "l"(p));
    return a;
}

__device__ __forceinline__ void cp16(uint32_t s, const void* g) {
    asm volatile("cp.async.cg.shared.global [%0], [%1], 16;" :: "r"(s), "l"(g));
}
#define CP_COMMIT() asm volatile("cp.async.commit_group;" ::: "memory")
#define CP_WAIT(n)  asm volatile("cp.async.wait_group %0;" :: "n"(n) : "memory")

__device__ __forceinline__ void ldm_x4(uint32_t* r, uint32_t addr) {
    asm volatile("ldmatrix.sync.aligned.m8n8.x4.shared.b16 {%0,%1,%2,%3}, [%4];"
                 : "=r"(r[0]), "=r"(r[1]), "=r"(r[2]), "=r"(r[3]) : "r"(addr));
}
__device__ __forceinline__ void ldm_x4t(uint32_t* r, uint32_t addr) {
    asm volatile("ldmatrix.sync.aligned.m8n8.x4.trans.shared.b16 {%0,%1,%2,%3}, [%4];"
                 : "=r"(r[0]), "=r"(r[1]), "=r"(r[2]), "=r"(r[3]) : "r"(addr));
}
__device__ __forceinline__ void mma_bf16(float* c, const uint32_t* a, const uint32_t* b) {
    asm volatile(
        "mma.sync.aligned.m16n8k16.row.col.f32.bf16.bf16.f32 "
        "{%0,%1,%2,%3}, {%4,%5,%6,%7}, {%8,%9}, {%0,%1,%2,%3};"
        : "+f"(c[0]), "+f"(c[1]), "+f"(c[2]), "+f"(c[3])
        : "r"(a[0]), "r"(a[1]), "r"(a[2]), "r"(a[3]), "r"(b[0]), "r"(b[1]));
}
__device__ __forceinline__ void mma_f16(float* c, const uint32_t* a, const uint32_t* b) {
    asm volatile(
        "mma.sync.aligned.m16n8k16.row.col.f32.f16.f16.f32 "
        "{%0,%1,%2,%3}, {%4,%5,%6,%7}, {%8,%9}, {%0,%1,%2,%3};"
        : "+f"(c[0]), "+f"(c[1]), "+f"(c[2]), "+f"(c[3])
        : "r"(a[0]), "r"(a[1]), "r"(a[2]), "r"(a[3]), "r"(b[0]), "r"(b[1]));
}

__device__ __forceinline__ float ex2f(float x) {
    float r;
    asm("ex2.approx.f32 %0, %1;" : "=f"(r) : "f"(x));
    return r;
}

// exp2 on the FMA/ALU pipes: magic-number floor + deg-4 poly, rel err ~4e-5.
__device__ __forceinline__ float exp2_poly(float y) {
    y = fmaxf(y, -80.0f);
    float z = y + 12582912.0f;           // 1.5 * 2^23
    uint32_t iz = __float_as_uint(z);
    float f = y - (z - 12582912.0f);     // f in [-0.5, 0.5]
    float p = fmaf(0.00961813f, f, 0.05550411f);
    p = fmaf(p, f, 0.24022651f);
    p = fmaf(p, f, 0.69314718f);
    p = fmaf(p, f, 1.0f);
    return p * __uint_as_float((iz << 23) + 0x3F800000u);
}

// Fast RNE split of two floats into (hi bf16x2, lo bf16x2).
__device__ __forceinline__ void packsplit(float a, float b, uint32_t& hp, uint32_t& lp) {
    asm("cvt.rn.bf16x2.f32 %0, %1, %2;" : "=r"(hp) : "f"(b), "f"(a));
    float ah = __uint_as_float(hp << 16);
    float bh = __uint_as_float(hp & 0xFFFF0000u);
    float la = a - ah;
    float lb = b - bh;
    asm("cvt.rn.bf16x2.f32 %0, %1, %2;" : "=r"(lp) : "f"(lb), "f"(la));
}

// RNE split of two floats into (hi f16x2, lo f16x2).
__device__ __forceinline__ void packsplit_f16(float a, float b, uint32_t& hp, uint32_t& lp) {
    __half2 h = __floats2half2_rn(a, b);
    float la = a - __half2float(__low2half(h));
    float lb = b - __half2float(__high2half(h));
    __half2 l = __floats2half2_rn(la, lb);
    hp = *reinterpret_cast<uint32_t*>(&h);
    lp = *reinterpret_cast<uint32_t*>(&l);
}

// ---------------------------------------------------------------------------
// Conversion kernels
// ---------------------------------------------------------------------------
__global__ void split_bf16_kernel(const float* __restrict__ in,
                                  __nv_bfloat16* __restrict__ hi,
                                  __nv_bfloat16* __restrict__ lo, int n4)
{
    int i = blockIdx.x * blockDim.x + threadIdx.x;
    if (i >= n4) return;
    float4 v = ((const float4*)in)[i];
    uint32_t h0, l0, h1, l1;
    packsplit(v.x, v.y, h0, l0);
    packsplit(v.z, v.w, h1, l1);
    ((uint32_t*)hi)[2*i]   = h0;
    ((uint32_t*)hi)[2*i+1] = h1;
    ((uint32_t*)lo)[2*i]   = l0;
    ((uint32_t*)lo)[2*i+1] = l1;
}

__global__ void transpose_split_kernel(const float* __restrict__ W,
                                       __nv_bfloat16* __restrict__ Th,
                                       __nv_bfloat16* __restrict__ Tl)
{
    __shared__ float t[32][33];
    int n0 = blockIdx.x * 32, k0 = blockIdx.y * 32;
    int tx = threadIdx.x, ty0 = threadIdx.y;   // 32 x 8
#pragma unroll
    for (int j = 0; j < 32; j += 8)
        t[ty0 + j][tx] = W[(size_t)(k0 + ty0 + j) * PHID + n0 + tx];
    __syncthreads();
#pragma unroll
    for (int j = 0; j < 32; j += 8) {
        int n = ty0 + j;
        float v = t[tx][n];
        __nv_bfloat16 h = __float2bfloat16(v);
        __nv_bfloat16 l = __float2bfloat16(v - __bfloat162float(h));
        size_t o = (size_t)(n0 + n) * PHID + k0 + tx;
        Th[o] = h;
        Tl[o] = l;
    }
}

// ---------------------------------------------------------------------------
// Shared GEMM tile config
// ---------------------------------------------------------------------------
#define LDT   40
#define TILE_B (128 * LDT * 2)   // 10240
#define OFF_AH 0
#define OFF_AL (TILE_B)
#define OFF_BH (2 * TILE_B)
#define OFF_BL (3 * TILE_B)
#define STAGE_B (4 * TILE_B)     // 40960
#define GSMEM  (2 * STAGE_B)     // 81920

// ---------------------------------------------------------------------------
// Merged QKV projection GEMM: one launch, sel = blockIdx.x>>4 picks Q/K/V.
// ---------------------------------------------------------------------------
__global__ __launch_bounds__(256, 2) void gemm_qkv(
    const __nv_bfloat16* __restrict__ Ah, const __nv_bfloat16* __restrict__ Al,
    const __nv_bfloat16* __restrict__ Wqh, const __nv_bfloat16* __restrict__ Wql,
    const __nv_bfloat16* __restrict__ Wkh, const __nv_bfloat16* __restrict__ Wkl,
    const __nv_bfloat16* __restrict__ Wvh, const __nv_bfloat16* __restrict__ Wvl,
    const float* __restrict__ bq, const float* __restrict__ bk,
    const float* __restrict__ bv,
    __nv_bfloat16* __restrict__ Qh, __nv_bfloat16* __restrict__ Ql,
    __nv_bfloat16* __restrict__ Kh, __nv_bfloat16* __restrict__ Kl,
    __half* __restrict__ Vh, __half* __restrict__ Vl)
{
    extern __shared__ char smem[];
    const uint32_t sb = smem_u32(smem);
    const int tid  = threadIdx.x;
    const int lane = tid & 31;
    const int warp = tid >> 5;
    const int wm = warp >> 2;
    const int wn = warp & 3;
    const int sel = blockIdx.x >> 4;            // 0=Q 1=K 2=V
    const int n0  = (blockIdx.x & 15) * 128;
    const int m0  = blockIdx.y * 128;

    const __nv_bfloat16* Bh = (sel == 0) ? Wqh : (sel == 1) ? Wkh : Wvh;
    const __nv_bfloat16* Bl = (sel == 0) ? Wql : (sel == 1) ? Wkl : Wvl;
    const float* bias = (sel == 0) ? bq : (sel == 1) ? bk : bv;
    const float scale = (sel == 0) ? QSCALE : 1.0f;

    const __nv_bfloat16* pAh = Ah + (size_t)m0 * PHID;
    const __nv_bfloat16* pAl = Al + (size_t)m0 * PHID;
    const __nv_bfloat16* pBh = Bh + (size_t)n0 * PHID;
    const __nv_bfloat16* pBl = Bl + (size_t)n0 * PHID;

    const int r0 = tid >> 2;
    const int c0 = (tid & 3) * 8;
    const uint32_t so0 = (uint32_t)(r0 * 80 + (tid & 3) * 16);
    const uint32_t so1 = (uint32_t)((r0 + 64) * 80 + (tid & 3) * 16);

    const uint32_t a_off = (uint32_t)((wm * 64 + (lane & 15)) * 80 + ((lane >> 4) << 4));
    // x4 B-operand offset: covers 2 ni per load
    const uint32_t b4_off = (uint32_t)((wn * 32 + ((lane >> 4) << 3) + (lane & 7)) * 80
                                       + ((lane & 8) ? 16 : 0));

    float acc[4][4][4];
#pragma unroll
    for (int mi = 0; mi < 4; mi++)
#pragma unroll
        for (int ni = 0; ni < 4; ni++)
#pragma unroll
            for (int j = 0; j < 4; j++) acc[mi][ni][j] = 0.0f;

    auto load_stage = [&](int stage, int kc) {
        const uint32_t st = sb + stage * STAGE_B;
        const size_t g0 = (size_t)r0 * PHID + kc * 32 + c0;
        const size_t g1 = (size_t)(r0 + 64) * PHID + kc * 32 + c0;
        cp16(st + OFF_AH + so0, pAh + g0);
        cp16(st + OFF_AH + so1, pAh + g1);
        cp16(st + OFF_AL + so0, pAl + g0);
        cp16(st + OFF_AL + so1, pAl + g1);
        cp16(st + OFF_BH + so0, pBh + g0);
        cp16(st + OFF_BH + so1, pBh + g1);
        cp16(st + OFF_BL + so0, pBl + g0);
        cp16(st + OFF_BL + so1, pBl + g1);
    };

    auto compute_stage = [&](int stage) {
        const uint32_t st = sb + stage * STAGE_B;
#pragma unroll
        for (int ks = 0; ks < 2; ks++) {
            const uint32_t k32 = ks * 32;
            uint32_t bhf[4][2], blf[4][2], a[4][4];
            ldm_x4(&bhf[0][0], st + OFF_BH + b4_off + k32);
            ldm_x4(&bhf[2][0], st + OFF_BH + b4_off + 1280 + k32);
            ldm_x4(&blf[0][0], st + OFF_BL + b4_off + k32);
            ldm_x4(&blf[2][0], st + OFF_BL + b4_off + 1280 + k32);
#pragma unroll
            for (int mi = 0; mi < 4; mi++)
                ldm_x4(a[mi], st + OFF_AH + a_off + mi * 1280 + k32);
#pragma unroll
            for (int mi = 0; mi < 4; mi++)
#pragma unroll
                for (int ni = 0; ni < 4; ni++)
                    mma_bf16(acc[mi][ni], a[mi], bhf[ni]);
#pragma unroll
            for (int mi = 0; mi < 4; mi++)
#pragma unroll
                for (int ni = 0; ni < 4; ni++)
                    mma_bf16(acc[mi][ni], a[mi], blf[ni]);
#pragma unroll
            for (int mi = 0; mi < 4; mi++)
                ldm_x4(a[mi], st + OFF_AL + a_off + mi * 1280 + k32);
#pragma unroll
            for (int mi = 0; mi < 4; mi++)
#pragma unroll
                for (int ni = 0; ni < 4; ni++)
                    mma_bf16(acc[mi][ni], a[mi], bhf[ni]);
        }
    };

    load_stage(0, 0);
    CP_COMMIT();
    const int NKC = PHID / 32;
    for (int kc = 0; kc < NKC; kc++) {
        if (kc + 1 < NKC) {
            load_stage((kc + 1) & 1, kc + 1);
            CP_COMMIT();
            CP_WAIT(1);
        } else {
            CP_WAIT(0);
        }
        __syncthreads();
        compute_stage(kc & 1);
        __syncthreads();
    }

#pragma unroll
    for (int mi = 0; mi < 4; mi++) {
        const int row = m0 + wm * 64 + mi * 16 + (lane >> 2);
#pragma unroll
        for (int ni = 0; ni < 4; ni++) {
            const int col = n0 + wn * 32 + ni * 8 + (lane & 3) * 2;
            const float b0 = bias[col], b1 = bias[col + 1];
            float v00 = (acc[mi][ni][0] + b0) * scale;
            float v01 = (acc[mi][ni][1] + b1) * scale;
            float v10 = (acc[mi][ni][2] + b0) * scale;
            float v11 = (acc[mi][ni][3] + b1) * scale;
            uint32_t hp, lp;
            if (sel == 2) {
                packsplit_f16(v00, v01, hp, lp);
                *(uint32_t*)(Vh + (size_t)row * PHID + col) = hp;
                *(uint32_t*)(Vl + (size_t)row * PHID + col) = lp;
                packsplit_f16(v10, v11, hp, lp);
                *(uint32_t*)(Vh + (size_t)(row + 8) * PHID + col) = hp;
                *(uint32_t*)(Vl + (size_t)(row + 8) * PHID + col) = lp;
            } else {
                __nv_bfloat16* Oh = (sel == 0) ? Qh : Kh;
                __nv_bfloat16* Ol = (sel == 0) ? Ql : Kl;
                packsplit(v00, v01, hp, lp);
                *(uint32_t*)(Oh + (size_t)row * PHID + col) = hp;
                *(uint32_t*)(Ol + (size_t)row * PHID + col) = lp;
                packsplit(v10, v11, hp, lp);
                *(uint32_t*)(Oh + (size_t)(row + 8) * PHID + col) = hp;
                *(uint32_t*)(Ol + (size_t)(row + 8) * PHID + col) = lp;
            }
        }
    }
}

// ---------------------------------------------------------------------------
// Output projection GEMM (split-bf16 in, fp32 out).
// ---------------------------------------------------------------------------
__global__ __launch_bounds__(256, 2) void gemm_split_mma(
    const __nv_bfloat16* __restrict__ Ah, const __nv_bfloat16* __restrict__ Al,
    const __nv_bfloat16* __restrict__ Bh, const __nv_bfloat16* __restrict__ Bl,
    const float* __restrict__ bias, float* __restrict__ C)
{
    extern __shared__ char smem[];
    const uint32_t sb = smem_u32(smem);
    const int tid  = threadIdx.x;
    const int lane = tid & 31;
    const int warp = tid >> 5;
    const int wm = warp >> 2;
    const int wn = warp & 3;
    const int m0 = blockIdx.y * 128;
    const int n0 = blockIdx.x * 128;

    const __nv_bfloat16* pAh = Ah + (size_t)m0 * PHID;
    const __nv_bfloat16* pAl = Al + (size_t)m0 * PHID;
    const __nv_bfloat16* pBh = Bh + (size_t)n0 * PHID;
    const __nv_bfloat16* pBl = Bl + (size_t)n0 * PHID;

    const int r0 = tid >> 2;
    const int c0 = (tid & 3) * 8;
    const uint32_t so0 = (uint32_t)(r0 * 80 + (tid & 3) * 16);
    const uint32_t so1 = (uint32_t)((r0 + 64) * 80 + (tid & 3) * 16);

    const uint32_t a_off = (uint32_t)((wm * 64 + (lane & 15)) * 80 + ((lane >> 4) << 4));
    const uint32_t b4_off = (uint32_t)((wn * 32 + ((lane >> 4) << 3) + (lane & 7)) * 80
                                       + ((lane & 8) ? 16 : 0));

    float acc[4][4][4];
#pragma unroll
    for (int mi = 0; mi < 4; mi++)
#pragma unroll
        for (int ni = 0; ni < 4; ni++)
#pragma unroll
            for (int j = 0; j < 4; j++) acc[mi][ni][j] = 0.0f;

    auto load_stage = [&](int stage, int kc) {
        const uint32_t st = sb + stage * STAGE_B;
        const size_t g0 = (size_t)r0 * PHID + kc * 32 + c0;
        const size_t g1 = (size_t)(r0 + 64) * PHID + kc * 32 + c0;
        cp16(st + OFF_AH + so0, pAh + g0);
        cp16(st + OFF_AH + so1, pAh + g1);
        cp16(st + OFF_AL + so0, pAl + g0);
        cp16(st + OFF_AL + so1, pAl + g1);
        cp16(st + OFF_BH + so0, pBh + g0);
        cp16(st + OFF_BH + so1, pBh + g1);
        cp16(st + OFF_BL + so0, pBl + g0);
        cp16(st + OFF_BL + so1, pBl + g1);
    };

    auto compute_stage = [&](int stage) {
        const uint32_t st = sb + stage * STAGE_B;
#pragma unroll
        for (int ks = 0; ks < 2; ks++) {
            const uint32_t k32 = ks * 32;
            uint32_t bhf[4][2], blf[4][2], a[4][4];
            ldm_x4(&bhf[0][0], st + OFF_BH + b4_off + k32);
            ldm_x4(&bhf[2][0], st + OFF_BH + b4_off + 1280 + k32);
            ldm_x4(&blf[0][0], st + OFF_BL + b4_off + k32);
            ldm_x4(&blf[2][0], st + OFF_BL + b4_off + 1280 + k32);
#pragma unroll
            for (int mi = 0; mi < 4; mi++)
                ldm_x4(a[mi], st + OFF_AH + a_off + mi * 1280 + k32);
#pragma unroll
            for (int mi = 0; mi < 4; mi++)
#pragma unroll
                for (int ni = 0; ni < 4; ni++)
                    mma_bf16(acc[mi][ni], a[mi], bhf[ni]);
#pragma unroll
            for (int mi = 0; mi < 4; mi++)
#pragma unroll
                for (int ni = 0; ni < 4; ni++)
                    mma_bf16(acc[mi][ni], a[mi], blf[ni]);
#pragma unroll
            for (int mi = 0; mi < 4; mi++)
                ldm_x4(a[mi], st + OFF_AL + a_off + mi * 1280 + k32);
#pragma unroll
            for (int mi = 0; mi < 4; mi++)
#pragma unroll
                for (int ni = 0; ni < 4; ni++)
                    mma_bf16(acc[mi][ni], a[mi], bhf[ni]);
        }
    };

    load_stage(0, 0);
    CP_COMMIT();
    const int NKC = PHID / 32;
    for (int kc = 0; kc < NKC; kc++) {
        if (kc + 1 < NKC) {
            load_stage((kc + 1) & 1, kc + 1);
            CP_COMMIT();
            CP_WAIT(1);
        } else {
            CP_WAIT(0);
        }
        __syncthreads();
        compute_stage(kc & 1);
        __syncthreads();
    }

#pragma unroll
    for (int mi = 0; mi < 4; mi++) {
        const int row = m0 + wm * 64 + mi * 16 + (lane >> 2);
#pragma unroll
        for (int ni = 0; ni < 4; ni++) {
            const int col = n0 + wn * 32 + ni * 8 + (lane & 3) * 2;
            const float b0 = bias[col], b1 = bias[col + 1];
            *(float2*)(C + (size_t)row * PHID + col) =
                make_float2(acc[mi][ni][0] + b0, acc[mi][ni][1] + b1);
            *(float2*)(C + (size_t)(row + 8) * PHID + col) =
                make_float2(acc[mi][ni][2] + b0, acc[mi][ni][3] + b1);
        }
    }
}

// ---------------------------------------------------------------------------
// Tensor-core flash attention: QK split-bf16 (3 combos), PV fp16 (2 combos),
// row sums via ones-MMA, exp split across MUFU + FMA-poly pipes.
// ---------------------------------------------------------------------------
#define AT_LDB  272
#define AT_QH   0
#define AT_QL   (128 * AT_LDB)            // 34816
#define AT_ST0  (2 * 128 * AT_LDB)        // 69632
#define AT_TILE (64 * AT_LDB)             // 17408
#define AT_STAGE (4 * AT_TILE)            // 69632
#define AT_SMEM (AT_ST0 + 2 * AT_STAGE)   // 208896

__global__ __launch_bounds__(256, 1) void attn_mma(
    const __nv_bfloat16* __restrict__ Qh, const __nv_bfloat16* __restrict__ Ql,
    const __nv_bfloat16* __restrict__ Kh, const __nv_bfloat16* __restrict__ Kl,
    const __half* __restrict__ Vh, const __half* __restrict__ Vl,
    const float* __restrict__ Bias,
    __nv_bfloat16* __restrict__ Ch, __nv_bfloat16* __restrict__ Cl)
{
    extern __shared__ char smem[];
    const uint32_t sb = smem_u32(smem);
    const int tid = threadIdx.x;
    const int lane = tid & 31;
    const int warp = tid >> 5;
    const int bh = blockIdx.y;
    const int b  = bh >> 4;
    const int h  = bh & 15;
    const int q0 = blockIdx.x * 128;
    const float L2E = 1.44269504f;

    const size_t base = (size_t)b * PS * PHID + (size_t)h * PD;
    const __nv_bfloat16* pQh = Qh + base + (size_t)q0 * PHID;
    const __nv_bfloat16* pQl = Ql + base + (size_t)q0 * PHID;
    const __nv_bfloat16* pKh = Kh + base;
    const __nv_bfloat16* pKl = Kl + base;
    const __half* pVh = Vh + base;
    const __half* pVl = Vl + base;

    // Q loader
    {
        const int r = tid >> 1;
        const int ce = (tid & 1) * 64;
        const uint32_t so = (uint32_t)(r * AT_LDB + (tid & 1) * 128);
#pragma unroll
        for (int i = 0; i < 8; i++) {
            cp16(sb + AT_QH + so + i * 16, pQh + (size_t)r * PHID + ce + i * 8);
            cp16(sb + AT_QL + so + i * 16, pQl + (size_t)r * PHID + ce + i * 8);
        }
    }

    // K/V stage loader
    const int kvr  = tid >> 2;
    const int kvce = (tid & 3) * 32;
    const uint32_t kvso = (uint32_t)(kvr * AT_LDB + (tid & 3) * 64);
    auto load_stage = [&](int stage, int t) {
        const uint32_t st = sb + AT_ST0 + stage * AT_STAGE;
        const size_t g = (size_t)(t * 64 + kvr) * PHID + kvce;
#pragma unroll
        for (int i = 0; i < 4; i++) {
            cp16(st + kvso + i * 16,               pKh + g + i * 8);
            cp16(st + AT_TILE + kvso + i * 16,     pKl + g + i * 8);
            cp16(st + 2 * AT_TILE + kvso + i * 16, pVh + g + i * 8);
            cp16(st + 3 * AT_TILE + kvso + i * 16, pVl + g + i * 8);
        }
    };

    load_stage(0, 0);
    CP_COMMIT();
    load_stage(1, 1);
    CP_COMMIT();

    const uint32_t q_off = (uint32_t)((warp * 16 + (lane & 15)) * AT_LDB + ((lane >> 4) << 4));
    // x4 K offset: covers 2 nf per load
    const uint32_t k4_off = (uint32_t)((((lane >> 4) << 3) + (lane & 7)) * AT_LDB
                                       + ((lane & 8) ? 16 : 0));
    // x4t V offset: covers 2 nd per load
    const uint32_t v4_off = (uint32_t)((((lane >> 3) & 1) * 8 + (lane & 7)) * AT_LDB
                                       + (lane >> 4) * 16);

    const float* biasR0 = Bias + ((size_t)bh * PS + q0 + warp * 16 + (lane >> 2)) * PS;
    const float* biasR1 = biasR0 + 8 * PS;
    const int bcol = (lane & 3) * 2;

    float o[16][4];
#pragma unroll
    for (int nd = 0; nd < 16; nd++)
#pragma unroll
        for (int j = 0; j < 4; j++) o[nd][j] = 0.0f;
    float lacc[4] = {0.0f, 0.0f, 0.0f, 0.0f};
    float m0 = -1e30f, m1 = -1e30f;
    const uint32_t ONESB[2] = {0x3C003C00u, 0x3C003C00u};

    // bias prefetch registers
    float2 nb0[8], nb1[8];
#pragma unroll
    for (int nf = 0; nf < 8; nf++) {
        nb0[nf] = *(const float2*)(biasR0 + nf * 8 + bcol);
        nb1[nf] = *(const float2*)(biasR1 + nf * 8 + bcol);
    }

    const int NT = PS / 64;   // 32
    for (int t = 0; t < NT; t++) {
        if (t < NT - 2) CP_WAIT(1); else CP_WAIT(0);
        __syncthreads();

        const uint32_t st = sb + AT_ST0 + (t & 1) * AT_STAGE;

        // consume prefetched bias, then prefetch next tile's bias
        float sc[8][4];
#pragma unroll
        for (int nf = 0; nf < 8; nf++) {
            sc[nf][0] = nb0[nf].x; sc[nf][1] = nb0[nf].y;
            sc[nf][2] = nb1[nf].x; sc[nf][3] = nb1[nf].y;
        }
        if (t + 1 < NT) {
            const int k1 = (t + 1) * 64;
#pragma unroll
            for (int nf = 0; nf < 8; nf++) {
                nb0[nf] = *(const float2*)(biasR0 + k1 + nf * 8 + bcol);
                nb1[nf] = *(const float2*)(biasR1 + k1 + nf * 8 + bcol);
            }
        }

        // ---- scores += Q K^T (split 3-combo), K via x4 pairs ----
#pragma unroll
        for (int ks = 0; ks < 8; ks++) {
            uint32_t qa[4], qla[4];
            ldm_x4(qa,  sb + AT_QH + q_off + ks * 32);
            ldm_x4(qla, sb + AT_QL + q_off + ks * 32);
#pragma unroll
            for (int nf2 = 0; nf2 < 4; nf2++) {
                uint32_t kbh[4], kbl[4];
                ldm_x4(kbh, st + k4_off + nf2 * 16 * AT_LDB + ks * 32);
                ldm_x4(kbl, st + AT_TILE + k4_off + nf2 * 16 * AT_LDB + ks * 32);
                mma_bf16(sc[2*nf2],   qa,  kbh);
                mma_bf16(sc[2*nf2+1], qa,  kbh + 2);
                mma_bf16(sc[2*nf2],   qa,  kbl);
                mma_bf16(sc[2*nf2+1], qa,  kbl + 2);
                mma_bf16(sc[2*nf2],   qla, kbh);
                mma_bf16(sc[2*nf2+1], qla, kbh + 2);
            }
        }

        // ---- online softmax: max ----
        float mx0 = sc[0][0], mx1 = sc[0][2];
#pragma unroll
        for (int nf = 0; nf < 8; nf++) {
            mx0 = fmaxf(mx0, fmaxf(sc[nf][0], sc[nf][1]));
            mx1 = fmaxf(mx1, fmaxf(sc[nf][2], sc[nf][3]));
        }
        mx0 = fmaxf(mx0, __shfl_xor_sync(0xffffffffu, mx0, 1));
        mx0 = fmaxf(mx0, __shfl_xor_sync(0xffffffffu, mx0, 2));
        mx1 = fmaxf(mx1, __shfl_xor_sync(0xffffffffu, mx1, 1));
        mx1 = fmaxf(mx1, __shfl_xor_sync(0xffffffffu, mx1, 2));
        const float mn0 = fmaxf(m0, mx0), mn1 = fmaxf(m1, mx1);
        const float mL0 = mn0 * L2E, mL1 = mn1 * L2E;
        const float al0 = ex2f((m0 - mn0) * L2E);
        const float al1 = ex2f((m1 - mn1) * L2E);
        m0 = mn0; m1 = mn1;

        // ---- exp: 8 elements on FMA-poly, 24 on MUFU ----
#pragma unroll
        for (int nf = 0; nf < 2; nf++) {
            sc[nf][0] = exp2_poly(fmaf(sc[nf][0], L2E, -mL0));
            sc[nf][1] = exp2_poly(fmaf(sc[nf][1], L2E, -mL0));
            sc[nf][2] = exp2_poly(fmaf(sc[nf][2], L2E, -mL1));
            sc[nf][3] = exp2_poly(fmaf(sc[nf][3], L2E, -mL1));
        }
#pragma unroll
        for (int nf = 2; nf < 8; nf++) {
            sc[nf][0] = ex2f(fmaf(sc[nf][0], L2E, -mL0));
            sc[nf][1] = ex2f(fmaf(sc[nf][1], L2E, -mL0));
            sc[nf][2] = ex2f(fmaf(sc[nf][2], L2E, -mL1));
            sc[nf][3] = ex2f(fmaf(sc[nf][3], L2E, -mL1));
        }

        // ---- rescale o and l accumulators (skip when max unchanged) ----
        if (al0 != 1.0f || al1 != 1.0f) {
#pragma unroll
            for (int nd = 0; nd < 16; nd++) {
                o[nd][0] *= al0; o[nd][1] *= al0;
                o[nd][2] *= al1; o[nd][3] *= al1;
            }
            lacc[0] *= al0; lacc[1] *= al0;
            lacc[2] *= al1; lacc[3] *= al1;
        }

        // ---- P fragments (fp16) ----
        uint32_t pf[4][4];
#pragma unroll
        for (int j2 = 0; j2 < 4; j2++) {
            const int f0 = 2 * j2, f1 = f0 + 1;
            __half2 h0 = __floats2half2_rn(sc[f0][0], sc[f0][1]);
            __half2 h1 = __floats2half2_rn(sc[f0][2], sc[f0][3]);
            __half2 h2 = __floats2half2_rn(sc[f1][0], sc[f1][1]);
            __half2 h3 = __floats2half2_rn(sc[f1][2], sc[f1][3]);
            pf[j2][0] = *reinterpret_cast<uint32_t*>(&h0);
            pf[j2][1] = *reinterpret_cast<uint32_t*>(&h1);
            pf[j2][2] = *reinterpret_cast<uint32_t*>(&h2);
            pf[j2][3] = *reinterpret_cast<uint32_t*>(&h3);
        }

        // ---- O += P V; l += P 1 (ones-MMA); V via x4.trans pairs ----
#pragma unroll
        for (int j2 = 0; j2 < 4; j2++) {
            mma_f16(lacc, pf[j2], ONESB);
            const uint32_t vrow = st + 2 * AT_TILE + v4_off + j2 * 16 * AT_LDB;
#pragma unroll
            for (int nd2 = 0; nd2 < 8; nd2++) {
                uint32_t vbh[4], vbl[4];
                ldm_x4t(vbh, vrow + nd2 * 32);
                ldm_x4t(vbl, vrow + AT_TILE + nd2 * 32);
                mma_f16(o[2*nd2],   pf[j2], vbh);
                mma_f16(o[2*nd2+1], pf[j2], vbh + 2);
                mma_f16(o[2*nd2],   pf[j2], vbl);
                mma_f16(o[2*nd2+1], pf[j2], vbl + 2);
            }
        }

        __syncthreads();
        if (t + 2 < NT) {
            load_stage(t & 1, t + 2);
            CP_COMMIT();
        }
    }

    // ---- epilogue: normalize, split, store ctx ----
    const float inv0 = 1.0f / lacc[0], inv1 = 1.0f / lacc[2];
    const int rg0 = q0 + warp * 16 + (lane >> 2);
    __nv_bfloat16* och = Ch + base;
    __nv_bfloat16* ocl = Cl + base;
#pragma unroll
    for (int nd = 0; nd < 16; nd++) {
        const int col = nd * 8 + (lane & 3) * 2;
        uint32_t hp, lp;
        packsplit(o[nd][0] * inv0, o[nd][1] * inv0, hp, lp);
        *(uint32_t*)(och + (size_t)rg0 * PHID + col) = hp;
        *(uint32_t*)(ocl + (size_t)rg0 * PHID + col) = lp;
        packsplit(o[nd][2] * inv1, o[nd][3] * inv1, hp, lp);
        *(uint32_t*)(och + (size_t)(rg0 + 8) * PHID + col) = hp;
        *(uint32_t*)(ocl + (size_t)(rg0 + 8) * PHID + col) = lp;
    }
}

// ---------------------------------------------------------------------------
extern "C" void kernel_launch(void* const* d_in, const int* in_sizes, int n_in,
                              void* d_out, int out_size)
{
    (void)in_sizes; (void)n_in; (void)out_size;
    const float* x    = (const float*)d_in[0];
    const float* bias = (const float*)d_in[1];
    const float* Wq   = (const float*)d_in[2];
    const float* bq   = (const float*)d_in[3];
    const float* Wk   = (const float*)d_in[4];
    const float* bk   = (const float*)d_in[5];
    const float* Wv   = (const float*)d_in[6];
    const float* bv   = (const float*)d_in[7];
    const float* Wo   = (const float*)d_in[8];
    const float* bo   = (const float*)d_in[9];
    float* out = (float*)d_out;

    __nv_bfloat16 *xh, *xl, *qh, *ql, *kh, *kl, *ch, *cl;
    __half *vhf, *vlf;
    __nv_bfloat16 *wqh, *wql, *wkh, *wkl, *wvh, *wvl, *woh, *wol;
    cudaGetSymbolAddress((void**)&xh, g_xh);
    cudaGetSymbolAddress((void**)&xl, g_xl);
    cudaGetSymbolAddress((void**)&qh, g_qh);
    cudaGetSymbolAddress((void**)&ql, g_ql);
    cudaGetSymbolAddress((void**)&kh, g_kh);
    cudaGetSymbolAddress((void**)&kl, g_kl);
    cudaGetSymbolAddress((void**)&vhf, g_vhf);
    cudaGetSymbolAddress((void**)&vlf, g_vlf);
    cudaGetSymbolAddress((void**)&ch, g_ch);
    cudaGetSymbolAddress((void**)&cl, g_cl);
    cudaGetSymbolAddress((void**)&wqh, g_wqh);
    cudaGetSymbolAddress((void**)&wql, g_wql);
    cudaGetSymbolAddress((void**)&wkh, g_wkh);
    cudaGetSymbolAddress((void**)&wkl, g_wkl);
    cudaGetSymbolAddress((void**)&wvh, g_wvh);
    cudaGetSymbolAddress((void**)&wvl, g_wvl);
    cudaGetSymbolAddress((void**)&woh, g_woh);
    cudaGetSymbolAddress((void**)&wol, g_wol);

    static bool attr_set = false;
    if (!attr_set) {
        cudaFuncSetAttribute(gemm_qkv,
                             cudaFuncAttributeMaxDynamicSharedMemorySize, GSMEM);
        cudaFuncSetAttribute(gemm_split_mma,
                             cudaFuncAttributeMaxDynamicSharedMemorySize, GSMEM);
        cudaFuncSetAttribute(attn_mma,
                             cudaFuncAttributeMaxDynamicSharedMemorySize, AT_SMEM);
        attr_set = true;
    }

    // 1) conversions
    {
        int n4 = PM * PHID / 4;
        split_bf16_kernel<<<(n4 + 255) / 256, 256>>>(x, xh, xl, n4);
        dim3 tg(PHID / 32, PHID / 32);
        dim3 tb(32, 8);
        transpose_split_kernel<<<tg, tb>>>(Wq, wqh, wql);
        transpose_split_kernel<<<tg, tb>>>(Wk, wkh, wkl);
        transpose_split_kernel<<<tg, tb>>>(Wv, wvh, wvl);
        transpose_split_kernel<<<tg, tb>>>(Wo, woh, wol);
    }

    // 2) merged QKV projections (Q/K -> split bf16, V -> split fp16)
    dim3 qkvgrid(3 * PHID / 128, PM / 128);   // (48, 32)
    gemm_qkv<<<qkvgrid, 256, GSMEM>>>(xh, xl, wqh, wql, wkh, wkl, wvh, wvl,
                                      bq, bk, bv, qh, ql, kh, kl, vhf, vlf);

    // 3) tensor-core attention -> split bf16 ctx
    dim3 agrid(PS / 128, PB * PH);      // (16, 32)
    attn_mma<<<agrid, 256, AT_SMEM>>>(qh, ql, kh, kl, vhf, vlf, bias, ch, cl);

    // 4) output projection -> fp32 out
    dim3 ggrid(PHID / 128, PM / 128);
    gemm_split_mma<<<ggrid, 256, GSMEM>>>(ch, cl, woh, wol, bo, out);
}

// round 9
// speedup vs baseline: 3.6974x; 1.1102x over previous
#include <cuda_runtime.h>
#include <cuda_bf16.h>
#include <cuda_fp16.h>
#include <math.h>
#include <stdint.h>

// Problem constants
#define PB   2
#define PS   2048
#define PHID 2048
#define PH   16
#define PD   128
#define PM   (PB * PS)          // 4096 rows
#define QSCALE 11.313708498984760f   // sqrt(128)

// ---------------------------------------------------------------------------
// Scratch (no cudaMalloc allowed)
// ---------------------------------------------------------------------------
__device__ __nv_bfloat16 g_xh[(size_t)PM * PHID];
__device__ __nv_bfloat16 g_xl[(size_t)PM * PHID];
__device__ __nv_bfloat16 g_qh[(size_t)PM * PHID];
__device__ __nv_bfloat16 g_ql[(size_t)PM * PHID];
__device__ __nv_bfloat16 g_kh[(size_t)PM * PHID];
__device__ __nv_bfloat16 g_kl[(size_t)PM * PHID];
__device__ __half        g_vhf[(size_t)PM * PHID];   // V, fp16
__device__ __nv_bfloat16 g_ch[(size_t)PM * PHID];
__device__ __nv_bfloat16 g_cl[(size_t)PM * PHID];

// split-bf16 transposed weights [N,K]
__device__ __nv_bfloat16 g_wqh[(size_t)PHID * PHID];
__device__ __nv_bfloat16 g_wql[(size_t)PHID * PHID];
__device__ __nv_bfloat16 g_wkh[(size_t)PHID * PHID];
__device__ __nv_bfloat16 g_wkl[(size_t)PHID * PHID];
__device__ __nv_bfloat16 g_wvh[(size_t)PHID * PHID];
__device__ __nv_bfloat16 g_wvl[(size_t)PHID * PHID];
__device__ __nv_bfloat16 g_woh[(size_t)PHID * PHID];
__device__ __nv_bfloat16 g_wol[(size_t)PHID * PHID];

// ---------------------------------------------------------------------------
// Helpers
// ---------------------------------------------------------------------------
__device__ __forceinline__ uint32_t smem_u32(const void* p) {
    uint32_t a;
    asm("{ .reg .u64 t; cvta.to.shared.u64 t, %1; cvt.u32.u64 %0, t; }"
        : "=r"(a) : "l"(p));
    return a;
}

__device__ __forceinline__ void cp16(uint32_t s, const void* g) {
    asm volatile("cp.async.cg.shared.global [%0], [%1], 16;" :: "r"(s), "l"(g));
}
#define CP_COMMIT() asm volatile("cp.async.commit_group;" ::: "memory")
#define CP_WAIT(n)  asm volatile("cp.async.wait_group %0;" :: "n"(n) : "memory")

__device__ __forceinline__ void ldm_x4(uint32_t* r, uint32_t addr) {
    asm volatile("ldmatrix.sync.aligned.m8n8.x4.shared.b16 {%0,%1,%2,%3}, [%4];"
                 : "=r"(r[0]), "=r"(r[1]), "=r"(r[2]), "=r"(r[3]) : "r"(addr));
}
__device__ __forceinline__ void ldm_x4t(uint32_t* r, uint32_t addr) {
    asm volatile("ldmatrix.sync.aligned.m8n8.x4.trans.shared.b16 {%0,%1,%2,%3}, [%4];"
                 : "=r"(r[0]), "=r"(r[1]), "=r"(r[2]), "=r"(r[3]) : "r"(addr));
}
__device__ __forceinline__ void mma_bf16(float* c, const uint32_t* a, const uint32_t* b) {
    asm volatile(
        "mma.sync.aligned.m16n8k16.row.col.f32.bf16.bf16.f32 "
        "{%0,%1,%2,%3}, {%4,%5,%6,%7}, {%8,%9}, {%0,%1,%2,%3};"
        : "+f"(c[0]), "+f"(c[1]), "+f"(c[2]), "+f"(c[3])
        : "r"(a[0]), "r"(a[1]), "r"(a[2]), "r"(a[3]), "r"(b[0]), "r"(b[1]));
}
__device__ __forceinline__ void mma_f16(float* c, const uint32_t* a, const uint32_t* b) {
    asm volatile(
        "mma.sync.aligned.m16n8k16.row.col.f32.f16.f16.f32 "
        "{%0,%1,%2,%3}, {%4,%5,%6,%7}, {%8,%9}, {%0,%1,%2,%3};"
        : "+f"(c[0]), "+f"(c[1]), "+f"(c[2]), "+f"(c[3])
        : "r"(a[0]), "r"(a[1]), "r"(a[2]), "r"(a[3]), "r"(b[0]), "r"(b[1]));
}

__device__ __forceinline__ float ex2f(float x) {
    float r;
    asm("ex2.approx.f32 %0, %1;" : "=f"(r) : "f"(x));
    return r;
}

// pack two fp32 exponent args into f16x2 and take 2^x on both at once
__device__ __forceinline__ uint32_t h2ex2(float y0, float y1) {
    uint32_t h, p;
    asm("cvt.rn.f16x2.f32 %0, %1, %2;" : "=r"(h) : "f"(y1), "f"(y0));
    asm("ex2.approx.f16x2 %0, %1;" : "=r"(p) : "r"(h));
    return p;
}

// Fast RNE split of two floats into (hi bf16x2, lo bf16x2).
__device__ __forceinline__ void packsplit(float a, float b, uint32_t& hp, uint32_t& lp) {
    asm("cvt.rn.bf16x2.f32 %0, %1, %2;" : "=r"(hp) : "f"(b), "f"(a));
    float ah = __uint_as_float(hp << 16);
    float bh = __uint_as_float(hp & 0xFFFF0000u);
    float la = a - ah;
    float lb = b - bh;
    asm("cvt.rn.bf16x2.f32 %0, %1, %2;" : "=r"(lp) : "f"(lb), "f"(la));
}

// ---------------------------------------------------------------------------
// Conversion kernels
// ---------------------------------------------------------------------------
__global__ void split_bf16_kernel(const float* __restrict__ in,
                                  __nv_bfloat16* __restrict__ hi,
                                  __nv_bfloat16* __restrict__ lo, int n4)
{
    int i = blockIdx.x * blockDim.x + threadIdx.x;
    if (i >= n4) return;
    float4 v = ((const float4*)in)[i];
    uint32_t h0, l0, h1, l1;
    packsplit(v.x, v.y, h0, l0);
    packsplit(v.z, v.w, h1, l1);
    ((uint32_t*)hi)[2*i]   = h0;
    ((uint32_t*)hi)[2*i+1] = h1;
    ((uint32_t*)lo)[2*i]   = l0;
    ((uint32_t*)lo)[2*i+1] = l1;
}

__global__ void transpose_split_kernel(const float* __restrict__ W,
                                       __nv_bfloat16* __restrict__ Th,
                                       __nv_bfloat16* __restrict__ Tl)
{
    __shared__ float t[32][33];
    int n0 = blockIdx.x * 32, k0 = blockIdx.y * 32;
    int tx = threadIdx.x, ty0 = threadIdx.y;   // 32 x 8
#pragma unroll
    for (int j = 0; j < 32; j += 8)
        t[ty0 + j][tx] = W[(size_t)(k0 + ty0 + j) * PHID + n0 + tx];
    __syncthreads();
#pragma unroll
    for (int j = 0; j < 32; j += 8) {
        int n = ty0 + j;
        float v = t[tx][n];
        __nv_bfloat16 h = __float2bfloat16(v);
        __nv_bfloat16 l = __float2bfloat16(v - __bfloat162float(h));
        size_t o = (size_t)(n0 + n) * PHID + k0 + tx;
        Th[o] = h;
        Tl[o] = l;
    }
}

// ---------------------------------------------------------------------------
// Shared GEMM tile config
// ---------------------------------------------------------------------------
#define LDT   40
#define TILE_B (128 * LDT * 2)   // 10240
#define OFF_AH 0
#define OFF_AL (TILE_B)
#define OFF_BH (2 * TILE_B)
#define OFF_BL (3 * TILE_B)
#define STAGE_B (4 * TILE_B)     // 40960
#define GSMEM  (2 * STAGE_B)     // 81920

// ---------------------------------------------------------------------------
// Merged QKV projection GEMM: one launch, sel = blockIdx.x>>4 picks Q/K/V.
// Q,K -> split bf16; V -> single fp16.
// ---------------------------------------------------------------------------
__global__ __launch_bounds__(256, 2) void gemm_qkv(
    const __nv_bfloat16* __restrict__ Ah, const __nv_bfloat16* __restrict__ Al,
    const __nv_bfloat16* __restrict__ Wqh, const __nv_bfloat16* __restrict__ Wql,
    const __nv_bfloat16* __restrict__ Wkh, const __nv_bfloat16* __restrict__ Wkl,
    const __nv_bfloat16* __restrict__ Wvh, const __nv_bfloat16* __restrict__ Wvl,
    const float* __restrict__ bq, const float* __restrict__ bk,
    const float* __restrict__ bv,
    __nv_bfloat16* __restrict__ Qh, __nv_bfloat16* __restrict__ Ql,
    __nv_bfloat16* __restrict__ Kh, __nv_bfloat16* __restrict__ Kl,
    __half* __restrict__ Vh)
{
    extern __shared__ char smem[];
    const uint32_t sb = smem_u32(smem);
    const int tid  = threadIdx.x;
    const int lane = tid & 31;
    const int warp = tid >> 5;
    const int wm = warp >> 2;
    const int wn = warp & 3;
    const int sel = blockIdx.x >> 4;            // 0=Q 1=K 2=V
    const int n0  = (blockIdx.x & 15) * 128;
    const int m0  = blockIdx.y * 128;

    const __nv_bfloat16* Bh = (sel == 0) ? Wqh : (sel == 1) ? Wkh : Wvh;
    const __nv_bfloat16* Bl = (sel == 0) ? Wql : (sel == 1) ? Wkl : Wvl;
    const float* bias = (sel == 0) ? bq : (sel == 1) ? bk : bv;
    const float scale = (sel == 0) ? QSCALE : 1.0f;

    const __nv_bfloat16* pAh = Ah + (size_t)m0 * PHID;
    const __nv_bfloat16* pAl = Al + (size_t)m0 * PHID;
    const __nv_bfloat16* pBh = Bh + (size_t)n0 * PHID;
    const __nv_bfloat16* pBl = Bl + (size_t)n0 * PHID;

    const int r0 = tid >> 2;
    const int c0 = (tid & 3) * 8;
    const uint32_t so0 = (uint32_t)(r0 * 80 + (tid & 3) * 16);
    const uint32_t so1 = (uint32_t)((r0 + 64) * 80 + (tid & 3) * 16);

    const uint32_t a_off = (uint32_t)((wm * 64 + (lane & 15)) * 80 + ((lane >> 4) << 4));
    const uint32_t b4_off = (uint32_t)((wn * 32 + ((lane >> 4) << 3) + (lane & 7)) * 80
                                       + ((lane & 8) ? 16 : 0));

    float acc[4][4][4];
#pragma unroll
    for (int mi = 0; mi < 4; mi++)
#pragma unroll
        for (int ni = 0; ni < 4; ni++)
#pragma unroll
            for (int j = 0; j < 4; j++) acc[mi][ni][j] = 0.0f;

    auto load_stage = [&](int stage, int kc) {
        const uint32_t st = sb + stage * STAGE_B;
        const size_t g0 = (size_t)r0 * PHID + kc * 32 + c0;
        const size_t g1 = (size_t)(r0 + 64) * PHID + kc * 32 + c0;
        cp16(st + OFF_AH + so0, pAh + g0);
        cp16(st + OFF_AH + so1, pAh + g1);
        cp16(st + OFF_AL + so0, pAl + g0);
        cp16(st + OFF_AL + so1, pAl + g1);
        cp16(st + OFF_BH + so0, pBh + g0);
        cp16(st + OFF_BH + so1, pBh + g1);
        cp16(st + OFF_BL + so0, pBl + g0);
        cp16(st + OFF_BL + so1, pBl + g1);
    };

    auto compute_stage = [&](int stage) {
        const uint32_t st = sb + stage * STAGE_B;
#pragma unroll
        for (int ks = 0; ks < 2; ks++) {
            const uint32_t k32 = ks * 32;
            uint32_t bhf[4][2], blf[4][2], a[4][4];
            ldm_x4(&bhf[0][0], st + OFF_BH + b4_off + k32);
            ldm_x4(&bhf[2][0], st + OFF_BH + b4_off + 1280 + k32);
            ldm_x4(&blf[0][0], st + OFF_BL + b4_off + k32);
            ldm_x4(&blf[2][0], st + OFF_BL + b4_off + 1280 + k32);
#pragma unroll
            for (int mi = 0; mi < 4; mi++)
                ldm_x4(a[mi], st + OFF_AH + a_off + mi * 1280 + k32);
#pragma unroll
            for (int mi = 0; mi < 4; mi++)
#pragma unroll
                for (int ni = 0; ni < 4; ni++)
                    mma_bf16(acc[mi][ni], a[mi], bhf[ni]);
#pragma unroll
            for (int mi = 0; mi < 4; mi++)
#pragma unroll
                for (int ni = 0; ni < 4; ni++)
                    mma_bf16(acc[mi][ni], a[mi], blf[ni]);
#pragma unroll
            for (int mi = 0; mi < 4; mi++)
                ldm_x4(a[mi], st + OFF_AL + a_off + mi * 1280 + k32);
#pragma unroll
            for (int mi = 0; mi < 4; mi++)
#pragma unroll
                for (int ni = 0; ni < 4; ni++)
                    mma_bf16(acc[mi][ni], a[mi], bhf[ni]);
        }
    };

    load_stage(0, 0);
    CP_COMMIT();
    const int NKC = PHID / 32;
    for (int kc = 0; kc < NKC; kc++) {
        if (kc + 1 < NKC) {
            load_stage((kc + 1) & 1, kc + 1);
            CP_COMMIT();
            CP_WAIT(1);
        } else {
            CP_WAIT(0);
        }
        __syncthreads();
        compute_stage(kc & 1);
        __syncthreads();
    }

#pragma unroll
    for (int mi = 0; mi < 4; mi++) {
        const int row = m0 + wm * 64 + mi * 16 + (lane >> 2);
#pragma unroll
        for (int ni = 0; ni < 4; ni++) {
            const int col = n0 + wn * 32 + ni * 8 + (lane & 3) * 2;
            const float b0 = bias[col], b1 = bias[col + 1];
            float v00 = (acc[mi][ni][0] + b0) * scale;
            float v01 = (acc[mi][ni][1] + b1) * scale;
            float v10 = (acc[mi][ni][2] + b0) * scale;
            float v11 = (acc[mi][ni][3] + b1) * scale;
            uint32_t hp, lp;
            if (sel == 2) {
                __half2 p0 = __floats2half2_rn(v00, v01);
                __half2 p1 = __floats2half2_rn(v10, v11);
                *(uint32_t*)(Vh + (size_t)row * PHID + col) =
                    *reinterpret_cast<uint32_t*>(&p0);
                *(uint32_t*)(Vh + (size_t)(row + 8) * PHID + col) =
                    *reinterpret_cast<uint32_t*>(&p1);
            } else {
                __nv_bfloat16* Oh = (sel == 0) ? Qh : Kh;
                __nv_bfloat16* Ol = (sel == 0) ? Ql : Kl;
                packsplit(v00, v01, hp, lp);
                *(uint32_t*)(Oh + (size_t)row * PHID + col) = hp;
                *(uint32_t*)(Ol + (size_t)row * PHID + col) = lp;
                packsplit(v10, v11, hp, lp);
                *(uint32_t*)(Oh + (size_t)(row + 8) * PHID + col) = hp;
                *(uint32_t*)(Ol + (size_t)(row + 8) * PHID + col) = lp;
            }
        }
    }
}

// ---------------------------------------------------------------------------
// Output projection GEMM (split-bf16 in, fp32 out).
// ---------------------------------------------------------------------------
__global__ __launch_bounds__(256, 2) void gemm_split_mma(
    const __nv_bfloat16* __restrict__ Ah, const __nv_bfloat16* __restrict__ Al,
    const __nv_bfloat16* __restrict__ Bh, const __nv_bfloat16* __restrict__ Bl,
    const float* __restrict__ bias, float* __restrict__ C)
{
    extern __shared__ char smem[];
    const uint32_t sb = smem_u32(smem);
    const int tid  = threadIdx.x;
    const int lane = tid & 31;
    const int warp = tid >> 5;
    const int wm = warp >> 2;
    const int wn = warp & 3;
    const int m0 = blockIdx.y * 128;
    const int n0 = blockIdx.x * 128;

    const __nv_bfloat16* pAh = Ah + (size_t)m0 * PHID;
    const __nv_bfloat16* pAl = Al + (size_t)m0 * PHID;
    const __nv_bfloat16* pBh = Bh + (size_t)n0 * PHID;
    const __nv_bfloat16* pBl = Bl + (size_t)n0 * PHID;

    const int r0 = tid >> 2;
    const int c0 = (tid & 3) * 8;
    const uint32_t so0 = (uint32_t)(r0 * 80 + (tid & 3) * 16);
    const uint32_t so1 = (uint32_t)((r0 + 64) * 80 + (tid & 3) * 16);

    const uint32_t a_off = (uint32_t)((wm * 64 + (lane & 15)) * 80 + ((lane >> 4) << 4));
    const uint32_t b4_off = (uint32_t)((wn * 32 + ((lane >> 4) << 3) + (lane & 7)) * 80
                                       + ((lane & 8) ? 16 : 0));

    float acc[4][4][4];
#pragma unroll
    for (int mi = 0; mi < 4; mi++)
#pragma unroll
        for (int ni = 0; ni < 4; ni++)
#pragma unroll
            for (int j = 0; j < 4; j++) acc[mi][ni][j] = 0.0f;

    auto load_stage = [&](int stage, int kc) {
        const uint32_t st = sb + stage * STAGE_B;
        const size_t g0 = (size_t)r0 * PHID + kc * 32 + c0;
        const size_t g1 = (size_t)(r0 + 64) * PHID + kc * 32 + c0;
        cp16(st + OFF_AH + so0, pAh + g0);
        cp16(st + OFF_AH + so1, pAh + g1);
        cp16(st + OFF_AL + so0, pAl + g0);
        cp16(st + OFF_AL + so1, pAl + g1);
        cp16(st + OFF_BH + so0, pBh + g0);
        cp16(st + OFF_BH + so1, pBh + g1);
        cp16(st + OFF_BL + so0, pBl + g0);
        cp16(st + OFF_BL + so1, pBl + g1);
    };

    auto compute_stage = [&](int stage) {
        const uint32_t st = sb + stage * STAGE_B;
#pragma unroll
        for (int ks = 0; ks < 2; ks++) {
            const uint32_t k32 = ks * 32;
            uint32_t bhf[4][2], blf[4][2], a[4][4];
            ldm_x4(&bhf[0][0], st + OFF_BH + b4_off + k32);
            ldm_x4(&bhf[2][0], st + OFF_BH + b4_off + 1280 + k32);
            ldm_x4(&blf[0][0], st + OFF_BL + b4_off + k32);
            ldm_x4(&blf[2][0], st + OFF_BL + b4_off + 1280 + k32);
#pragma unroll
            for (int mi = 0; mi < 4; mi++)
                ldm_x4(a[mi], st + OFF_AH + a_off + mi * 1280 + k32);
#pragma unroll
            for (int mi = 0; mi < 4; mi++)
#pragma unroll
                for (int ni = 0; ni < 4; ni++)
                    mma_bf16(acc[mi][ni], a[mi], bhf[ni]);
#pragma unroll
            for (int mi = 0; mi < 4; mi++)
#pragma unroll
                for (int ni = 0; ni < 4; ni++)
                    mma_bf16(acc[mi][ni], a[mi], blf[ni]);
#pragma unroll
            for (int mi = 0; mi < 4; mi++)
                ldm_x4(a[mi], st + OFF_AL + a_off + mi * 1280 + k32);
#pragma unroll
            for (int mi = 0; mi < 4; mi++)
#pragma unroll
                for (int ni = 0; ni < 4; ni++)
                    mma_bf16(acc[mi][ni], a[mi], bhf[ni]);
        }
    };

    load_stage(0, 0);
    CP_COMMIT();
    const int NKC = PHID / 32;
    for (int kc = 0; kc < NKC; kc++) {
        if (kc + 1 < NKC) {
            load_stage((kc + 1) & 1, kc + 1);
            CP_COMMIT();
            CP_WAIT(1);
        } else {
            CP_WAIT(0);
        }
        __syncthreads();
        compute_stage(kc & 1);
        __syncthreads();
    }

#pragma unroll
    for (int mi = 0; mi < 4; mi++) {
        const int row = m0 + wm * 64 + mi * 16 + (lane >> 2);
#pragma unroll
        for (int ni = 0; ni < 4; ni++) {
            const int col = n0 + wn * 32 + ni * 8 + (lane & 3) * 2;
            const float b0 = bias[col], b1 = bias[col + 1];
            *(float2*)(C + (size_t)row * PHID + col) =
                make_float2(acc[mi][ni][0] + b0, acc[mi][ni][1] + b1);
            *(float2*)(C + (size_t)(row + 8) * PHID + col) =
                make_float2(acc[mi][ni][2] + b0, acc[mi][ni][3] + b1);
        }
    }
}

// ---------------------------------------------------------------------------
// Tensor-core flash attention: QK split-bf16 (3 combos), PV fp16 (1 combo),
// P via f16x2 MUFU exp, row sums via ones-MMA.
// smem: Q(h,l) 2x34816 + 2 stages x 3 tiles x 17408 = 174080 B.
// ---------------------------------------------------------------------------
#define AT_LDB  272
#define AT_QH   0
#define AT_QL   (128 * AT_LDB)            // 34816
#define AT_ST0  (2 * 128 * AT_LDB)        // 69632
#define AT_TILE (64 * AT_LDB)             // 17408
#define AT_STAGE (3 * AT_TILE)            // 52224
#define AT_SMEM (AT_ST0 + 2 * AT_STAGE)   // 174080

__global__ __launch_bounds__(256, 1) void attn_mma(
    const __nv_bfloat16* __restrict__ Qh, const __nv_bfloat16* __restrict__ Ql,
    const __nv_bfloat16* __restrict__ Kh, const __nv_bfloat16* __restrict__ Kl,
    const __half* __restrict__ Vh,
    const float* __restrict__ Bias,
    __nv_bfloat16* __restrict__ Ch, __nv_bfloat16* __restrict__ Cl)
{
    extern __shared__ char smem[];
    const uint32_t sb = smem_u32(smem);
    const int tid = threadIdx.x;
    const int lane = tid & 31;
    const int warp = tid >> 5;
    const int bh = blockIdx.y;
    const int b  = bh >> 4;
    const int h  = bh & 15;
    const int q0 = blockIdx.x * 128;
    const float L2E = 1.44269504f;

    const size_t base = (size_t)b * PS * PHID + (size_t)h * PD;
    const __nv_bfloat16* pQh = Qh + base + (size_t)q0 * PHID;
    const __nv_bfloat16* pQl = Ql + base + (size_t)q0 * PHID;
    const __nv_bfloat16* pKh = Kh + base;
    const __nv_bfloat16* pKl = Kl + base;
    const __half* pVh = Vh + base;

    // Q loader
    {
        const int r = tid >> 1;
        const int ce = (tid & 1) * 64;
        const uint32_t so = (uint32_t)(r * AT_LDB + (tid & 1) * 128);
#pragma unroll
        for (int i = 0; i < 8; i++) {
            cp16(sb + AT_QH + so + i * 16, pQh + (size_t)r * PHID + ce + i * 8);
            cp16(sb + AT_QL + so + i * 16, pQl + (size_t)r * PHID + ce + i * 8);
        }
    }

    // K/V stage loader (3 tiles: Kh, Kl, Vh)
    const int kvr  = tid >> 2;
    const int kvce = (tid & 3) * 32;
    const uint32_t kvso = (uint32_t)(kvr * AT_LDB + (tid & 3) * 64);
    auto load_stage = [&](int stage, int t) {
        const uint32_t st = sb + AT_ST0 + stage * AT_STAGE;
        const size_t g = (size_t)(t * 64 + kvr) * PHID + kvce;
#pragma unroll
        for (int i = 0; i < 4; i++) {
            cp16(st + kvso + i * 16,               pKh + g + i * 8);
            cp16(st + AT_TILE + kvso + i * 16,     pKl + g + i * 8);
            cp16(st + 2 * AT_TILE + kvso + i * 16, pVh + g + i * 8);
        }
    };

    load_stage(0, 0);
    CP_COMMIT();
    load_stage(1, 1);
    CP_COMMIT();

    const uint32_t q_off = (uint32_t)((warp * 16 + (lane & 15)) * AT_LDB + ((lane >> 4) << 4));
    const uint32_t k4_off = (uint32_t)((((lane >> 4) << 3) + (lane & 7)) * AT_LDB
                                       + ((lane & 8) ? 16 : 0));
    const uint32_t v4_off = (uint32_t)((((lane >> 3) & 1) * 8 + (lane & 7)) * AT_LDB
                                       + (lane >> 4) * 16);

    const float* biasR0 = Bias + ((size_t)bh * PS + q0 + warp * 16 + (lane >> 2)) * PS;
    const float* biasR1 = biasR0 + 8 * PS;
    const int bcol = (lane & 3) * 2;

    float o[16][4];
#pragma unroll
    for (int nd = 0; nd < 16; nd++)
#pragma unroll
        for (int j = 0; j < 4; j++) o[nd][j] = 0.0f;
    float lacc[4] = {0.0f, 0.0f, 0.0f, 0.0f};
    float m0 = -1e30f, m1 = -1e30f;
    const uint32_t ONESB[2] = {0x3C003C00u, 0x3C003C00u};

    // bias prefetch registers
    float2 nb0[8], nb1[8];
#pragma unroll
    for (int nf = 0; nf < 8; nf++) {
        nb0[nf] = *(const float2*)(biasR0 + nf * 8 + bcol);
        nb1[nf] = *(const float2*)(biasR1 + nf * 8 + bcol);
    }

    const int NT = PS / 64;   // 32
    for (int t = 0; t < NT; t++) {
        if (t < NT - 2) CP_WAIT(1); else CP_WAIT(0);
        __syncthreads();

        const uint32_t st = sb + AT_ST0 + (t & 1) * AT_STAGE;

        // consume prefetched bias, then prefetch next tile's bias
        float sc[8][4];
#pragma unroll
        for (int nf = 0; nf < 8; nf++) {
            sc[nf][0] = nb0[nf].x; sc[nf][1] = nb0[nf].y;
            sc[nf][2] = nb1[nf].x; sc[nf][3] = nb1[nf].y;
        }
        if (t + 1 < NT) {
            const int k1 = (t + 1) * 64;
#pragma unroll
            for (int nf = 0; nf < 8; nf++) {
                nb0[nf] = *(const float2*)(biasR0 + k1 + nf * 8 + bcol);
                nb1[nf] = *(const float2*)(biasR1 + k1 + nf * 8 + bcol);
            }
        }

        // ---- scores += Q K^T (split 3-combo), K via x4 pairs ----
#pragma unroll
        for (int ks = 0; ks < 8; ks++) {
            uint32_t qa[4], qla[4];
            ldm_x4(qa,  sb + AT_QH + q_off + ks * 32);
            ldm_x4(qla, sb + AT_QL + q_off + ks * 32);
#pragma unroll
            for (int nf2 = 0; nf2 < 4; nf2++) {
                uint32_t kbh[4], kbl[4];
                ldm_x4(kbh, st + k4_off + nf2 * 16 * AT_LDB + ks * 32);
                ldm_x4(kbl, st + AT_TILE + k4_off + nf2 * 16 * AT_LDB + ks * 32);
                mma_bf16(sc[2*nf2],   qa,  kbh);
                mma_bf16(sc[2*nf2+1], qa,  kbh + 2);
                mma_bf16(sc[2*nf2],   qa,  kbl);
                mma_bf16(sc[2*nf2+1], qa,  kbl + 2);
                mma_bf16(sc[2*nf2],   qla, kbh);
                mma_bf16(sc[2*nf2+1], qla, kbh + 2);
            }
        }

        // ---- online softmax: max ----
        float mx0 = sc[0][0], mx1 = sc[0][2];
#pragma unroll
        for (int nf = 0; nf < 8; nf++) {
            mx0 = fmaxf(mx0, fmaxf(sc[nf][0], sc[nf][1]));
            mx1 = fmaxf(mx1, fmaxf(sc[nf][2], sc[nf][3]));
        }
        mx0 = fmaxf(mx0, __shfl_xor_sync(0xffffffffu, mx0, 1));
        mx0 = fmaxf(mx0, __shfl_xor_sync(0xffffffffu, mx0, 2));
        mx1 = fmaxf(mx1, __shfl_xor_sync(0xffffffffu, mx1, 1));
        mx1 = fmaxf(mx1, __shfl_xor_sync(0xffffffffu, mx1, 2));
        const float mn0 = fmaxf(m0, mx0), mn1 = fmaxf(m1, mx1);
        const float mL0 = mn0 * L2E, mL1 = mn1 * L2E;
        const float al0 = ex2f((m0 - mn0) * L2E);
        const float al1 = ex2f((m1 - mn1) * L2E);
        m0 = mn0; m1 = mn1;

        // ---- rescale o and l accumulators (skip when max unchanged) ----
        if (al0 != 1.0f || al1 != 1.0f) {
#pragma unroll
            for (int nd = 0; nd < 16; nd++) {
                o[nd][0] *= al0; o[nd][1] *= al0;
                o[nd][2] *= al1; o[nd][3] *= al1;
            }
            lacc[0] *= al0; lacc[1] *= al0;
            lacc[2] *= al1; lacc[3] *= al1;
        }

        // ---- P fragments directly via f16x2 exp ----
        uint32_t pf[4][4];
#pragma unroll
        for (int j2 = 0; j2 < 4; j2++) {
            const int f0 = 2 * j2, f1 = f0 + 1;
            pf[j2][0] = h2ex2(fmaf(sc[f0][0], L2E, -mL0), fmaf(sc[f0][1], L2E, -mL0));
            pf[j2][1] = h2ex2(fmaf(sc[f0][2], L2E, -mL1), fmaf(sc[f0][3], L2E, -mL1));
            pf[j2][2] = h2ex2(fmaf(sc[f1][0], L2E, -mL0), fmaf(sc[f1][1], L2E, -mL0));
            pf[j2][3] = h2ex2(fmaf(sc[f1][2], L2E, -mL1), fmaf(sc[f1][3], L2E, -mL1));
        }

        // ---- O += P V; l += P 1 (ones-MMA); V via x4.trans pairs ----
#pragma unroll
        for (int j2 = 0; j2 < 4; j2++) {
            mma_f16(lacc, pf[j2], ONESB);
            const uint32_t vrow = st + 2 * AT_TILE + v4_off + j2 * 16 * AT_LDB;
#pragma unroll
            for (int nd2 = 0; nd2 < 8; nd2++) {
                uint32_t vbh[4];
                ldm_x4t(vbh, vrow + nd2 * 32);
                mma_f16(o[2*nd2],   pf[j2], vbh);
                mma_f16(o[2*nd2+1], pf[j2], vbh + 2);
            }
        }

        __syncthreads();
        if (t + 2 < NT) {
            load_stage(t & 1, t + 2);
            CP_COMMIT();
        }
    }

    // ---- epilogue: normalize, split, store ctx ----
    const float inv0 = 1.0f / lacc[0], inv1 = 1.0f / lacc[2];
    const int rg0 = q0 + warp * 16 + (lane >> 2);
    __nv_bfloat16* och = Ch + base;
    __nv_bfloat16* ocl = Cl + base;
#pragma unroll
    for (int nd = 0; nd < 16; nd++) {
        const int col = nd * 8 + (lane & 3) * 2;
        uint32_t hp, lp;
        packsplit(o[nd][0] * inv0, o[nd][1] * inv0, hp, lp);
        *(uint32_t*)(och + (size_t)rg0 * PHID + col) = hp;
        *(uint32_t*)(ocl + (size_t)rg0 * PHID + col) = lp;
        packsplit(o[nd][2] * inv1, o[nd][3] * inv1, hp, lp);
        *(uint32_t*)(och + (size_t)(rg0 + 8) * PHID + col) = hp;
        *(uint32_t*)(ocl + (size_t)(rg0 + 8) * PHID + col) = lp;
    }
}

// ---------------------------------------------------------------------------
extern "C" void kernel_launch(void* const* d_in, const int* in_sizes, int n_in,
                              void* d_out, int out_size)
{
    (void)in_sizes; (void)n_in; (void)out_size;
    const float* x    = (const float*)d_in[0];
    const float* bias = (const float*)d_in[1];
    const float* Wq   = (const float*)d_in[2];
    const float* bq   = (const float*)d_in[3];
    const float* Wk   = (const float*)d_in[4];
    const float* bk   = (const float*)d_in[5];
    const float* Wv   = (const float*)d_in[6];
    const float* bv   = (const float*)d_in[7];
    const float* Wo   = (const float*)d_in[8];
    const float* bo   = (const float*)d_in[9];
    float* out = (float*)d_out;

    __nv_bfloat16 *xh, *xl, *qh, *ql, *kh, *kl, *ch, *cl;
    __half *vhf;
    __nv_bfloat16 *wqh, *wql, *wkh, *wkl, *wvh, *wvl, *woh, *wol;
    cudaGetSymbolAddress((void**)&xh, g_xh);
    cudaGetSymbolAddress((void**)&xl, g_xl);
    cudaGetSymbolAddress((void**)&qh, g_qh);
    cudaGetSymbolAddress((void**)&ql, g_ql);
    cudaGetSymbolAddress((void**)&kh, g_kh);
    cudaGetSymbolAddress((void**)&kl, g_kl);
    cudaGetSymbolAddress((void**)&vhf, g_vhf);
    cudaGetSymbolAddress((void**)&ch, g_ch);
    cudaGetSymbolAddress((void**)&cl, g_cl);
    cudaGetSymbolAddress((void**)&wqh, g_wqh);
    cudaGetSymbolAddress((void**)&wql, g_wql);
    cudaGetSymbolAddress((void**)&wkh, g_wkh);
    cudaGetSymbolAddress((void**)&wkl, g_wkl);
    cudaGetSymbolAddress((void**)&wvh, g_wvh);
    cudaGetSymbolAddress((void**)&wvl, g_wvl);
    cudaGetSymbolAddress((void**)&woh, g_woh);
    cudaGetSymbolAddress((void**)&wol, g_wol);

    static bool attr_set = false;
    if (!attr_set) {
        cudaFuncSetAttribute(gemm_qkv,
                             cudaFuncAttributeMaxDynamicSharedMemorySize, GSMEM);
        cudaFuncSetAttribute(gemm_split_mma,
                             cudaFuncAttributeMaxDynamicSharedMemorySize, GSMEM);
        cudaFuncSetAttribute(attn_mma,
                             cudaFuncAttributeMaxDynamicSharedMemorySize, AT_SMEM);
        attr_set = true;
    }

    // 1) conversions
    {
        int n4 = PM * PHID / 4;
        split_bf16_kernel<<<(n4 + 255) / 256, 256>>>(x, xh, xl, n4);
        dim3 tg(PHID / 32, PHID / 32);
        dim3 tb(32, 8);
        transpose_split_kernel<<<tg, tb>>>(Wq, wqh, wql);
        transpose_split_kernel<<<tg, tb>>>(Wk, wkh, wkl);
        transpose_split_kernel<<<tg, tb>>>(Wv, wvh, wvl);
        transpose_split_kernel<<<tg, tb>>>(Wo, woh, wol);
    }

    // 2) merged QKV projections (Q/K -> split bf16, V -> fp16)
    dim3 qkvgrid(3 * PHID / 128, PM / 128);   // (48, 32)
    gemm_qkv<<<qkvgrid, 256, GSMEM>>>(xh, xl, wqh, wql, wkh, wkl, wvh, wvl,
                                      bq, bk, bv, qh, ql, kh, kl, vhf);

    // 3) tensor-core attention -> split bf16 ctx
    dim3 agrid(PS / 128, PB * PH);      // (16, 32)
    attn_mma<<<agrid, 256, AT_SMEM>>>(qh, ql, kh, kl, vhf, bias, ch, cl);

    // 4) output projection -> fp32 out
    dim3 ggrid(PHID / 128, PM / 128);
    gemm_split_mma<<<ggrid, 256, GSMEM>>>(ch, cl, woh, wol, bo, out);
}

// round 10
// speedup vs baseline: 4.0586x; 1.0977x over previous
#include <cuda_runtime.h>
#include <cuda_bf16.h>
#include <cuda_fp16.h>
#include <math.h>
#include <stdint.h>

// Problem constants
#define PB   2
#define PS   2048
#define PHID 2048
#define PH   16
#define PD   128
#define PM   (PB * PS)          // 4096 rows
#define QSCALE 11.313708498984760f   // sqrt(128)

// ---------------------------------------------------------------------------
// Scratch (no cudaMalloc allowed)
// ---------------------------------------------------------------------------
__device__ __nv_bfloat16 g_xh[(size_t)PM * PHID];    // x split bf16 (QK path)
__device__ __nv_bfloat16 g_xl[(size_t)PM * PHID];
__device__ __half        g_xh2[(size_t)PM * PHID];   // x split fp16 (V path)
__device__ __half        g_xl2[(size_t)PM * PHID];
__device__ __nv_bfloat16 g_qh[(size_t)PM * PHID];
__device__ __nv_bfloat16 g_ql[(size_t)PM * PHID];
__device__ __nv_bfloat16 g_kh[(size_t)PM * PHID];
__device__ __nv_bfloat16 g_kl[(size_t)PM * PHID];
__device__ __half        g_vhf[(size_t)PM * PHID];   // V, fp16
__device__ __half        g_ch2[(size_t)PM * PHID];   // ctx split fp16
__device__ __half        g_cl2[(size_t)PM * PHID];

// transposed weights [N,K]
__device__ __nv_bfloat16 g_wqh[(size_t)PHID * PHID];
__device__ __nv_bfloat16 g_wql[(size_t)PHID * PHID];
__device__ __nv_bfloat16 g_wkh[(size_t)PHID * PHID];
__device__ __nv_bfloat16 g_wkl[(size_t)PHID * PHID];
__device__ __half        g_wvt[(size_t)PHID * PHID]; // Wv^T single fp16
__device__ __half        g_wot[(size_t)PHID * PHID]; // Wo^T single fp16

// ---------------------------------------------------------------------------
// Helpers
// ---------------------------------------------------------------------------
__device__ __forceinline__ uint32_t smem_u32(const void* p) {
    uint32_t a;
    asm("{ .reg .u64 t; cvta.to.shared.u64 t, %1; cvt.u32.u64 %0, t; }"
        : "=r"(a) : "l"(p));
    return a;
}

__device__ __forceinline__ void cp16(uint32_t s, const void* g) {
    asm volatile("cp.async.cg.shared.global [%0], [%1], 16;" :: "r"(s), "l"(g));
}
#define CP_COMMIT() asm volatile("cp.async.commit_group;" ::: "memory")
#define CP_WAIT(n)  asm volatile("cp.async.wait_group %0;" :: "n"(n) : "memory")

__device__ __forceinline__ void ldm_x4(uint32_t* r, uint32_t addr) {
    asm volatile("ldmatrix.sync.aligned.m8n8.x4.shared.b16 {%0,%1,%2,%3}, [%4];"
                 : "=r"(r[0]), "=r"(r[1]), "=r"(r[2]), "=r"(r[3]) : "r"(addr));
}
__device__ __forceinline__ void ldm_x4t(uint32_t* r, uint32_t addr) {
    asm volatile("ldmatrix.sync.aligned.m8n8.x4.trans.shared.b16 {%0,%1,%2,%3}, [%4];"
                 : "=r"(r[0]), "=r"(r[1]), "=r"(r[2]), "=r"(r[3]) : "r"(addr));
}
__device__ __forceinline__ void mma_bf16(float* c, const uint32_t* a, const uint32_t* b) {
    asm volatile(
        "mma.sync.aligned.m16n8k16.row.col.f32.bf16.bf16.f32 "
        "{%0,%1,%2,%3}, {%4,%5,%6,%7}, {%8,%9}, {%0,%1,%2,%3};"
        : "+f"(c[0]), "+f"(c[1]), "+f"(c[2]), "+f"(c[3])
        : "r"(a[0]), "r"(a[1]), "r"(a[2]), "r"(a[3]), "r"(b[0]), "r"(b[1]));
}
__device__ __forceinline__ void mma_f16(float* c, const uint32_t* a, const uint32_t* b) {
    asm volatile(
        "mma.sync.aligned.m16n8k16.row.col.f32.f16.f16.f32 "
        "{%0,%1,%2,%3}, {%4,%5,%6,%7}, {%8,%9}, {%0,%1,%2,%3};"
        : "+f"(c[0]), "+f"(c[1]), "+f"(c[2]), "+f"(c[3])
        : "r"(a[0]), "r"(a[1]), "r"(a[2]), "r"(a[3]), "r"(b[0]), "r"(b[1]));
}

__device__ __forceinline__ float ex2f(float x) {
    float r;
    asm("ex2.approx.f32 %0, %1;" : "=f"(r) : "f"(x));
    return r;
}

// pack two fp32 exponent args into f16x2 and take 2^x on both at once
__device__ __forceinline__ uint32_t h2ex2(float y0, float y1) {
    uint32_t h, p;
    asm("cvt.rn.f16x2.f32 %0, %1, %2;" : "=r"(h) : "f"(y1), "f"(y0));
    asm("ex2.approx.f16x2 %0, %1;" : "=r"(p) : "r"(h));
    return p;
}

// Fast RNE split of two floats into (hi bf16x2, lo bf16x2).
__device__ __forceinline__ void packsplit(float a, float b, uint32_t& hp, uint32_t& lp) {
    asm("cvt.rn.bf16x2.f32 %0, %1, %2;" : "=r"(hp) : "f"(b), "f"(a));
    float ah = __uint_as_float(hp << 16);
    float bh = __uint_as_float(hp & 0xFFFF0000u);
    float la = a - ah;
    float lb = b - bh;
    asm("cvt.rn.bf16x2.f32 %0, %1, %2;" : "=r"(lp) : "f"(lb), "f"(la));
}

// RNE split of two floats into (hi f16x2, lo f16x2).
__device__ __forceinline__ void packsplit_f16(float a, float b, uint32_t& hp, uint32_t& lp) {
    __half2 h = __floats2half2_rn(a, b);
    float la = a - __half2float(__low2half(h));
    float lb = b - __half2float(__high2half(h));
    __half2 l = __floats2half2_rn(la, lb);
    hp = *reinterpret_cast<uint32_t*>(&h);
    lp = *reinterpret_cast<uint32_t*>(&l);
}

// ---------------------------------------------------------------------------
// Conversion kernels
// ---------------------------------------------------------------------------
__global__ void split_x_kernel(const float* __restrict__ in,
                               __nv_bfloat16* __restrict__ hb,
                               __nv_bfloat16* __restrict__ lb,
                               __half* __restrict__ hf,
                               __half* __restrict__ lf, int n4)
{
    int i = blockIdx.x * blockDim.x + threadIdx.x;
    if (i >= n4) return;
    float4 v = ((const float4*)in)[i];
    uint32_t h0, l0, h1, l1;
    packsplit(v.x, v.y, h0, l0);
    packsplit(v.z, v.w, h1, l1);
    ((uint32_t*)hb)[2*i]   = h0;
    ((uint32_t*)hb)[2*i+1] = h1;
    ((uint32_t*)lb)[2*i]   = l0;
    ((uint32_t*)lb)[2*i+1] = l1;
    packsplit_f16(v.x, v.y, h0, l0);
    packsplit_f16(v.z, v.w, h1, l1);
    ((uint32_t*)hf)[2*i]   = h0;
    ((uint32_t*)hf)[2*i+1] = h1;
    ((uint32_t*)lf)[2*i]   = l0;
    ((uint32_t*)lf)[2*i+1] = l1;
}

// One launch transposes all 4 weight matrices.  z=0,1 -> bf16 split (Wq, Wk);
// z=2,3 -> single fp16 (Wv, Wo).
__global__ void transpose_all_kernel(
    const float* __restrict__ Wq, const float* __restrict__ Wk,
    const float* __restrict__ Wv, const float* __restrict__ Wo,
    __nv_bfloat16* __restrict__ Tqh, __nv_bfloat16* __restrict__ Tql,
    __nv_bfloat16* __restrict__ Tkh, __nv_bfloat16* __restrict__ Tkl,
    __half* __restrict__ Tv, __half* __restrict__ To)
{
    __shared__ float t[32][33];
    int z = blockIdx.z;
    const float* W = (z == 0) ? Wq : (z == 1) ? Wk : (z == 2) ? Wv : Wo;
    int n0 = blockIdx.x * 32, k0 = blockIdx.y * 32;
    int tx = threadIdx.x, ty0 = threadIdx.y;   // 32 x 8
#pragma unroll
    for (int j = 0; j < 32; j += 8)
        t[ty0 + j][tx] = W[(size_t)(k0 + ty0 + j) * PHID + n0 + tx];
    __syncthreads();
#pragma unroll
    for (int j = 0; j < 32; j += 8) {
        int n = ty0 + j;
        float v = t[tx][n];
        size_t o = (size_t)(n0 + n) * PHID + k0 + tx;
        if (z < 2) {
            __nv_bfloat16 h = __float2bfloat16(v);
            __nv_bfloat16 l = __float2bfloat16(v - __bfloat162float(h));
            if (z == 0) { Tqh[o] = h; Tql[o] = l; }
            else        { Tkh[o] = h; Tkl[o] = l; }
        } else {
            __half h = __float2half_rn(v);
            if (z == 2) Tv[o] = h; else To[o] = h;
        }
    }
}

// ---------------------------------------------------------------------------
// Shared GEMM tile config
// ---------------------------------------------------------------------------
#define LDT   40
#define TILE_B (128 * LDT * 2)   // 10240
#define OFF_AH 0
#define OFF_AL (TILE_B)
#define OFF_BH (2 * TILE_B)
#define OFF_BL (3 * TILE_B)
#define STAGE_B (4 * TILE_B)     // 40960
#define GSMEM  (2 * STAGE_B)     // 81920

#define STAGE2_B (3 * TILE_B)    // 30720 (fp16 2-combo: Ah, Al, B)
#define GSMEM2 (2 * STAGE2_B)    // 61440

// ---------------------------------------------------------------------------
// Q/K projection GEMM (split-bf16, 3 combos): sel = blockIdx.x>>4 in {0,1}.
// ---------------------------------------------------------------------------
__global__ __launch_bounds__(256, 2) void gemm_qk(
    const __nv_bfloat16* __restrict__ Ah, const __nv_bfloat16* __restrict__ Al,
    const __nv_bfloat16* __restrict__ Wqh, const __nv_bfloat16* __restrict__ Wql,
    const __nv_bfloat16* __restrict__ Wkh, const __nv_bfloat16* __restrict__ Wkl,
    const float* __restrict__ bq, const float* __restrict__ bk,
    __nv_bfloat16* __restrict__ Qh, __nv_bfloat16* __restrict__ Ql,
    __nv_bfloat16* __restrict__ Kh, __nv_bfloat16* __restrict__ Kl)
{
    extern __shared__ char smem[];
    const uint32_t sb = smem_u32(smem);
    const int tid  = threadIdx.x;
    const int lane = tid & 31;
    const int warp = tid >> 5;
    const int wm = warp >> 2;
    const int wn = warp & 3;
    const int sel = blockIdx.x >> 4;            // 0=Q 1=K
    const int n0  = (blockIdx.x & 15) * 128;
    const int m0  = blockIdx.y * 128;

    const __nv_bfloat16* Bh = sel ? Wkh : Wqh;
    const __nv_bfloat16* Bl = sel ? Wkl : Wql;
    const float* bias = sel ? bk : bq;
    const float scale = sel ? 1.0f : QSCALE;

    const __nv_bfloat16* pAh = Ah + (size_t)m0 * PHID;
    const __nv_bfloat16* pAl = Al + (size_t)m0 * PHID;
    const __nv_bfloat16* pBh = Bh + (size_t)n0 * PHID;
    const __nv_bfloat16* pBl = Bl + (size_t)n0 * PHID;

    const int r0 = tid >> 2;
    const int c0 = (tid & 3) * 8;
    const uint32_t so0 = (uint32_t)(r0 * 80 + (tid & 3) * 16);
    const uint32_t so1 = (uint32_t)((r0 + 64) * 80 + (tid & 3) * 16);

    const uint32_t a_off = (uint32_t)((wm * 64 + (lane & 15)) * 80 + ((lane >> 4) << 4));
    const uint32_t b4_off = (uint32_t)((wn * 32 + ((lane >> 4) << 3) + (lane & 7)) * 80
                                       + ((lane & 8) ? 16 : 0));

    float acc[4][4][4];
#pragma unroll
    for (int mi = 0; mi < 4; mi++)
#pragma unroll
        for (int ni = 0; ni < 4; ni++)
#pragma unroll
            for (int j = 0; j < 4; j++) acc[mi][ni][j] = 0.0f;

    auto load_stage = [&](int stage, int kc) {
        const uint32_t st = sb + stage * STAGE_B;
        const size_t g0 = (size_t)r0 * PHID + kc * 32 + c0;
        const size_t g1 = (size_t)(r0 + 64) * PHID + kc * 32 + c0;
        cp16(st + OFF_AH + so0, pAh + g0);
        cp16(st + OFF_AH + so1, pAh + g1);
        cp16(st + OFF_AL + so0, pAl + g0);
        cp16(st + OFF_AL + so1, pAl + g1);
        cp16(st + OFF_BH + so0, pBh + g0);
        cp16(st + OFF_BH + so1, pBh + g1);
        cp16(st + OFF_BL + so0, pBl + g0);
        cp16(st + OFF_BL + so1, pBl + g1);
    };

    auto compute_stage = [&](int stage) {
        const uint32_t st = sb + stage * STAGE_B;
#pragma unroll
        for (int ks = 0; ks < 2; ks++) {
            const uint32_t k32 = ks * 32;
            uint32_t bhf[4][2], blf[4][2], a[4][4];
            ldm_x4(&bhf[0][0], st + OFF_BH + b4_off + k32);
            ldm_x4(&bhf[2][0], st + OFF_BH + b4_off + 1280 + k32);
            ldm_x4(&blf[0][0], st + OFF_BL + b4_off + k32);
            ldm_x4(&blf[2][0], st + OFF_BL + b4_off + 1280 + k32);
#pragma unroll
            for (int mi = 0; mi < 4; mi++)
                ldm_x4(a[mi], st + OFF_AH + a_off + mi * 1280 + k32);
#pragma unroll
            for (int mi = 0; mi < 4; mi++)
#pragma unroll
                for (int ni = 0; ni < 4; ni++)
                    mma_bf16(acc[mi][ni], a[mi], bhf[ni]);
#pragma unroll
            for (int mi = 0; mi < 4; mi++)
#pragma unroll
                for (int ni = 0; ni < 4; ni++)
                    mma_bf16(acc[mi][ni], a[mi], blf[ni]);
#pragma unroll
            for (int mi = 0; mi < 4; mi++)
                ldm_x4(a[mi], st + OFF_AL + a_off + mi * 1280 + k32);
#pragma unroll
            for (int mi = 0; mi < 4; mi++)
#pragma unroll
                for (int ni = 0; ni < 4; ni++)
                    mma_bf16(acc[mi][ni], a[mi], bhf[ni]);
        }
    };

    load_stage(0, 0);
    CP_COMMIT();
    const int NKC = PHID / 32;
    for (int kc = 0; kc < NKC; kc++) {
        if (kc + 1 < NKC) {
            load_stage((kc + 1) & 1, kc + 1);
            CP_COMMIT();
            CP_WAIT(1);
        } else {
            CP_WAIT(0);
        }
        __syncthreads();
        compute_stage(kc & 1);
        __syncthreads();
    }

    __nv_bfloat16* Oh = sel ? Kh : Qh;
    __nv_bfloat16* Ol = sel ? Kl : Ql;
#pragma unroll
    for (int mi = 0; mi < 4; mi++) {
        const int row = m0 + wm * 64 + mi * 16 + (lane >> 2);
#pragma unroll
        for (int ni = 0; ni < 4; ni++) {
            const int col = n0 + wn * 32 + ni * 8 + (lane & 3) * 2;
            const float b0 = bias[col], b1 = bias[col + 1];
            float v00 = (acc[mi][ni][0] + b0) * scale;
            float v01 = (acc[mi][ni][1] + b1) * scale;
            float v10 = (acc[mi][ni][2] + b0) * scale;
            float v11 = (acc[mi][ni][3] + b1) * scale;
            uint32_t hp, lp;
            packsplit(v00, v01, hp, lp);
            *(uint32_t*)(Oh + (size_t)row * PHID + col) = hp;
            *(uint32_t*)(Ol + (size_t)row * PHID + col) = lp;
            packsplit(v10, v11, hp, lp);
            *(uint32_t*)(Oh + (size_t)(row + 8) * PHID + col) = hp;
            *(uint32_t*)(Ol + (size_t)(row + 8) * PHID + col) = lp;
        }
    }
}

// ---------------------------------------------------------------------------
// fp16 2-combo GEMM: C = (Ah + Al) @ B^T + bias, A split fp16, B single fp16.
// Cf != null -> fp32 out; else Co fp16 out.
// ---------------------------------------------------------------------------
__global__ __launch_bounds__(256, 2) void gemm_f16_2c(
    const __half* __restrict__ Ah, const __half* __restrict__ Al,
    const __half* __restrict__ Bt,
    const float* __restrict__ bias, float* __restrict__ Cf,
    __half* __restrict__ Co)
{
    extern __shared__ char smem[];
    const uint32_t sb = smem_u32(smem);
    const int tid  = threadIdx.x;
    const int lane = tid & 31;
    const int warp = tid >> 5;
    const int wm = warp >> 2;
    const int wn = warp & 3;
    const int m0 = blockIdx.y * 128;
    const int n0 = blockIdx.x * 128;

    const __half* pAh = Ah + (size_t)m0 * PHID;
    const __half* pAl = Al + (size_t)m0 * PHID;
    const __half* pB  = Bt + (size_t)n0 * PHID;

    const int r0 = tid >> 2;
    const int c0 = (tid & 3) * 8;
    const uint32_t so0 = (uint32_t)(r0 * 80 + (tid & 3) * 16);
    const uint32_t so1 = (uint32_t)((r0 + 64) * 80 + (tid & 3) * 16);

    const uint32_t a_off = (uint32_t)((wm * 64 + (lane & 15)) * 80 + ((lane >> 4) << 4));
    const uint32_t b4_off = (uint32_t)((wn * 32 + ((lane >> 4) << 3) + (lane & 7)) * 80
                                       + ((lane & 8) ? 16 : 0));

    float acc[4][4][4];
#pragma unroll
    for (int mi = 0; mi < 4; mi++)
#pragma unroll
        for (int ni = 0; ni < 4; ni++)
#pragma unroll
            for (int j = 0; j < 4; j++) acc[mi][ni][j] = 0.0f;

    auto load_stage = [&](int stage, int kc) {
        const uint32_t st = sb + stage * STAGE2_B;
        const size_t g0 = (size_t)r0 * PHID + kc * 32 + c0;
        const size_t g1 = (size_t)(r0 + 64) * PHID + kc * 32 + c0;
        cp16(st + OFF_AH + so0, pAh + g0);
        cp16(st + OFF_AH + so1, pAh + g1);
        cp16(st + OFF_AL + so0, pAl + g0);
        cp16(st + OFF_AL + so1, pAl + g1);
        cp16(st + OFF_BH + so0, pB + g0);
        cp16(st + OFF_BH + so1, pB + g1);
    };

    auto compute_stage = [&](int stage) {
        const uint32_t st = sb + stage * STAGE2_B;
#pragma unroll
        for (int ks = 0; ks < 2; ks++) {
            const uint32_t k32 = ks * 32;
            uint32_t bf[4][2], a[4][4];
            ldm_x4(&bf[0][0], st + OFF_BH + b4_off + k32);
            ldm_x4(&bf[2][0], st + OFF_BH + b4_off + 1280 + k32);
#pragma unroll
            for (int mi = 0; mi < 4; mi++)
                ldm_x4(a[mi], st + OFF_AH + a_off + mi * 1280 + k32);
#pragma unroll
            for (int mi = 0; mi < 4; mi++)
#pragma unroll
                for (int ni = 0; ni < 4; ni++)
                    mma_f16(acc[mi][ni], a[mi], bf[ni]);
#pragma unroll
            for (int mi = 0; mi < 4; mi++)
                ldm_x4(a[mi], st + OFF_AL + a_off + mi * 1280 + k32);
#pragma unroll
            for (int mi = 0; mi < 4; mi++)
#pragma unroll
                for (int ni = 0; ni < 4; ni++)
                    mma_f16(acc[mi][ni], a[mi], bf[ni]);
        }
    };

    load_stage(0, 0);
    CP_COMMIT();
    const int NKC = PHID / 32;
    for (int kc = 0; kc < NKC; kc++) {
        if (kc + 1 < NKC) {
            load_stage((kc + 1) & 1, kc + 1);
            CP_COMMIT();
            CP_WAIT(1);
        } else {
            CP_WAIT(0);
        }
        __syncthreads();
        compute_stage(kc & 1);
        __syncthreads();
    }

#pragma unroll
    for (int mi = 0; mi < 4; mi++) {
        const int row = m0 + wm * 64 + mi * 16 + (lane >> 2);
#pragma unroll
        for (int ni = 0; ni < 4; ni++) {
            const int col = n0 + wn * 32 + ni * 8 + (lane & 3) * 2;
            const float b0 = bias[col], b1 = bias[col + 1];
            float v00 = acc[mi][ni][0] + b0;
            float v01 = acc[mi][ni][1] + b1;
            float v10 = acc[mi][ni][2] + b0;
            float v11 = acc[mi][ni][3] + b1;
            if (Cf) {
                *(float2*)(Cf + (size_t)row * PHID + col)       = make_float2(v00, v01);
                *(float2*)(Cf + (size_t)(row + 8) * PHID + col) = make_float2(v10, v11);
            } else {
                __half2 p0 = __floats2half2_rn(v00, v01);
                __half2 p1 = __floats2half2_rn(v10, v11);
                *(uint32_t*)(Co + (size_t)row * PHID + col) =
                    *reinterpret_cast<uint32_t*>(&p0);
                *(uint32_t*)(Co + (size_t)(row + 8) * PHID + col) =
                    *reinterpret_cast<uint32_t*>(&p1);
            }
        }
    }
}

// ---------------------------------------------------------------------------
// Tensor-core flash attention: QK split-bf16 (3 combos), PV fp16 (1 combo),
// P via f16x2 MUFU exp, row sums via ones-MMA.  ctx out: split fp16.
// ---------------------------------------------------------------------------
#define AT_LDB  272
#define AT_QH   0
#define AT_QL   (128 * AT_LDB)            // 34816
#define AT_ST0  (2 * 128 * AT_LDB)        // 69632
#define AT_TILE (64 * AT_LDB)             // 17408
#define AT_STAGE (3 * AT_TILE)            // 52224
#define AT_SMEM (AT_ST0 + 2 * AT_STAGE)   // 174080

__global__ __launch_bounds__(256, 1) void attn_mma(
    const __nv_bfloat16* __restrict__ Qh, const __nv_bfloat16* __restrict__ Ql,
    const __nv_bfloat16* __restrict__ Kh, const __nv_bfloat16* __restrict__ Kl,
    const __half* __restrict__ Vh,
    const float* __restrict__ Bias,
    __half* __restrict__ Ch, __half* __restrict__ Cl)
{
    extern __shared__ char smem[];
    const uint32_t sb = smem_u32(smem);
    const int tid = threadIdx.x;
    const int lane = tid & 31;
    const int warp = tid >> 5;
    const int bh = blockIdx.y;
    const int b  = bh >> 4;
    const int h  = bh & 15;
    const int q0 = blockIdx.x * 128;
    const float L2E = 1.44269504f;

    const size_t base = (size_t)b * PS * PHID + (size_t)h * PD;
    const __nv_bfloat16* pQh = Qh + base + (size_t)q0 * PHID;
    const __nv_bfloat16* pQl = Ql + base + (size_t)q0 * PHID;
    const __nv_bfloat16* pKh = Kh + base;
    const __nv_bfloat16* pKl = Kl + base;
    const __half* pVh = Vh + base;

    // Q loader
    {
        const int r = tid >> 1;
        const int ce = (tid & 1) * 64;
        const uint32_t so = (uint32_t)(r * AT_LDB + (tid & 1) * 128);
#pragma unroll
        for (int i = 0; i < 8; i++) {
            cp16(sb + AT_QH + so + i * 16, pQh + (size_t)r * PHID + ce + i * 8);
            cp16(sb + AT_QL + so + i * 16, pQl + (size_t)r * PHID + ce + i * 8);
        }
    }

    // K/V stage loader (3 tiles: Kh, Kl, Vh)
    const int kvr  = tid >> 2;
    const int kvce = (tid & 3) * 32;
    const uint32_t kvso = (uint32_t)(kvr * AT_LDB + (tid & 3) * 64);
    auto load_stage = [&](int stage, int t) {
        const uint32_t st = sb + AT_ST0 + stage * AT_STAGE;
        const size_t g = (size_t)(t * 64 + kvr) * PHID + kvce;
#pragma unroll
        for (int i = 0; i < 4; i++) {
            cp16(st + kvso + i * 16,               pKh + g + i * 8);
            cp16(st + AT_TILE + kvso + i * 16,     pKl + g + i * 8);
            cp16(st + 2 * AT_TILE + kvso + i * 16, pVh + g + i * 8);
        }
    };

    load_stage(0, 0);
    CP_COMMIT();
    load_stage(1, 1);
    CP_COMMIT();

    const uint32_t q_off = (uint32_t)((warp * 16 + (lane & 15)) * AT_LDB + ((lane >> 4) << 4));
    const uint32_t k4_off = (uint32_t)((((lane >> 4) << 3) + (lane & 7)) * AT_LDB
                                       + ((lane & 8) ? 16 : 0));
    const uint32_t v4_off = (uint32_t)((((lane >> 3) & 1) * 8 + (lane & 7)) * AT_LDB
                                       + (lane >> 4) * 16);

    const float* biasR0 = Bias + ((size_t)bh * PS + q0 + warp * 16 + (lane >> 2)) * PS;
    const float* biasR1 = biasR0 + 8 * PS;
    const int bcol = (lane & 3) * 2;

    float o[16][4];
#pragma unroll
    for (int nd = 0; nd < 16; nd++)
#pragma unroll
        for (int j = 0; j < 4; j++) o[nd][j] = 0.0f;
    float lacc[4] = {0.0f, 0.0f, 0.0f, 0.0f};
    float m0 = -1e30f, m1 = -1e30f;
    const uint32_t ONESB[2] = {0x3C003C00u, 0x3C003C00u};

    // bias prefetch registers
    float2 nb0[8], nb1[8];
#pragma unroll
    for (int nf = 0; nf < 8; nf++) {
        nb0[nf] = *(const float2*)(biasR0 + nf * 8 + bcol);
        nb1[nf] = *(const float2*)(biasR1 + nf * 8 + bcol);
    }

    const int NT = PS / 64;   // 32
    for (int t = 0; t < NT; t++) {
        if (t < NT - 2) CP_WAIT(1); else CP_WAIT(0);
        __syncthreads();

        const uint32_t st = sb + AT_ST0 + (t & 1) * AT_STAGE;

        // consume prefetched bias, then prefetch next tile's bias
        float sc[8][4];
#pragma unroll
        for (int nf = 0; nf < 8; nf++) {
            sc[nf][0] = nb0[nf].x; sc[nf][1] = nb0[nf].y;
            sc[nf][2] = nb1[nf].x; sc[nf][3] = nb1[nf].y;
        }
        if (t + 1 < NT) {
            const int k1 = (t + 1) * 64;
#pragma unroll
            for (int nf = 0; nf < 8; nf++) {
                nb0[nf] = *(const float2*)(biasR0 + k1 + nf * 8 + bcol);
                nb1[nf] = *(const float2*)(biasR1 + k1 + nf * 8 + bcol);
            }
        }

        // ---- scores += Q K^T (split 3-combo), K via x4 pairs ----
#pragma unroll
        for (int ks = 0; ks < 8; ks++) {
            uint32_t qa[4], qla[4];
            ldm_x4(qa,  sb + AT_QH + q_off + ks * 32);
            ldm_x4(qla, sb + AT_QL + q_off + ks * 32);
#pragma unroll
            for (int nf2 = 0; nf2 < 4; nf2++) {
                uint32_t kbh[4], kbl[4];
                ldm_x4(kbh, st + k4_off + nf2 * 16 * AT_LDB + ks * 32);
                ldm_x4(kbl, st + AT_TILE + k4_off + nf2 * 16 * AT_LDB + ks * 32);
                mma_bf16(sc[2*nf2],   qa,  kbh);
                mma_bf16(sc[2*nf2+1], qa,  kbh + 2);
                mma_bf16(sc[2*nf2],   qa,  kbl);
                mma_bf16(sc[2*nf2+1], qa,  kbl + 2);
                mma_bf16(sc[2*nf2],   qla, kbh);
                mma_bf16(sc[2*nf2+1], qla, kbh + 2);
            }
        }

        // ---- online softmax: max ----
        float mx0 = sc[0][0], mx1 = sc[0][2];
#pragma unroll
        for (int nf = 0; nf < 8; nf++) {
            mx0 = fmaxf(mx0, fmaxf(sc[nf][0], sc[nf][1]));
            mx1 = fmaxf(mx1, fmaxf(sc[nf][2], sc[nf][3]));
        }
        mx0 = fmaxf(mx0, __shfl_xor_sync(0xffffffffu, mx0, 1));
        mx0 = fmaxf(mx0, __shfl_xor_sync(0xffffffffu, mx0, 2));
        mx1 = fmaxf(mx1, __shfl_xor_sync(0xffffffffu, mx1, 1));
        mx1 = fmaxf(mx1, __shfl_xor_sync(0xffffffffu, mx1, 2));
        const float mn0 = fmaxf(m0, mx0), mn1 = fmaxf(m1, mx1);
        const float mL0 = mn0 * L2E, mL1 = mn1 * L2E;
        const float al0 = ex2f((m0 - mn0) * L2E);
        const float al1 = ex2f((m1 - mn1) * L2E);
        m0 = mn0; m1 = mn1;

        // ---- rescale o and l accumulators (skip when max unchanged) ----
        if (al0 != 1.0f || al1 != 1.0f) {
#pragma unroll
            for (int nd = 0; nd < 16; nd++) {
                o[nd][0] *= al0; o[nd][1] *= al0;
                o[nd][2] *= al1; o[nd][3] *= al1;
            }
            lacc[0] *= al0; lacc[1] *= al0;
            lacc[2] *= al1; lacc[3] *= al1;
        }

        // ---- P fragments directly via f16x2 exp ----
        uint32_t pf[4][4];
#pragma unroll
        for (int j2 = 0; j2 < 4; j2++) {
            const int f0 = 2 * j2, f1 = f0 + 1;
            pf[j2][0] = h2ex2(fmaf(sc[f0][0], L2E, -mL0), fmaf(sc[f0][1], L2E, -mL0));
            pf[j2][1] = h2ex2(fmaf(sc[f0][2], L2E, -mL1), fmaf(sc[f0][3], L2E, -mL1));
            pf[j2][2] = h2ex2(fmaf(sc[f1][0], L2E, -mL0), fmaf(sc[f1][1], L2E, -mL0));
            pf[j2][3] = h2ex2(fmaf(sc[f1][2], L2E, -mL1), fmaf(sc[f1][3], L2E, -mL1));
        }

        // ---- O += P V; l += P 1 (ones-MMA); V via x4.trans pairs ----
#pragma unroll
        for (int j2 = 0; j2 < 4; j2++) {
            mma_f16(lacc, pf[j2], ONESB);
            const uint32_t vrow = st + 2 * AT_TILE + v4_off + j2 * 16 * AT_LDB;
#pragma unroll
            for (int nd2 = 0; nd2 < 8; nd2++) {
                uint32_t vbh[4];
                ldm_x4t(vbh, vrow + nd2 * 32);
                mma_f16(o[2*nd2],   pf[j2], vbh);
                mma_f16(o[2*nd2+1], pf[j2], vbh + 2);
            }
        }

        __syncthreads();
        if (t + 2 < NT) {
            load_stage(t & 1, t + 2);
            CP_COMMIT();
        }
    }

    // ---- epilogue: normalize, split fp16, store ctx ----
    const float inv0 = 1.0f / lacc[0], inv1 = 1.0f / lacc[2];
    const int rg0 = q0 + warp * 16 + (lane >> 2);
    __half* och = Ch + base;
    __half* ocl = Cl + base;
#pragma unroll
    for (int nd = 0; nd < 16; nd++) {
        const int col = nd * 8 + (lane & 3) * 2;
        uint32_t hp, lp;
        packsplit_f16(o[nd][0] * inv0, o[nd][1] * inv0, hp, lp);
        *(uint32_t*)(och + (size_t)rg0 * PHID + col) = hp;
        *(uint32_t*)(ocl + (size_t)rg0 * PHID + col) = lp;
        packsplit_f16(o[nd][2] * inv1, o[nd][3] * inv1, hp, lp);
        *(uint32_t*)(och + (size_t)(rg0 + 8) * PHID + col) = hp;
        *(uint32_t*)(ocl + (size_t)(rg0 + 8) * PHID + col) = lp;
    }
}

// ---------------------------------------------------------------------------
extern "C" void kernel_launch(void* const* d_in, const int* in_sizes, int n_in,
                              void* d_out, int out_size)
{
    (void)in_sizes; (void)n_in; (void)out_size;
    const float* x    = (const float*)d_in[0];
    const float* bias = (const float*)d_in[1];
    const float* Wq   = (const float*)d_in[2];
    const float* bq   = (const float*)d_in[3];
    const float* Wk   = (const float*)d_in[4];
    const float* bk   = (const float*)d_in[5];
    const float* Wv   = (const float*)d_in[6];
    const float* bv   = (const float*)d_in[7];
    const float* Wo   = (const float*)d_in[8];
    const float* bo   = (const float*)d_in[9];
    float* out = (float*)d_out;

    __nv_bfloat16 *xh, *xl, *qh, *ql, *kh, *kl;
    __half *xh2, *xl2, *vhf, *ch2, *cl2, *wvt, *wot;
    __nv_bfloat16 *wqh, *wql, *wkh, *wkl;
    cudaGetSymbolAddress((void**)&xh, g_xh);
    cudaGetSymbolAddress((void**)&xl, g_xl);
    cudaGetSymbolAddress((void**)&xh2, g_xh2);
    cudaGetSymbolAddress((void**)&xl2, g_xl2);
    cudaGetSymbolAddress((void**)&qh, g_qh);
    cudaGetSymbolAddress((void**)&ql, g_ql);
    cudaGetSymbolAddress((void**)&kh, g_kh);
    cudaGetSymbolAddress((void**)&kl, g_kl);
    cudaGetSymbolAddress((void**)&vhf, g_vhf);
    cudaGetSymbolAddress((void**)&ch2, g_ch2);
    cudaGetSymbolAddress((void**)&cl2, g_cl2);
    cudaGetSymbolAddress((void**)&wqh, g_wqh);
    cudaGetSymbolAddress((void**)&wql, g_wql);
    cudaGetSymbolAddress((void**)&wkh, g_wkh);
    cudaGetSymbolAddress((void**)&wkl, g_wkl);
    cudaGetSymbolAddress((void**)&wvt, g_wvt);
    cudaGetSymbolAddress((void**)&wot, g_wot);

    static bool attr_set = false;
    if (!attr_set) {
        cudaFuncSetAttribute(gemm_qk,
                             cudaFuncAttributeMaxDynamicSharedMemorySize, GSMEM);
        cudaFuncSetAttribute(gemm_f16_2c,
                             cudaFuncAttributeMaxDynamicSharedMemorySize, GSMEM2);
        cudaFuncSetAttribute(attn_mma,
                             cudaFuncAttributeMaxDynamicSharedMemorySize, AT_SMEM);
        attr_set = true;
    }

    // 1) conversions
    {
        int n4 = PM * PHID / 4;
        split_x_kernel<<<(n4 + 255) / 256, 256>>>(x, xh, xl, xh2, xl2, n4);
        dim3 tg(PHID / 32, PHID / 32, 4);
        dim3 tb(32, 8);
        transpose_all_kernel<<<tg, tb>>>(Wq, Wk, Wv, Wo,
                                         wqh, wql, wkh, wkl, wvt, wot);
    }

    // 2) projections
    dim3 qkgrid(2 * PHID / 128, PM / 128);    // (32, 32)
    gemm_qk<<<qkgrid, 256, GSMEM>>>(xh, xl, wqh, wql, wkh, wkl,
                                    bq, bk, qh, ql, kh, kl);
    dim3 vgrid(PHID / 128, PM / 128);         // (16, 32)
    gemm_f16_2c<<<vgrid, 256, GSMEM2>>>(xh2, xl2, wvt, bv, nullptr, vhf);

    // 3) tensor-core attention -> split fp16 ctx
    dim3 agrid(PS / 128, PB * PH);            // (16, 32)
    attn_mma<<<agrid, 256, AT_SMEM>>>(qh, ql, kh, kl, vhf, bias, ch2, cl2);

    // 4) output projection -> fp32 out
    gemm_f16_2c<<<vgrid, 256, GSMEM2>>>(ch2, cl2, wot, bo, out, nullptr);
}

// round 11
// speedup vs baseline: 4.1715x; 1.0278x over previous
#include <cuda_runtime.h>
#include <cuda_bf16.h>
#include <cuda_fp16.h>
#include <math.h>
#include <stdint.h>

// Problem constants
#define PB   2
#define PS   2048
#define PHID 2048
#define PH   16
#define PD   128
#define PM   (PB * PS)          // 4096 rows
#define QSCALE 11.313708498984760f   // sqrt(128)

// ---------------------------------------------------------------------------
// Scratch (no cudaMalloc allowed)
// ---------------------------------------------------------------------------
__device__ __nv_bfloat16 g_xh[(size_t)PM * PHID];    // x split bf16 (QK path)
__device__ __nv_bfloat16 g_xl[(size_t)PM * PHID];
__device__ __half        g_xh2[(size_t)PM * PHID];   // x split fp16 (V path)
__device__ __half        g_xl2[(size_t)PM * PHID];
__device__ __nv_bfloat16 g_qh[(size_t)PM * PHID];
__device__ __nv_bfloat16 g_ql[(size_t)PM * PHID];
__device__ __nv_bfloat16 g_kh[(size_t)PM * PHID];
__device__ __nv_bfloat16 g_kl[(size_t)PM * PHID];
__device__ __half        g_vhf[(size_t)PM * PHID];   // V, fp16
__device__ __half        g_ch2[(size_t)PM * PHID];   // ctx split fp16
__device__ __half        g_cl2[(size_t)PM * PHID];

// transposed weights [N,K]
__device__ __nv_bfloat16 g_wqh[(size_t)PHID * PHID];
__device__ __nv_bfloat16 g_wql[(size_t)PHID * PHID];
__device__ __nv_bfloat16 g_wkh[(size_t)PHID * PHID];
__device__ __nv_bfloat16 g_wkl[(size_t)PHID * PHID];
__device__ __half        g_wvt[(size_t)PHID * PHID]; // Wv^T single fp16
__device__ __half        g_wot[(size_t)PHID * PHID]; // Wo^T single fp16

// ---------------------------------------------------------------------------
// Helpers
// ---------------------------------------------------------------------------
__device__ __forceinline__ uint32_t smem_u32(const void* p) {
    uint32_t a;
    asm("{ .reg .u64 t; cvta.to.shared.u64 t, %1; cvt.u32.u64 %0, t; }"
        : "=r"(a) : "l"(p));
    return a;
}

__device__ __forceinline__ void cp16(uint32_t s, const void* g) {
    asm volatile("cp.async.cg.shared.global [%0], [%1], 16;" :: "r"(s), "l"(g));
}
#define CP_COMMIT() asm volatile("cp.async.commit_group;" ::: "memory")
#define CP_WAIT(n)  asm volatile("cp.async.wait_group %0;" :: "n"(n) : "memory")

__device__ __forceinline__ void ldm_x4(uint32_t* r, uint32_t addr) {
    asm volatile("ldmatrix.sync.aligned.m8n8.x4.shared.b16 {%0,%1,%2,%3}, [%4];"
                 : "=r"(r[0]), "=r"(r[1]), "=r"(r[2]), "=r"(r[3]) : "r"(addr));
}
__device__ __forceinline__ void ldm_x4t(uint32_t* r, uint32_t addr) {
    asm volatile("ldmatrix.sync.aligned.m8n8.x4.trans.shared.b16 {%0,%1,%2,%3}, [%4];"
                 : "=r"(r[0]), "=r"(r[1]), "=r"(r[2]), "=r"(r[3]) : "r"(addr));
}
__device__ __forceinline__ void mma_bf16(float* c, const uint32_t* a, const uint32_t* b) {
    asm volatile(
        "mma.sync.aligned.m16n8k16.row.col.f32.bf16.bf16.f32 "
        "{%0,%1,%2,%3}, {%4,%5,%6,%7}, {%8,%9}, {%0,%1,%2,%3};"
        : "+f"(c[0]), "+f"(c[1]), "+f"(c[2]), "+f"(c[3])
        : "r"(a[0]), "r"(a[1]), "r"(a[2]), "r"(a[3]), "r"(b[0]), "r"(b[1]));
}
__device__ __forceinline__ void mma_f16(float* c, const uint32_t* a, const uint32_t* b) {
    asm volatile(
        "mma.sync.aligned.m16n8k16.row.col.f32.f16.f16.f32 "
        "{%0,%1,%2,%3}, {%4,%5,%6,%7}, {%8,%9}, {%0,%1,%2,%3};"
        : "+f"(c[0]), "+f"(c[1]), "+f"(c[2]), "+f"(c[3])
        : "r"(a[0]), "r"(a[1]), "r"(a[2]), "r"(a[3]), "r"(b[0]), "r"(b[1]));
}

__device__ __forceinline__ float ex2f(float x) {
    float r;
    asm("ex2.approx.f32 %0, %1;" : "=f"(r) : "f"(x));
    return r;
}

// pack two fp32 exponent args into f16x2 and take 2^x on both at once
__device__ __forceinline__ uint32_t h2ex2(float y0, float y1) {
    uint32_t h, p;
    asm("cvt.rn.f16x2.f32 %0, %1, %2;" : "=r"(h) : "f"(y1), "f"(y0));
    asm("ex2.approx.f16x2 %0, %1;" : "=r"(p) : "r"(h));
    return p;
}

// Fast RNE split of two floats into (hi bf16x2, lo bf16x2).
__device__ __forceinline__ void packsplit(float a, float b, uint32_t& hp, uint32_t& lp) {
    asm("cvt.rn.bf16x2.f32 %0, %1, %2;" : "=r"(hp) : "f"(b), "f"(a));
    float ah = __uint_as_float(hp << 16);
    float bh = __uint_as_float(hp & 0xFFFF0000u);
    float la = a - ah;
    float lb = b - bh;
    asm("cvt.rn.bf16x2.f32 %0, %1, %2;" : "=r"(lp) : "f"(lb), "f"(la));
}

// RNE split of two floats into (hi f16x2, lo f16x2).
__device__ __forceinline__ void packsplit_f16(float a, float b, uint32_t& hp, uint32_t& lp) {
    __half2 h = __floats2half2_rn(a, b);
    float la = a - __half2float(__low2half(h));
    float lb = b - __half2float(__high2half(h));
    __half2 l = __floats2half2_rn(la, lb);
    hp = *reinterpret_cast<uint32_t*>(&h);
    lp = *reinterpret_cast<uint32_t*>(&l);
}

// ---------------------------------------------------------------------------
// Conversion kernels
// ---------------------------------------------------------------------------
__global__ void split_x_kernel(const float* __restrict__ in,
                               __nv_bfloat16* __restrict__ hb,
                               __nv_bfloat16* __restrict__ lb,
                               __half* __restrict__ hf,
                               __half* __restrict__ lf, int n4)
{
    int i = blockIdx.x * blockDim.x + threadIdx.x;
    if (i >= n4) return;
    float4 v = ((const float4*)in)[i];
    uint32_t h0, l0, h1, l1;
    packsplit(v.x, v.y, h0, l0);
    packsplit(v.z, v.w, h1, l1);
    ((uint32_t*)hb)[2*i]   = h0;
    ((uint32_t*)hb)[2*i+1] = h1;
    ((uint32_t*)lb)[2*i]   = l0;
    ((uint32_t*)lb)[2*i+1] = l1;
    packsplit_f16(v.x, v.y, h0, l0);
    packsplit_f16(v.z, v.w, h1, l1);
    ((uint32_t*)hf)[2*i]   = h0;
    ((uint32_t*)hf)[2*i+1] = h1;
    ((uint32_t*)lf)[2*i]   = l0;
    ((uint32_t*)lf)[2*i+1] = l1;
}

// One launch transposes all 4 weight matrices.  z=0,1 -> bf16 split (Wq, Wk);
// z=2,3 -> single fp16 (Wv, Wo).
__global__ void transpose_all_kernel(
    const float* __restrict__ Wq, const float* __restrict__ Wk,
    const float* __restrict__ Wv, const float* __restrict__ Wo,
    __nv_bfloat16* __restrict__ Tqh, __nv_bfloat16* __restrict__ Tql,
    __nv_bfloat16* __restrict__ Tkh, __nv_bfloat16* __restrict__ Tkl,
    __half* __restrict__ Tv, __half* __restrict__ To)
{
    __shared__ float t[32][33];
    int z = blockIdx.z;
    const float* W = (z == 0) ? Wq : (z == 1) ? Wk : (z == 2) ? Wv : Wo;
    int n0 = blockIdx.x * 32, k0 = blockIdx.y * 32;
    int tx = threadIdx.x, ty0 = threadIdx.y;   // 32 x 8
#pragma unroll
    for (int j = 0; j < 32; j += 8)
        t[ty0 + j][tx] = W[(size_t)(k0 + ty0 + j) * PHID + n0 + tx];
    __syncthreads();
#pragma unroll
    for (int j = 0; j < 32; j += 8) {
        int n = ty0 + j;
        float v = t[tx][n];
        size_t o = (size_t)(n0 + n) * PHID + k0 + tx;
        if (z < 2) {
            __nv_bfloat16 h = __float2bfloat16(v);
            __nv_bfloat16 l = __float2bfloat16(v - __bfloat162float(h));
            if (z == 0) { Tqh[o] = h; Tql[o] = l; }
            else        { Tkh[o] = h; Tkl[o] = l; }
        } else {
            __half h = __float2half_rn(v);
            if (z == 2) Tv[o] = h; else To[o] = h;
        }
    }
}

// ---------------------------------------------------------------------------
// Shared GEMM tile config
// ---------------------------------------------------------------------------
#define LDT   40
#define TILE_B (128 * LDT * 2)   // 10240
#define OFF_AH 0
#define OFF_AL (TILE_B)
#define OFF_BH (2 * TILE_B)
#define OFF_BL (3 * TILE_B)
#define STAGE_B (4 * TILE_B)     // 40960
#define GSMEM  (2 * STAGE_B)     // 81920

#define STAGE2_B (3 * TILE_B)    // 30720 (fp16 2-combo: Ah, Al, B)
#define GSMEM2 (3 * STAGE2_B)    // 92160 (3-stage pipeline)

// ---------------------------------------------------------------------------
// Q/K projection GEMM (split-bf16, 3 combos): sel = blockIdx.x>>4 in {0,1}.
// 2-stage double buffer (smem-bound; 2 CTAs/SM).
// ---------------------------------------------------------------------------
__global__ __launch_bounds__(256, 2) void gemm_qk(
    const __nv_bfloat16* __restrict__ Ah, const __nv_bfloat16* __restrict__ Al,
    const __nv_bfloat16* __restrict__ Wqh, const __nv_bfloat16* __restrict__ Wql,
    const __nv_bfloat16* __restrict__ Wkh, const __nv_bfloat16* __restrict__ Wkl,
    const float* __restrict__ bq, const float* __restrict__ bk,
    __nv_bfloat16* __restrict__ Qh, __nv_bfloat16* __restrict__ Ql,
    __nv_bfloat16* __restrict__ Kh, __nv_bfloat16* __restrict__ Kl)
{
    extern __shared__ char smem[];
    const uint32_t sb = smem_u32(smem);
    const int tid  = threadIdx.x;
    const int lane = tid & 31;
    const int warp = tid >> 5;
    const int wm = warp >> 2;
    const int wn = warp & 3;
    const int sel = blockIdx.x >> 4;            // 0=Q 1=K
    const int n0  = (blockIdx.x & 15) * 128;
    const int m0  = blockIdx.y * 128;

    const __nv_bfloat16* Bh = sel ? Wkh : Wqh;
    const __nv_bfloat16* Bl = sel ? Wkl : Wql;
    const float* bias = sel ? bk : bq;
    const float scale = sel ? 1.0f : QSCALE;

    const __nv_bfloat16* pAh = Ah + (size_t)m0 * PHID;
    const __nv_bfloat16* pAl = Al + (size_t)m0 * PHID;
    const __nv_bfloat16* pBh = Bh + (size_t)n0 * PHID;
    const __nv_bfloat16* pBl = Bl + (size_t)n0 * PHID;

    const int r0 = tid >> 2;
    const int c0 = (tid & 3) * 8;
    const uint32_t so0 = (uint32_t)(r0 * 80 + (tid & 3) * 16);
    const uint32_t so1 = (uint32_t)((r0 + 64) * 80 + (tid & 3) * 16);

    const uint32_t a_off = (uint32_t)((wm * 64 + (lane & 15)) * 80 + ((lane >> 4) << 4));
    const uint32_t b4_off = (uint32_t)((wn * 32 + ((lane >> 4) << 3) + (lane & 7)) * 80
                                       + ((lane & 8) ? 16 : 0));

    float acc[4][4][4];
#pragma unroll
    for (int mi = 0; mi < 4; mi++)
#pragma unroll
        for (int ni = 0; ni < 4; ni++)
#pragma unroll
            for (int j = 0; j < 4; j++) acc[mi][ni][j] = 0.0f;

    auto load_stage = [&](int stage, int kc) {
        const uint32_t st = sb + stage * STAGE_B;
        const size_t g0 = (size_t)r0 * PHID + kc * 32 + c0;
        const size_t g1 = (size_t)(r0 + 64) * PHID + kc * 32 + c0;
        cp16(st + OFF_AH + so0, pAh + g0);
        cp16(st + OFF_AH + so1, pAh + g1);
        cp16(st + OFF_AL + so0, pAl + g0);
        cp16(st + OFF_AL + so1, pAl + g1);
        cp16(st + OFF_BH + so0, pBh + g0);
        cp16(st + OFF_BH + so1, pBh + g1);
        cp16(st + OFF_BL + so0, pBl + g0);
        cp16(st + OFF_BL + so1, pBl + g1);
    };

    auto compute_stage = [&](int stage) {
        const uint32_t st = sb + stage * STAGE_B;
#pragma unroll
        for (int ks = 0; ks < 2; ks++) {
            const uint32_t k32 = ks * 32;
            uint32_t bhf[4][2], blf[4][2], a[4][4];
            ldm_x4(&bhf[0][0], st + OFF_BH + b4_off + k32);
            ldm_x4(&bhf[2][0], st + OFF_BH + b4_off + 1280 + k32);
            ldm_x4(&blf[0][0], st + OFF_BL + b4_off + k32);
            ldm_x4(&blf[2][0], st + OFF_BL + b4_off + 1280 + k32);
#pragma unroll
            for (int mi = 0; mi < 4; mi++)
                ldm_x4(a[mi], st + OFF_AH + a_off + mi * 1280 + k32);
#pragma unroll
            for (int mi = 0; mi < 4; mi++)
#pragma unroll
                for (int ni = 0; ni < 4; ni++)
                    mma_bf16(acc[mi][ni], a[mi], bhf[ni]);
#pragma unroll
            for (int mi = 0; mi < 4; mi++)
#pragma unroll
                for (int ni = 0; ni < 4; ni++)
                    mma_bf16(acc[mi][ni], a[mi], blf[ni]);
#pragma unroll
            for (int mi = 0; mi < 4; mi++)
                ldm_x4(a[mi], st + OFF_AL + a_off + mi * 1280 + k32);
#pragma unroll
            for (int mi = 0; mi < 4; mi++)
#pragma unroll
                for (int ni = 0; ni < 4; ni++)
                    mma_bf16(acc[mi][ni], a[mi], bhf[ni]);
        }
    };

    load_stage(0, 0);
    CP_COMMIT();
    const int NKC = PHID / 32;
    for (int kc = 0; kc < NKC; kc++) {
        if (kc + 1 < NKC) {
            load_stage((kc + 1) & 1, kc + 1);
            CP_COMMIT();
            CP_WAIT(1);
        } else {
            CP_WAIT(0);
        }
        __syncthreads();
        compute_stage(kc & 1);
        __syncthreads();
    }

    __nv_bfloat16* Oh = sel ? Kh : Qh;
    __nv_bfloat16* Ol = sel ? Kl : Ql;
#pragma unroll
    for (int mi = 0; mi < 4; mi++) {
        const int row = m0 + wm * 64 + mi * 16 + (lane >> 2);
#pragma unroll
        for (int ni = 0; ni < 4; ni++) {
            const int col = n0 + wn * 32 + ni * 8 + (lane & 3) * 2;
            const float b0 = bias[col], b1 = bias[col + 1];
            float v00 = (acc[mi][ni][0] + b0) * scale;
            float v01 = (acc[mi][ni][1] + b1) * scale;
            float v10 = (acc[mi][ni][2] + b0) * scale;
            float v11 = (acc[mi][ni][3] + b1) * scale;
            uint32_t hp, lp;
            packsplit(v00, v01, hp, lp);
            *(uint32_t*)(Oh + (size_t)row * PHID + col) = hp;
            *(uint32_t*)(Ol + (size_t)row * PHID + col) = lp;
            packsplit(v10, v11, hp, lp);
            *(uint32_t*)(Oh + (size_t)(row + 8) * PHID + col) = hp;
            *(uint32_t*)(Ol + (size_t)(row + 8) * PHID + col) = lp;
        }
    }
}

// ---------------------------------------------------------------------------
// fp16 2-combo GEMM: C = (Ah + Al) @ B^T + bias.  3-stage pipeline,
// ONE __syncthreads per K-chunk (load of stage (kc+2)%3 == (kc-1)%3 is safe:
// its compute finished before this iteration's barrier).
// ---------------------------------------------------------------------------
__global__ __launch_bounds__(256, 2) void gemm_f16_2c(
    const __half* __restrict__ Ah, const __half* __restrict__ Al,
    const __half* __restrict__ Bt,
    const float* __restrict__ bias, float* __restrict__ Cf,
    __half* __restrict__ Co)
{
    extern __shared__ char smem[];
    const uint32_t sb = smem_u32(smem);
    const int tid  = threadIdx.x;
    const int lane = tid & 31;
    const int warp = tid >> 5;
    const int wm = warp >> 2;
    const int wn = warp & 3;
    const int m0 = blockIdx.y * 128;
    const int n0 = blockIdx.x * 128;

    const __half* pAh = Ah + (size_t)m0 * PHID;
    const __half* pAl = Al + (size_t)m0 * PHID;
    const __half* pB  = Bt + (size_t)n0 * PHID;

    const int r0 = tid >> 2;
    const int c0 = (tid & 3) * 8;
    const uint32_t so0 = (uint32_t)(r0 * 80 + (tid & 3) * 16);
    const uint32_t so1 = (uint32_t)((r0 + 64) * 80 + (tid & 3) * 16);

    const uint32_t a_off = (uint32_t)((wm * 64 + (lane & 15)) * 80 + ((lane >> 4) << 4));
    const uint32_t b4_off = (uint32_t)((wn * 32 + ((lane >> 4) << 3) + (lane & 7)) * 80
                                       + ((lane & 8) ? 16 : 0));

    float acc[4][4][4];
#pragma unroll
    for (int mi = 0; mi < 4; mi++)
#pragma unroll
        for (int ni = 0; ni < 4; ni++)
#pragma unroll
            for (int j = 0; j < 4; j++) acc[mi][ni][j] = 0.0f;

    auto load_stage = [&](int stage, int kc) {
        const uint32_t st = sb + stage * STAGE2_B;
        const size_t g0 = (size_t)r0 * PHID + kc * 32 + c0;
        const size_t g1 = (size_t)(r0 + 64) * PHID + kc * 32 + c0;
        cp16(st + OFF_AH + so0, pAh + g0);
        cp16(st + OFF_AH + so1, pAh + g1);
        cp16(st + OFF_AL + so0, pAl + g0);
        cp16(st + OFF_AL + so1, pAl + g1);
        cp16(st + OFF_BH + so0, pB + g0);
        cp16(st + OFF_BH + so1, pB + g1);
    };

    auto compute_stage = [&](int stage) {
        const uint32_t st = sb + stage * STAGE2_B;
#pragma unroll
        for (int ks = 0; ks < 2; ks++) {
            const uint32_t k32 = ks * 32;
            uint32_t bf[4][2], a[4][4];
            ldm_x4(&bf[0][0], st + OFF_BH + b4_off + k32);
            ldm_x4(&bf[2][0], st + OFF_BH + b4_off + 1280 + k32);
#pragma unroll
            for (int mi = 0; mi < 4; mi++)
                ldm_x4(a[mi], st + OFF_AH + a_off + mi * 1280 + k32);
#pragma unroll
            for (int mi = 0; mi < 4; mi++)
#pragma unroll
                for (int ni = 0; ni < 4; ni++)
                    mma_f16(acc[mi][ni], a[mi], bf[ni]);
#pragma unroll
            for (int mi = 0; mi < 4; mi++)
                ldm_x4(a[mi], st + OFF_AL + a_off + mi * 1280 + k32);
#pragma unroll
            for (int mi = 0; mi < 4; mi++)
#pragma unroll
                for (int ni = 0; ni < 4; ni++)
                    mma_f16(acc[mi][ni], a[mi], bf[ni]);
        }
    };

    load_stage(0, 0);
    CP_COMMIT();
    load_stage(1, 1);
    CP_COMMIT();
    const int NKC = PHID / 32;   // 64
    for (int kc = 0; kc < NKC; kc++) {
        if (kc < NKC - 1) { CP_WAIT(1); } else { CP_WAIT(0); }
        __syncthreads();
        compute_stage(kc % 3);
        if (kc + 2 < NKC) {
            load_stage((kc + 2) % 3, kc + 2);
            CP_COMMIT();
        }
    }

#pragma unroll
    for (int mi = 0; mi < 4; mi++) {
        const int row = m0 + wm * 64 + mi * 16 + (lane >> 2);
#pragma unroll
        for (int ni = 0; ni < 4; ni++) {
            const int col = n0 + wn * 32 + ni * 8 + (lane & 3) * 2;
            const float b0 = bias[col], b1 = bias[col + 1];
            float v00 = acc[mi][ni][0] + b0;
            float v01 = acc[mi][ni][1] + b1;
            float v10 = acc[mi][ni][2] + b0;
            float v11 = acc[mi][ni][3] + b1;
            if (Cf) {
                *(float2*)(Cf + (size_t)row * PHID + col)       = make_float2(v00, v01);
                *(float2*)(Cf + (size_t)(row + 8) * PHID + col) = make_float2(v10, v11);
            } else {
                __half2 p0 = __floats2half2_rn(v00, v01);
                __half2 p1 = __floats2half2_rn(v10, v11);
                *(uint32_t*)(Co + (size_t)row * PHID + col) =
                    *reinterpret_cast<uint32_t*>(&p0);
                *(uint32_t*)(Co + (size_t)(row + 8) * PHID + col) =
                    *reinterpret_cast<uint32_t*>(&p1);
            }
        }
    }
}

// ---------------------------------------------------------------------------
// Tensor-core flash attention: QK split-bf16 (3 combos), PV fp16 (1 combo),
// P via f16x2 MUFU exp, row sums via ones-MMA.  ctx out: split fp16.
// 3 K/V stages, ONE __syncthreads per tile.
// ---------------------------------------------------------------------------
#define AT_LDB  272
#define AT_QH   0
#define AT_QL   (128 * AT_LDB)            // 34816
#define AT_ST0  (2 * 128 * AT_LDB)        // 69632
#define AT_TILE (64 * AT_LDB)             // 17408
#define AT_STAGE (3 * AT_TILE)            // 52224
#define AT_SMEM (AT_ST0 + 3 * AT_STAGE)   // 226304

__global__ __launch_bounds__(256, 1) void attn_mma(
    const __nv_bfloat16* __restrict__ Qh, const __nv_bfloat16* __restrict__ Ql,
    const __nv_bfloat16* __restrict__ Kh, const __nv_bfloat16* __restrict__ Kl,
    const __half* __restrict__ Vh,
    const float* __restrict__ Bias,
    __half* __restrict__ Ch, __half* __restrict__ Cl)
{
    extern __shared__ char smem[];
    const uint32_t sb = smem_u32(smem);
    const int tid = threadIdx.x;
    const int lane = tid & 31;
    const int warp = tid >> 5;
    const int bh = blockIdx.y;
    const int b  = bh >> 4;
    const int h  = bh & 15;
    const int q0 = blockIdx.x * 128;
    const float L2E = 1.44269504f;

    const size_t base = (size_t)b * PS * PHID + (size_t)h * PD;
    const __nv_bfloat16* pQh = Qh + base + (size_t)q0 * PHID;
    const __nv_bfloat16* pQl = Ql + base + (size_t)q0 * PHID;
    const __nv_bfloat16* pKh = Kh + base;
    const __nv_bfloat16* pKl = Kl + base;
    const __half* pVh = Vh + base;

    // Q loader
    {
        const int r = tid >> 1;
        const int ce = (tid & 1) * 64;
        const uint32_t so = (uint32_t)(r * AT_LDB + (tid & 1) * 128);
#pragma unroll
        for (int i = 0; i < 8; i++) {
            cp16(sb + AT_QH + so + i * 16, pQh + (size_t)r * PHID + ce + i * 8);
            cp16(sb + AT_QL + so + i * 16, pQl + (size_t)r * PHID + ce + i * 8);
        }
    }

    // K/V stage loader (3 tiles: Kh, Kl, Vh)
    const int kvr  = tid >> 2;
    const int kvce = (tid & 3) * 32;
    const uint32_t kvso = (uint32_t)(kvr * AT_LDB + (tid & 3) * 64);
    auto load_stage = [&](int stage, int t) {
        const uint32_t st = sb + AT_ST0 + stage * AT_STAGE;
        const size_t g = (size_t)(t * 64 + kvr) * PHID + kvce;
#pragma unroll
        for (int i = 0; i < 4; i++) {
            cp16(st + kvso + i * 16,               pKh + g + i * 8);
            cp16(st + AT_TILE + kvso + i * 16,     pKl + g + i * 8);
            cp16(st + 2 * AT_TILE + kvso + i * 16, pVh + g + i * 8);
        }
    };

    load_stage(0, 0);
    CP_COMMIT();
    load_stage(1, 1);
    CP_COMMIT();

    const uint32_t q_off = (uint32_t)((warp * 16 + (lane & 15)) * AT_LDB + ((lane >> 4) << 4));
    const uint32_t k4_off = (uint32_t)((((lane >> 4) << 3) + (lane & 7)) * AT_LDB
                                       + ((lane & 8) ? 16 : 0));
    const uint32_t v4_off = (uint32_t)((((lane >> 3) & 1) * 8 + (lane & 7)) * AT_LDB
                                       + (lane >> 4) * 16);

    const float* biasR0 = Bias + ((size_t)bh * PS + q0 + warp * 16 + (lane >> 2)) * PS;
    const float* biasR1 = biasR0 + 8 * PS;
    const int bcol = (lane & 3) * 2;

    float o[16][4];
#pragma unroll
    for (int nd = 0; nd < 16; nd++)
#pragma unroll
        for (int j = 0; j < 4; j++) o[nd][j] = 0.0f;
    float lacc[4] = {0.0f, 0.0f, 0.0f, 0.0f};
    float m0 = -1e30f, m1 = -1e30f;
    const uint32_t ONESB[2] = {0x3C003C00u, 0x3C003C00u};

    // bias prefetch registers
    float2 nb0[8], nb1[8];
#pragma unroll
    for (int nf = 0; nf < 8; nf++) {
        nb0[nf] = *(const float2*)(biasR0 + nf * 8 + bcol);
        nb1[nf] = *(const float2*)(biasR1 + nf * 8 + bcol);
    }

    const int NT = PS / 64;   // 32
    for (int t = 0; t < NT; t++) {
        if (t < NT - 1) { CP_WAIT(1); } else { CP_WAIT(0); }
        __syncthreads();

        const uint32_t st = sb + AT_ST0 + (t % 3) * AT_STAGE;

        // consume prefetched bias, then prefetch next tile's bias
        float sc[8][4];
#pragma unroll
        for (int nf = 0; nf < 8; nf++) {
            sc[nf][0] = nb0[nf].x; sc[nf][1] = nb0[nf].y;
            sc[nf][2] = nb1[nf].x; sc[nf][3] = nb1[nf].y;
        }
        if (t + 1 < NT) {
            const int k1 = (t + 1) * 64;
#pragma unroll
            for (int nf = 0; nf < 8; nf++) {
                nb0[nf] = *(const float2*)(biasR0 + k1 + nf * 8 + bcol);
                nb1[nf] = *(const float2*)(biasR1 + k1 + nf * 8 + bcol);
            }
        }

        // ---- scores += Q K^T (split 3-combo), K via x4 pairs ----
#pragma unroll
        for (int ks = 0; ks < 8; ks++) {
            uint32_t qa[4], qla[4];
            ldm_x4(qa,  sb + AT_QH + q_off + ks * 32);
            ldm_x4(qla, sb + AT_QL + q_off + ks * 32);
#pragma unroll
            for (int nf2 = 0; nf2 < 4; nf2++) {
                uint32_t kbh[4], kbl[4];
                ldm_x4(kbh, st + k4_off + nf2 * 16 * AT_LDB + ks * 32);
                ldm_x4(kbl, st + AT_TILE + k4_off + nf2 * 16 * AT_LDB + ks * 32);
                mma_bf16(sc[2*nf2],   qa,  kbh);
                mma_bf16(sc[2*nf2+1], qa,  kbh + 2);
                mma_bf16(sc[2*nf2],   qa,  kbl);
                mma_bf16(sc[2*nf2+1], qa,  kbl + 2);
                mma_bf16(sc[2*nf2],   qla, kbh);
                mma_bf16(sc[2*nf2+1], qla, kbh + 2);
            }
        }

        // ---- online softmax: max ----
        float mx0 = sc[0][0], mx1 = sc[0][2];
#pragma unroll
        for (int nf = 0; nf < 8; nf++) {
            mx0 = fmaxf(mx0, fmaxf(sc[nf][0], sc[nf][1]));
            mx1 = fmaxf(mx1, fmaxf(sc[nf][2], sc[nf][3]));
        }
        mx0 = fmaxf(mx0, __shfl_xor_sync(0xffffffffu, mx0, 1));
        mx0 = fmaxf(mx0, __shfl_xor_sync(0xffffffffu, mx0, 2));
        mx1 = fmaxf(mx1, __shfl_xor_sync(0xffffffffu, mx1, 1));
        mx1 = fmaxf(mx1, __shfl_xor_sync(0xffffffffu, mx1, 2));
        const float mn0 = fmaxf(m0, mx0), mn1 = fmaxf(m1, mx1);
        const float mL0 = mn0 * L2E, mL1 = mn1 * L2E;
        const float al0 = ex2f((m0 - mn0) * L2E);
        const float al1 = ex2f((m1 - mn1) * L2E);
        m0 = mn0; m1 = mn1;

        // ---- rescale o and l accumulators (skip when max unchanged) ----
        if (al0 != 1.0f || al1 != 1.0f) {
#pragma unroll
            for (int nd = 0; nd < 16; nd++) {
                o[nd][0] *= al0; o[nd][1] *= al0;
                o[nd][2] *= al1; o[nd][3] *= al1;
            }
            lacc[0] *= al0; lacc[1] *= al0;
            lacc[2] *= al1; lacc[3] *= al1;
        }

        // ---- P fragments directly via f16x2 exp ----
        uint32_t pf[4][4];
#pragma unroll
        for (int j2 = 0; j2 < 4; j2++) {
            const int f0 = 2 * j2, f1 = f0 + 1;
            pf[j2][0] = h2ex2(fmaf(sc[f0][0], L2E, -mL0), fmaf(sc[f0][1], L2E, -mL0));
            pf[j2][1] = h2ex2(fmaf(sc[f0][2], L2E, -mL1), fmaf(sc[f0][3], L2E, -mL1));
            pf[j2][2] = h2ex2(fmaf(sc[f1][0], L2E, -mL0), fmaf(sc[f1][1], L2E, -mL0));
            pf[j2][3] = h2ex2(fmaf(sc[f1][2], L2E, -mL1), fmaf(sc[f1][3], L2E, -mL1));
        }

        // ---- O += P V; l += P 1 (ones-MMA); V via x4.trans pairs ----
#pragma unroll
        for (int j2 = 0; j2 < 4; j2++) {
            mma_f16(lacc, pf[j2], ONESB);
            const uint32_t vrow = st + 2 * AT_TILE + v4_off + j2 * 16 * AT_LDB;
#pragma unroll
            for (int nd2 = 0; nd2 < 8; nd2++) {
                uint32_t vbh[4];
                ldm_x4t(vbh, vrow + nd2 * 32);
                mma_f16(o[2*nd2],   pf[j2], vbh);
                mma_f16(o[2*nd2+1], pf[j2], vbh + 2);
            }
        }

        if (t + 2 < NT) {
            load_stage((t + 2) % 3, t + 2);
            CP_COMMIT();
        }
    }

    // ---- epilogue: normalize, split fp16, store ctx ----
    const float inv0 = 1.0f / lacc[0], inv1 = 1.0f / lacc[2];
    const int rg0 = q0 + warp * 16 + (lane >> 2);
    __half* och = Ch + base;
    __half* ocl = Cl + base;
#pragma unroll
    for (int nd = 0; nd < 16; nd++) {
        const int col = nd * 8 + (lane & 3) * 2;
        uint32_t hp, lp;
        packsplit_f16(o[nd][0] * inv0, o[nd][1] * inv0, hp, lp);
        *(uint32_t*)(och + (size_t)rg0 * PHID + col) = hp;
        *(uint32_t*)(ocl + (size_t)rg0 * PHID + col) = lp;
        packsplit_f16(o[nd][2] * inv1, o[nd][3] * inv1, hp, lp);
        *(uint32_t*)(och + (size_t)(rg0 + 8) * PHID + col) = hp;
        *(uint32_t*)(ocl + (size_t)(rg0 + 8) * PHID + col) = lp;
    }
}

// ---------------------------------------------------------------------------
extern "C" void kernel_launch(void* const* d_in, const int* in_sizes, int n_in,
                              void* d_out, int out_size)
{
    (void)in_sizes; (void)n_in; (void)out_size;
    const float* x    = (const float*)d_in[0];
    const float* bias = (const float*)d_in[1];
    const float* Wq   = (const float*)d_in[2];
    const float* bq   = (const float*)d_in[3];
    const float* Wk   = (const float*)d_in[4];
    const float* bk   = (const float*)d_in[5];
    const float* Wv   = (const float*)d_in[6];
    const float* bv   = (const float*)d_in[7];
    const float* Wo   = (const float*)d_in[8];
    const float* bo   = (const float*)d_in[9];
    float* out = (float*)d_out;

    __nv_bfloat16 *xh, *xl, *qh, *ql, *kh, *kl;
    __half *xh2, *xl2, *vhf, *ch2, *cl2, *wvt, *wot;
    __nv_bfloat16 *wqh, *wql, *wkh, *wkl;
    cudaGetSymbolAddress((void**)&xh, g_xh);
    cudaGetSymbolAddress((void**)&xl, g_xl);
    cudaGetSymbolAddress((void**)&xh2, g_xh2);
    cudaGetSymbolAddress((void**)&xl2, g_xl2);
    cudaGetSymbolAddress((void**)&qh, g_qh);
    cudaGetSymbolAddress((void**)&ql, g_ql);
    cudaGetSymbolAddress((void**)&kh, g_kh);
    cudaGetSymbolAddress((void**)&kl, g_kl);
    cudaGetSymbolAddress((void**)&vhf, g_vhf);
    cudaGetSymbolAddress((void**)&ch2, g_ch2);
    cudaGetSymbolAddress((void**)&cl2, g_cl2);
    cudaGetSymbolAddress((void**)&wqh, g_wqh);
    cudaGetSymbolAddress((void**)&wql, g_wql);
    cudaGetSymbolAddress((void**)&wkh, g_wkh);
    cudaGetSymbolAddress((void**)&wkl, g_wkl);
    cudaGetSymbolAddress((void**)&wvt, g_wvt);
    cudaGetSymbolAddress((void**)&wot, g_wot);

    static bool attr_set = false;
    if (!attr_set) {
        cudaFuncSetAttribute(gemm_qk,
                             cudaFuncAttributeMaxDynamicSharedMemorySize, GSMEM);
        cudaFuncSetAttribute(gemm_f16_2c,
                             cudaFuncAttributeMaxDynamicSharedMemorySize, GSMEM2);
        cudaFuncSetAttribute(attn_mma,
                             cudaFuncAttributeMaxDynamicSharedMemorySize, AT_SMEM);
        attr_set = true;
    }

    // 1) conversions
    {
        int n4 = PM * PHID / 4;
        split_x_kernel<<<(n4 + 255) / 256, 256>>>(x, xh, xl, xh2, xl2, n4);
        dim3 tg(PHID / 32, PHID / 32, 4);
        dim3 tb(32, 8);
        transpose_all_kernel<<<tg, tb>>>(Wq, Wk, Wv, Wo,
                                         wqh, wql, wkh, wkl, wvt, wot);
    }

    // 2) projections
    dim3 qkgrid(2 * PHID / 128, PM / 128);    // (32, 32)
    gemm_qk<<<qkgrid, 256, GSMEM>>>(xh, xl, wqh, wql, wkh, wkl,
                                    bq, bk, qh, ql, kh, kl);
    dim3 vgrid(PHID / 128, PM / 128);         // (16, 32)
    gemm_f16_2c<<<vgrid, 256, GSMEM2>>>(xh2, xl2, wvt, bv, nullptr, vhf);

    // 3) tensor-core attention -> split fp16 ctx
    dim3 agrid(PS / 128, PB * PH);            // (16, 32)
    attn_mma<<<agrid, 256, AT_SMEM>>>(qh, ql, kh, kl, vhf, bias, ch2, cl2);

    // 4) output projection -> fp32 out
    gemm_f16_2c<<<vgrid, 256, GSMEM2>>>(ch2, cl2, wot, bo, out, nullptr);
}

// round 12
// speedup vs baseline: 4.2050x; 1.0080x over previous
#include <cuda_runtime.h>
#include <cuda_bf16.h>
#include <cuda_fp16.h>
#include <math.h>
#include <stdint.h>

// Problem constants
#define PB   2
#define PS   2048
#define PHID 2048
#define PH   16
#define PD   128
#define PM   (PB * PS)          // 4096 rows
#define QSCALE 11.313708498984760f   // sqrt(128)

// ---------------------------------------------------------------------------
// Scratch (no cudaMalloc allowed)
// ---------------------------------------------------------------------------
__device__ __nv_bfloat16 g_xh[(size_t)PM * PHID];    // x split bf16 (QK path)
__device__ __nv_bfloat16 g_xl[(size_t)PM * PHID];
__device__ __half        g_xh2[(size_t)PM * PHID];   // x split fp16 (V path)
__device__ __half        g_xl2[(size_t)PM * PHID];
__device__ __nv_bfloat16 g_qh[(size_t)PM * PHID];
__device__ __nv_bfloat16 g_ql[(size_t)PM * PHID];
__device__ __nv_bfloat16 g_kh[(size_t)PM * PHID];
__device__ __nv_bfloat16 g_kl[(size_t)PM * PHID];
__device__ __half        g_vhf[(size_t)PM * PHID];   // V, fp16
__device__ __half        g_ch2[(size_t)PM * PHID];   // ctx split fp16
__device__ __half        g_cl2[(size_t)PM * PHID];

// transposed weights [N,K]
__device__ __nv_bfloat16 g_wqh[(size_t)PHID * PHID];
__device__ __nv_bfloat16 g_wql[(size_t)PHID * PHID];
__device__ __nv_bfloat16 g_wkh[(size_t)PHID * PHID];
__device__ __nv_bfloat16 g_wkl[(size_t)PHID * PHID];
__device__ __half        g_wvt[(size_t)PHID * PHID]; // Wv^T single fp16
__device__ __half        g_wot[(size_t)PHID * PHID]; // Wo^T single fp16

// ---------------------------------------------------------------------------
// Helpers
// ---------------------------------------------------------------------------
__device__ __forceinline__ uint32_t smem_u32(const void* p) {
    uint32_t a;
    asm("{ .reg .u64 t; cvta.to.shared.u64 t, %1; cvt.u32.u64 %0, t; }"
        : "=r"(a) : "l"(p));
    return a;
}

__device__ __forceinline__ void cp16(uint32_t s, const void* g) {
    asm volatile("cp.async.cg.shared.global [%0], [%1], 16;" :: "r"(s), "l"(g));
}
#define CP_COMMIT() asm volatile("cp.async.commit_group;" ::: "memory")
#define CP_WAIT(n)  asm volatile("cp.async.wait_group %0;" :: "n"(n) : "memory")

__device__ __forceinline__ void ldm_x4(uint32_t* r, uint32_t addr) {
    asm volatile("ldmatrix.sync.aligned.m8n8.x4.shared.b16 {%0,%1,%2,%3}, [%4];"
                 : "=r"(r[0]), "=r"(r[1]), "=r"(r[2]), "=r"(r[3]) : "r"(addr));
}
__device__ __forceinline__ void ldm_x4t(uint32_t* r, uint32_t addr) {
    asm volatile("ldmatrix.sync.aligned.m8n8.x4.trans.shared.b16 {%0,%1,%2,%3}, [%4];"
                 : "=r"(r[0]), "=r"(r[1]), "=r"(r[2]), "=r"(r[3]) : "r"(addr));
}
__device__ __forceinline__ void mma_bf16(float* c, const uint32_t* a, const uint32_t* b) {
    asm volatile(
        "mma.sync.aligned.m16n8k16.row.col.f32.bf16.bf16.f32 "
        "{%0,%1,%2,%3}, {%4,%5,%6,%7}, {%8,%9}, {%0,%1,%2,%3};"
        : "+f"(c[0]), "+f"(c[1]), "+f"(c[2]), "+f"(c[3])
        : "r"(a[0]), "r"(a[1]), "r"(a[2]), "r"(a[3]), "r"(b[0]), "r"(b[1]));
}
__device__ __forceinline__ void mma_f16(float* c, const uint32_t* a, const uint32_t* b) {
    asm volatile(
        "mma.sync.aligned.m16n8k16.row.col.f32.f16.f16.f32 "
        "{%0,%1,%2,%3}, {%4,%5,%6,%7}, {%8,%9}, {%0,%1,%2,%3};"
        : "+f"(c[0]), "+f"(c[1]), "+f"(c[2]), "+f"(c[3])
        : "r"(a[0]), "r"(a[1]), "r"(a[2]), "r"(a[3]), "r"(b[0]), "r"(b[1]));
}

__device__ __forceinline__ float ex2f(float x) {
    float r;
    asm("ex2.approx.f32 %0, %1;" : "=f"(r) : "f"(x));
    return r;
}

// pack two fp32 exponent args into f16x2 and take 2^x on both at once
__device__ __forceinline__ uint32_t h2ex2(float y0, float y1) {
    uint32_t h, p;
    asm("cvt.rn.f16x2.f32 %0, %1, %2;" : "=r"(h) : "f"(y1), "f"(y0));
    asm("ex2.approx.f16x2 %0, %1;" : "=r"(p) : "r"(h));
    return p;
}

// Fast RNE split of two floats into (hi bf16x2, lo bf16x2).
__device__ __forceinline__ void packsplit(float a, float b, uint32_t& hp, uint32_t& lp) {
    asm("cvt.rn.bf16x2.f32 %0, %1, %2;" : "=r"(hp) : "f"(b), "f"(a));
    float ah = __uint_as_float(hp << 16);
    float bh = __uint_as_float(hp & 0xFFFF0000u);
    float la = a - ah;
    float lb = b - bh;
    asm("cvt.rn.bf16x2.f32 %0, %1, %2;" : "=r"(lp) : "f"(lb), "f"(la));
}

// RNE split of two floats into (hi f16x2, lo f16x2).
__device__ __forceinline__ void packsplit_f16(float a, float b, uint32_t& hp, uint32_t& lp) {
    __half2 h = __floats2half2_rn(a, b);
    float la = a - __half2float(__low2half(h));
    float lb = b - __half2float(__high2half(h));
    __half2 l = __floats2half2_rn(la, lb);
    hp = *reinterpret_cast<uint32_t*>(&h);
    lp = *reinterpret_cast<uint32_t*>(&l);
}

// ---------------------------------------------------------------------------
// Conversion kernels
// ---------------------------------------------------------------------------
__global__ void split_x_kernel(const float* __restrict__ in,
                               __nv_bfloat16* __restrict__ hb,
                               __nv_bfloat16* __restrict__ lb,
                               __half* __restrict__ hf,
                               __half* __restrict__ lf, int n4)
{
    int i = blockIdx.x * blockDim.x + threadIdx.x;
    if (i >= n4) return;
    float4 v = ((const float4*)in)[i];
    uint32_t h0, l0, h1, l1;
    packsplit(v.x, v.y, h0, l0);
    packsplit(v.z, v.w, h1, l1);
    ((uint32_t*)hb)[2*i]   = h0;
    ((uint32_t*)hb)[2*i+1] = h1;
    ((uint32_t*)lb)[2*i]   = l0;
    ((uint32_t*)lb)[2*i+1] = l1;
    packsplit_f16(v.x, v.y, h0, l0);
    packsplit_f16(v.z, v.w, h1, l1);
    ((uint32_t*)hf)[2*i]   = h0;
    ((uint32_t*)hf)[2*i+1] = h1;
    ((uint32_t*)lf)[2*i]   = l0;
    ((uint32_t*)lf)[2*i+1] = l1;
}

// One launch transposes all 4 weight matrices.  z=0,1 -> bf16 split (Wq, Wk);
// z=2,3 -> single fp16 (Wv, Wo).
__global__ void transpose_all_kernel(
    const float* __restrict__ Wq, const float* __restrict__ Wk,
    const float* __restrict__ Wv, const float* __restrict__ Wo,
    __nv_bfloat16* __restrict__ Tqh, __nv_bfloat16* __restrict__ Tql,
    __nv_bfloat16* __restrict__ Tkh, __nv_bfloat16* __restrict__ Tkl,
    __half* __restrict__ Tv, __half* __restrict__ To)
{
    __shared__ float t[32][33];
    int z = blockIdx.z;
    const float* W = (z == 0) ? Wq : (z == 1) ? Wk : (z == 2) ? Wv : Wo;
    int n0 = blockIdx.x * 32, k0 = blockIdx.y * 32;
    int tx = threadIdx.x, ty0 = threadIdx.y;   // 32 x 8
#pragma unroll
    for (int j = 0; j < 32; j += 8)
        t[ty0 + j][tx] = W[(size_t)(k0 + ty0 + j) * PHID + n0 + tx];
    __syncthreads();
#pragma unroll
    for (int j = 0; j < 32; j += 8) {
        int n = ty0 + j;
        float v = t[tx][n];
        size_t o = (size_t)(n0 + n) * PHID + k0 + tx;
        if (z < 2) {
            __nv_bfloat16 h = __float2bfloat16(v);
            __nv_bfloat16 l = __float2bfloat16(v - __bfloat162float(h));
            if (z == 0) { Tqh[o] = h; Tql[o] = l; }
            else        { Tkh[o] = h; Tkl[o] = l; }
        } else {
            __half h = __float2half_rn(v);
            if (z == 2) Tv[o] = h; else To[o] = h;
        }
    }
}

// ---------------------------------------------------------------------------
// GEMM tile configs
// ---------------------------------------------------------------------------
#define LDT   40
#define TILE_B (128 * LDT * 2)   // 10240
#define OFF_AH 0
#define OFF_AL (TILE_B)
#define OFF_BH (2 * TILE_B)
#define OFF_BL (3 * TILE_B)

#define STAGE2_B (3 * TILE_B)    // 30720 (fp16 2-combo: Ah, Al, B)
#define GSMEM2 (3 * STAGE2_B)    // 92160 (3-stage pipeline)

// gemm_qk 4-stage BK=16 ring: tile = 128 rows x 48B (16 bf16 + 8 pad)
#define QK_TILE  6144
#define QK_AH    0
#define QK_AL    (QK_TILE)
#define QK_BH    (2 * QK_TILE)
#define QK_BL    (3 * QK_TILE)
#define QK_STAGE (4 * QK_TILE)   // 24576
#define QK_SMEM  (4 * QK_STAGE)  // 98304

// ---------------------------------------------------------------------------
// Q/K projection GEMM (split-bf16, 3 combos): sel = blockIdx.x>>4 in {0,1}.
// 4-stage BK=16 ring, ONE __syncthreads per chunk, 3-chunk prefetch.
// ---------------------------------------------------------------------------
__global__ __launch_bounds__(256, 2) void gemm_qk(
    const __nv_bfloat16* __restrict__ Ah, const __nv_bfloat16* __restrict__ Al,
    const __nv_bfloat16* __restrict__ Wqh, const __nv_bfloat16* __restrict__ Wql,
    const __nv_bfloat16* __restrict__ Wkh, const __nv_bfloat16* __restrict__ Wkl,
    const float* __restrict__ bq, const float* __restrict__ bk,
    __nv_bfloat16* __restrict__ Qh, __nv_bfloat16* __restrict__ Ql,
    __nv_bfloat16* __restrict__ Kh, __nv_bfloat16* __restrict__ Kl)
{
    extern __shared__ char smem[];
    const uint32_t sb = smem_u32(smem);
    const int tid  = threadIdx.x;
    const int lane = tid & 31;
    const int warp = tid >> 5;
    const int wm = warp >> 2;
    const int wn = warp & 3;
    const int sel = blockIdx.x >> 4;            // 0=Q 1=K
    const int n0  = (blockIdx.x & 15) * 128;
    const int m0  = blockIdx.y * 128;

    const __nv_bfloat16* Bh = sel ? Wkh : Wqh;
    const __nv_bfloat16* Bl = sel ? Wkl : Wql;
    const float* bias = sel ? bk : bq;
    const float scale = sel ? 1.0f : QSCALE;

    const __nv_bfloat16* pAh = Ah + (size_t)m0 * PHID;
    const __nv_bfloat16* pAl = Al + (size_t)m0 * PHID;
    const __nv_bfloat16* pBh = Bh + (size_t)n0 * PHID;
    const __nv_bfloat16* pBl = Bl + (size_t)n0 * PHID;

    // loader: 256 threads, one 16B chunk per tile each
    const int r0 = tid >> 1;               // 0..127
    const int ce = (tid & 1) * 8;          // elem col within 16
    const uint32_t so = (uint32_t)(r0 * 48 + (tid & 1) * 16);

    const uint32_t a_off = (uint32_t)((wm * 64 + (lane & 15)) * 48 + ((lane >> 4) << 4));
    const uint32_t b4_off = (uint32_t)((wn * 32 + ((lane >> 4) << 3) + (lane & 7)) * 48
                                       + ((lane & 8) ? 16 : 0));

    float acc[4][4][4];
#pragma unroll
    for (int mi = 0; mi < 4; mi++)
#pragma unroll
        for (int ni = 0; ni < 4; ni++)
#pragma unroll
            for (int j = 0; j < 4; j++) acc[mi][ni][j] = 0.0f;

    auto load_stage = [&](int stage, int kc) {
        const uint32_t st = sb + stage * QK_STAGE;
        const size_t g = (size_t)r0 * PHID + kc * 16 + ce;
        cp16(st + QK_AH + so, pAh + g);
        cp16(st + QK_AL + so, pAl + g);
        cp16(st + QK_BH + so, pBh + g);
        cp16(st + QK_BL + so, pBl + g);
    };

    auto compute_stage = [&](int stage) {
        const uint32_t st = sb + stage * QK_STAGE;
        uint32_t bh0[4], bh1[4], bl0[4], bl1[4], a[4][4];
        ldm_x4(bh0, st + QK_BH + b4_off);
        ldm_x4(bh1, st + QK_BH + b4_off + 768);
        ldm_x4(bl0, st + QK_BL + b4_off);
        ldm_x4(bl1, st + QK_BL + b4_off + 768);
#pragma unroll
        for (int mi = 0; mi < 4; mi++)
            ldm_x4(a[mi], st + QK_AH + a_off + mi * 768);
#pragma unroll
        for (int mi = 0; mi < 4; mi++) {
            mma_bf16(acc[mi][0], a[mi], bh0);
            mma_bf16(acc[mi][1], a[mi], bh0 + 2);
            mma_bf16(acc[mi][2], a[mi], bh1);
            mma_bf16(acc[mi][3], a[mi], bh1 + 2);
        }
#pragma unroll
        for (int mi = 0; mi < 4; mi++) {
            mma_bf16(acc[mi][0], a[mi], bl0);
            mma_bf16(acc[mi][1], a[mi], bl0 + 2);
            mma_bf16(acc[mi][2], a[mi], bl1);
            mma_bf16(acc[mi][3], a[mi], bl1 + 2);
        }
#pragma unroll
        for (int mi = 0; mi < 4; mi++)
            ldm_x4(a[mi], st + QK_AL + a_off + mi * 768);
#pragma unroll
        for (int mi = 0; mi < 4; mi++) {
            mma_bf16(acc[mi][0], a[mi], bh0);
            mma_bf16(acc[mi][1], a[mi], bh0 + 2);
            mma_bf16(acc[mi][2], a[mi], bh1);
            mma_bf16(acc[mi][3], a[mi], bh1 + 2);
        }
    };

    load_stage(0, 0);
    CP_COMMIT();
    load_stage(1, 1);
    CP_COMMIT();
    load_stage(2, 2);
    CP_COMMIT();
    const int NKC = PHID / 16;   // 128
    for (int kc = 0; kc < NKC; kc++) {
        if (kc < NKC - 2)      { CP_WAIT(2); }
        else if (kc == NKC - 2){ CP_WAIT(1); }
        else                   { CP_WAIT(0); }
        __syncthreads();
        compute_stage(kc & 3);
        if (kc + 3 < NKC) {
            load_stage((kc + 3) & 3, kc + 3);
            CP_COMMIT();
        }
    }

    __nv_bfloat16* Oh = sel ? Kh : Qh;
    __nv_bfloat16* Ol = sel ? Kl : Ql;
#pragma unroll
    for (int mi = 0; mi < 4; mi++) {
        const int row = m0 + wm * 64 + mi * 16 + (lane >> 2);
#pragma unroll
        for (int ni = 0; ni < 4; ni++) {
            const int col = n0 + wn * 32 + ni * 8 + (lane & 3) * 2;
            const float b0 = bias[col], b1 = bias[col + 1];
            float v00 = (acc[mi][ni][0] + b0) * scale;
            float v01 = (acc[mi][ni][1] + b1) * scale;
            float v10 = (acc[mi][ni][2] + b0) * scale;
            float v11 = (acc[mi][ni][3] + b1) * scale;
            uint32_t hp, lp;
            packsplit(v00, v01, hp, lp);
            *(uint32_t*)(Oh + (size_t)row * PHID + col) = hp;
            *(uint32_t*)(Ol + (size_t)row * PHID + col) = lp;
            packsplit(v10, v11, hp, lp);
            *(uint32_t*)(Oh + (size_t)(row + 8) * PHID + col) = hp;
            *(uint32_t*)(Ol + (size_t)(row + 8) * PHID + col) = lp;
        }
    }
}

// ---------------------------------------------------------------------------
// fp16 2-combo GEMM: C = (Ah + Al) @ B^T + bias.  3-stage pipeline,
// ONE __syncthreads per K-chunk.
// ---------------------------------------------------------------------------
__global__ __launch_bounds__(256, 2) void gemm_f16_2c(
    const __half* __restrict__ Ah, const __half* __restrict__ Al,
    const __half* __restrict__ Bt,
    const float* __restrict__ bias, float* __restrict__ Cf,
    __half* __restrict__ Co)
{
    extern __shared__ char smem[];
    const uint32_t sb = smem_u32(smem);
    const int tid  = threadIdx.x;
    const int lane = tid & 31;
    const int warp = tid >> 5;
    const int wm = warp >> 2;
    const int wn = warp & 3;
    const int m0 = blockIdx.y * 128;
    const int n0 = blockIdx.x * 128;

    const __half* pAh = Ah + (size_t)m0 * PHID;
    const __half* pAl = Al + (size_t)m0 * PHID;
    const __half* pB  = Bt + (size_t)n0 * PHID;

    const int r0 = tid >> 2;
    const int c0 = (tid & 3) * 8;
    const uint32_t so0 = (uint32_t)(r0 * 80 + (tid & 3) * 16);
    const uint32_t so1 = (uint32_t)((r0 + 64) * 80 + (tid & 3) * 16);

    const uint32_t a_off = (uint32_t)((wm * 64 + (lane & 15)) * 80 + ((lane >> 4) << 4));
    const uint32_t b4_off = (uint32_t)((wn * 32 + ((lane >> 4) << 3) + (lane & 7)) * 80
                                       + ((lane & 8) ? 16 : 0));

    float acc[4][4][4];
#pragma unroll
    for (int mi = 0; mi < 4; mi++)
#pragma unroll
        for (int ni = 0; ni < 4; ni++)
#pragma unroll
            for (int j = 0; j < 4; j++) acc[mi][ni][j] = 0.0f;

    auto load_stage = [&](int stage, int kc) {
        const uint32_t st = sb + stage * STAGE2_B;
        const size_t g0 = (size_t)r0 * PHID + kc * 32 + c0;
        const size_t g1 = (size_t)(r0 + 64) * PHID + kc * 32 + c0;
        cp16(st + OFF_AH + so0, pAh + g0);
        cp16(st + OFF_AH + so1, pAh + g1);
        cp16(st + OFF_AL + so0, pAl + g0);
        cp16(st + OFF_AL + so1, pAl + g1);
        cp16(st + OFF_BH + so0, pB + g0);
        cp16(st + OFF_BH + so1, pB + g1);
    };

    auto compute_stage = [&](int stage) {
        const uint32_t st = sb + stage * STAGE2_B;
#pragma unroll
        for (int ks = 0; ks < 2; ks++) {
            const uint32_t k32 = ks * 32;
            uint32_t bf[4][2], a[4][4];
            ldm_x4(&bf[0][0], st + OFF_BH + b4_off + k32);
            ldm_x4(&bf[2][0], st + OFF_BH + b4_off + 1280 + k32);
#pragma unroll
            for (int mi = 0; mi < 4; mi++)
                ldm_x4(a[mi], st + OFF_AH + a_off + mi * 1280 + k32);
#pragma unroll
            for (int mi = 0; mi < 4; mi++)
#pragma unroll
                for (int ni = 0; ni < 4; ni++)
                    mma_f16(acc[mi][ni], a[mi], bf[ni]);
#pragma unroll
            for (int mi = 0; mi < 4; mi++)
                ldm_x4(a[mi], st + OFF_AL + a_off + mi * 1280 + k32);
#pragma unroll
            for (int mi = 0; mi < 4; mi++)
#pragma unroll
                for (int ni = 0; ni < 4; ni++)
                    mma_f16(acc[mi][ni], a[mi], bf[ni]);
        }
    };

    load_stage(0, 0);
    CP_COMMIT();
    load_stage(1, 1);
    CP_COMMIT();
    const int NKC = PHID / 32;   // 64
    for (int kc = 0; kc < NKC; kc++) {
        if (kc < NKC - 1) { CP_WAIT(1); } else { CP_WAIT(0); }
        __syncthreads();
        compute_stage(kc % 3);
        if (kc + 2 < NKC) {
            load_stage((kc + 2) % 3, kc + 2);
            CP_COMMIT();
        }
    }

#pragma unroll
    for (int mi = 0; mi < 4; mi++) {
        const int row = m0 + wm * 64 + mi * 16 + (lane >> 2);
#pragma unroll
        for (int ni = 0; ni < 4; ni++) {
            const int col = n0 + wn * 32 + ni * 8 + (lane & 3) * 2;
            const float b0 = bias[col], b1 = bias[col + 1];
            float v00 = acc[mi][ni][0] + b0;
            float v01 = acc[mi][ni][1] + b1;
            float v10 = acc[mi][ni][2] + b0;
            float v11 = acc[mi][ni][3] + b1;
            if (Cf) {
                *(float2*)(Cf + (size_t)row * PHID + col)       = make_float2(v00, v01);
                *(float2*)(Cf + (size_t)(row + 8) * PHID + col) = make_float2(v10, v11);
            } else {
                __half2 p0 = __floats2half2_rn(v00, v01);
                __half2 p1 = __floats2half2_rn(v10, v11);
                *(uint32_t*)(Co + (size_t)row * PHID + col) =
                    *reinterpret_cast<uint32_t*>(&p0);
                *(uint32_t*)(Co + (size_t)(row + 8) * PHID + col) =
                    *reinterpret_cast<uint32_t*>(&p1);
            }
        }
    }
}

// ---------------------------------------------------------------------------
// Tensor-core flash attention: QK split-bf16 (3 combos), PV fp16 (1 combo),
// P via f16x2 MUFU exp, row sums via ones-MMA.  ctx out: split fp16.
// 3 K/V stages, ONE __syncthreads per tile.
// ---------------------------------------------------------------------------
#define AT_LDB  272
#define AT_QH   0
#define AT_QL   (128 * AT_LDB)            // 34816
#define AT_ST0  (2 * 128 * AT_LDB)        // 69632
#define AT_TILE (64 * AT_LDB)             // 17408
#define AT_STAGE (3 * AT_TILE)            // 52224
#define AT_SMEM (AT_ST0 + 3 * AT_STAGE)   // 226304

__global__ __launch_bounds__(256, 1) void attn_mma(
    const __nv_bfloat16* __restrict__ Qh, const __nv_bfloat16* __restrict__ Ql,
    const __nv_bfloat16* __restrict__ Kh, const __nv_bfloat16* __restrict__ Kl,
    const __half* __restrict__ Vh,
    const float* __restrict__ Bias,
    __half* __restrict__ Ch, __half* __restrict__ Cl)
{
    extern __shared__ char smem[];
    const uint32_t sb = smem_u32(smem);
    const int tid = threadIdx.x;
    const int lane = tid & 31;
    const int warp = tid >> 5;
    const int bh = blockIdx.y;
    const int b  = bh >> 4;
    const int h  = bh & 15;
    const int q0 = blockIdx.x * 128;
    const float L2E = 1.44269504f;

    const size_t base = (size_t)b * PS * PHID + (size_t)h * PD;
    const __nv_bfloat16* pQh = Qh + base + (size_t)q0 * PHID;
    const __nv_bfloat16* pQl = Ql + base + (size_t)q0 * PHID;
    const __nv_bfloat16* pKh = Kh + base;
    const __nv_bfloat16* pKl = Kl + base;
    const __half* pVh = Vh + base;

    // Q loader
    {
        const int r = tid >> 1;
        const int ce = (tid & 1) * 64;
        const uint32_t so = (uint32_t)(r * AT_LDB + (tid & 1) * 128);
#pragma unroll
        for (int i = 0; i < 8; i++) {
            cp16(sb + AT_QH + so + i * 16, pQh + (size_t)r * PHID + ce + i * 8);
            cp16(sb + AT_QL + so + i * 16, pQl + (size_t)r * PHID + ce + i * 8);
        }
    }

    // K/V stage loader (3 tiles: Kh, Kl, Vh)
    const int kvr  = tid >> 2;
    const int kvce = (tid & 3) * 32;
    const uint32_t kvso = (uint32_t)(kvr * AT_LDB + (tid & 3) * 64);
    auto load_stage = [&](int stage, int t) {
        const uint32_t st = sb + AT_ST0 + stage * AT_STAGE;
        const size_t g = (size_t)(t * 64 + kvr) * PHID + kvce;
#pragma unroll
        for (int i = 0; i < 4; i++) {
            cp16(st + kvso + i * 16,               pKh + g + i * 8);
            cp16(st + AT_TILE + kvso + i * 16,     pKl + g + i * 8);
            cp16(st + 2 * AT_TILE + kvso + i * 16, pVh + g + i * 8);
        }
    };

    load_stage(0, 0);
    CP_COMMIT();
    load_stage(1, 1);
    CP_COMMIT();

    const uint32_t q_off = (uint32_t)((warp * 16 + (lane & 15)) * AT_LDB + ((lane >> 4) << 4));
    const uint32_t k4_off = (uint32_t)((((lane >> 4) << 3) + (lane & 7)) * AT_LDB
                                       + ((lane & 8) ? 16 : 0));
    const uint32_t v4_off = (uint32_t)((((lane >> 3) & 1) * 8 + (lane & 7)) * AT_LDB
                                       + (lane >> 4) * 16);

    const float* biasR0 = Bias + ((size_t)bh * PS + q0 + warp * 16 + (lane >> 2)) * PS;
    const float* biasR1 = biasR0 + 8 * PS;
    const int bcol = (lane & 3) * 2;

    float o[16][4];
#pragma unroll
    for (int nd = 0; nd < 16; nd++)
#pragma unroll
        for (int j = 0; j < 4; j++) o[nd][j] = 0.0f;
    float lacc[4] = {0.0f, 0.0f, 0.0f, 0.0f};
    float m0 = -1e30f, m1 = -1e30f;
    const uint32_t ONESB[2] = {0x3C003C00u, 0x3C003C00u};

    // bias prefetch registers
    float2 nb0[8], nb1[8];
#pragma unroll
    for (int nf = 0; nf < 8; nf++) {
        nb0[nf] = *(const float2*)(biasR0 + nf * 8 + bcol);
        nb1[nf] = *(const float2*)(biasR1 + nf * 8 + bcol);
    }

    const int NT = PS / 64;   // 32
    for (int t = 0; t < NT; t++) {
        if (t < NT - 1) { CP_WAIT(1); } else { CP_WAIT(0); }
        __syncthreads();

        const uint32_t st = sb + AT_ST0 + (t % 3) * AT_STAGE;

        // consume prefetched bias, then prefetch next tile's bias
        float sc[8][4];
#pragma unroll
        for (int nf = 0; nf < 8; nf++) {
            sc[nf][0] = nb0[nf].x; sc[nf][1] = nb0[nf].y;
            sc[nf][2] = nb1[nf].x; sc[nf][3] = nb1[nf].y;
        }
        if (t + 1 < NT) {
            const int k1 = (t + 1) * 64;
#pragma unroll
            for (int nf = 0; nf < 8; nf++) {
                nb0[nf] = *(const float2*)(biasR0 + k1 + nf * 8 + bcol);
                nb1[nf] = *(const float2*)(biasR1 + k1 + nf * 8 + bcol);
            }
        }

        // ---- scores += Q K^T (split 3-combo), K via x4 pairs ----
#pragma unroll
        for (int ks = 0; ks < 8; ks++) {
            uint32_t qa[4], qla[4];
            ldm_x4(qa,  sb + AT_QH + q_off + ks * 32);
            ldm_x4(qla, sb + AT_QL + q_off + ks * 32);
#pragma unroll
            for (int nf2 = 0; nf2 < 4; nf2++) {
                uint32_t kbh[4], kbl[4];
                ldm_x4(kbh, st + k4_off + nf2 * 16 * AT_LDB + ks * 32);
                ldm_x4(kbl, st + AT_TILE + k4_off + nf2 * 16 * AT_LDB + ks * 32);
                mma_bf16(sc[2*nf2],   qa,  kbh);
                mma_bf16(sc[2*nf2+1], qa,  kbh + 2);
                mma_bf16(sc[2*nf2],   qa,  kbl);
                mma_bf16(sc[2*nf2+1], qa,  kbl + 2);
                mma_bf16(sc[2*nf2],   qla, kbh);
                mma_bf16(sc[2*nf2+1], qla, kbh + 2);
            }
        }

        // ---- online softmax: max ----
        float mx0 = sc[0][0], mx1 = sc[0][2];
#pragma unroll
        for (int nf = 0; nf < 8; nf++) {
            mx0 = fmaxf(mx0, fmaxf(sc[nf][0], sc[nf][1]));
            mx1 = fmaxf(mx1, fmaxf(sc[nf][2], sc[nf][3]));
        }
        mx0 = fmaxf(mx0, __shfl_xor_sync(0xffffffffu, mx0, 1));
        mx0 = fmaxf(mx0, __shfl_xor_sync(0xffffffffu, mx0, 2));
        mx1 = fmaxf(mx1, __shfl_xor_sync(0xffffffffu, mx1, 1));
        mx1 = fmaxf(mx1, __shfl_xor_sync(0xffffffffu, mx1, 2));
        const float mn0 = fmaxf(m0, mx0), mn1 = fmaxf(m1, mx1);
        const float mL0 = mn0 * L2E, mL1 = mn1 * L2E;
        const float al0 = ex2f((m0 - mn0) * L2E);
        const float al1 = ex2f((m1 - mn1) * L2E);
        m0 = mn0; m1 = mn1;

        // ---- rescale o and l accumulators (skip when max unchanged) ----
        if (al0 != 1.0f || al1 != 1.0f) {
#pragma unroll
            for (int nd = 0; nd < 16; nd++) {
                o[nd][0] *= al0; o[nd][1] *= al0;
                o[nd][2] *= al1; o[nd][3] *= al1;
            }
            lacc[0] *= al0; lacc[1] *= al0;
            lacc[2] *= al1; lacc[3] *= al1;
        }

        // ---- P fragments directly via f16x2 exp ----
        uint32_t pf[4][4];
#pragma unroll
        for (int j2 = 0; j2 < 4; j2++) {
            const int f0 = 2 * j2, f1 = f0 + 1;
            pf[j2][0] = h2ex2(fmaf(sc[f0][0], L2E, -mL0), fmaf(sc[f0][1], L2E, -mL0));
            pf[j2][1] = h2ex2(fmaf(sc[f0][2], L2E, -mL1), fmaf(sc[f0][3], L2E, -mL1));
            pf[j2][2] = h2ex2(fmaf(sc[f1][0], L2E, -mL0), fmaf(sc[f1][1], L2E, -mL0));
            pf[j2][3] = h2ex2(fmaf(sc[f1][2], L2E, -mL1), fmaf(sc[f1][3], L2E, -mL1));
        }

        // ---- O += P V; l += P 1 (ones-MMA); V via x4.trans pairs ----
#pragma unroll
        for (int j2 = 0; j2 < 4; j2++) {
            mma_f16(lacc, pf[j2], ONESB);
            const uint32_t vrow = st + 2 * AT_TILE + v4_off + j2 * 16 * AT_LDB;
#pragma unroll
            for (int nd2 = 0; nd2 < 8; nd2++) {
                uint32_t vbh[4];
                ldm_x4t(vbh, vrow + nd2 * 32);
                mma_f16(o[2*nd2],   pf[j2], vbh);
                mma_f16(o[2*nd2+1], pf[j2], vbh + 2);
            }
        }

        if (t + 2 < NT) {
            load_stage((t + 2) % 3, t + 2);
            CP_COMMIT();
        }
    }

    // ---- epilogue: normalize, split fp16, store ctx ----
    const float inv0 = 1.0f / lacc[0], inv1 = 1.0f / lacc[2];
    const int rg0 = q0 + warp * 16 + (lane >> 2);
    __half* och = Ch + base;
    __half* ocl = Cl + base;
#pragma unroll
    for (int nd = 0; nd < 16; nd++) {
        const int col = nd * 8 + (lane & 3) * 2;
        uint32_t hp, lp;
        packsplit_f16(o[nd][0] * inv0, o[nd][1] * inv0, hp, lp);
        *(uint32_t*)(och + (size_t)rg0 * PHID + col) = hp;
        *(uint32_t*)(ocl + (size_t)rg0 * PHID + col) = lp;
        packsplit_f16(o[nd][2] * inv1, o[nd][3] * inv1, hp, lp);
        *(uint32_t*)(och + (size_t)(rg0 + 8) * PHID + col) = hp;
        *(uint32_t*)(ocl + (size_t)(rg0 + 8) * PHID + col) = lp;
    }
}

// ---------------------------------------------------------------------------
extern "C" void kernel_launch(void* const* d_in, const int* in_sizes, int n_in,
                              void* d_out, int out_size)
{
    (void)in_sizes; (void)n_in; (void)out_size;
    const float* x    = (const float*)d_in[0];
    const float* bias = (const float*)d_in[1];
    const float* Wq   = (const float*)d_in[2];
    const float* bq   = (const float*)d_in[3];
    const float* Wk   = (const float*)d_in[4];
    const float* bk   = (const float*)d_in[5];
    const float* Wv   = (const float*)d_in[6];
    const float* bv   = (const float*)d_in[7];
    const float* Wo   = (const float*)d_in[8];
    const float* bo   = (const float*)d_in[9];
    float* out = (float*)d_out;

    __nv_bfloat16 *xh, *xl, *qh, *ql, *kh, *kl;
    __half *xh2, *xl2, *vhf, *ch2, *cl2, *wvt, *wot;
    __nv_bfloat16 *wqh, *wql, *wkh, *wkl;
    cudaGetSymbolAddress((void**)&xh, g_xh);
    cudaGetSymbolAddress((void**)&xl, g_xl);
    cudaGetSymbolAddress((void**)&xh2, g_xh2);
    cudaGetSymbolAddress((void**)&xl2, g_xl2);
    cudaGetSymbolAddress((void**)&qh, g_qh);
    cudaGetSymbolAddress((void**)&ql, g_ql);
    cudaGetSymbolAddress((void**)&kh, g_kh);
    cudaGetSymbolAddress((void**)&kl, g_kl);
    cudaGetSymbolAddress((void**)&vhf, g_vhf);
    cudaGetSymbolAddress((void**)&ch2, g_ch2);
    cudaGetSymbolAddress((void**)&cl2, g_cl2);
    cudaGetSymbolAddress((void**)&wqh, g_wqh);
    cudaGetSymbolAddress((void**)&wql, g_wql);
    cudaGetSymbolAddress((void**)&wkh, g_wkh);
    cudaGetSymbolAddress((void**)&wkl, g_wkl);
    cudaGetSymbolAddress((void**)&wvt, g_wvt);
    cudaGetSymbolAddress((void**)&wot, g_wot);

    static bool attr_set = false;
    if (!attr_set) {
        cudaFuncSetAttribute(gemm_qk,
                             cudaFuncAttributeMaxDynamicSharedMemorySize, QK_SMEM);
        cudaFuncSetAttribute(gemm_f16_2c,
                             cudaFuncAttributeMaxDynamicSharedMemorySize, GSMEM2);
        cudaFuncSetAttribute(attn_mma,
                             cudaFuncAttributeMaxDynamicSharedMemorySize, AT_SMEM);
        attr_set = true;
    }

    // 1) conversions
    {
        int n4 = PM * PHID / 4;
        split_x_kernel<<<(n4 + 255) / 256, 256>>>(x, xh, xl, xh2, xl2, n4);
        dim3 tg(PHID / 32, PHID / 32, 4);
        dim3 tb(32, 8);
        transpose_all_kernel<<<tg, tb>>>(Wq, Wk, Wv, Wo,
                                         wqh, wql, wkh, wkl, wvt, wot);
    }

    // 2) projections
    dim3 qkgrid(2 * PHID / 128, PM / 128);    // (32, 32)
    gemm_qk<<<qkgrid, 256, QK_SMEM>>>(xh, xl, wqh, wql, wkh, wkl,
                                      bq, bk, qh, ql, kh, kl);
    dim3 vgrid(PHID / 128, PM / 128);         // (16, 32)
    gemm_f16_2c<<<vgrid, 256, GSMEM2>>>(xh2, xl2, wvt, bv, nullptr, vhf);

    // 3) tensor-core attention -> split fp16 ctx
    dim3 agrid(PS / 128, PB * PH);            // (16, 32)
    attn_mma<<<agrid, 256, AT_SMEM>>>(qh, ql, kh, kl, vhf, bias, ch2, cl2);

    // 4) output projection -> fp32 out
    gemm_f16_2c<<<vgrid, 256, GSMEM2>>>(ch2, cl2, wot, bo, out, nullptr);
}

// round 13
// speedup vs baseline: 4.2139x; 1.0021x over previous
#include <cuda_runtime.h>
#include <cuda_bf16.h>
#include <cuda_fp16.h>
#include <math.h>
#include <stdint.h>

// Problem constants
#define PB   2
#define PS   2048
#define PHID 2048
#define PH   16
#define PD   128
#define PM   (PB * PS)          // 4096 rows
#define QSCALE 11.313708498984760f   // sqrt(128)

// ---------------------------------------------------------------------------
// Scratch (no cudaMalloc allowed)
// ---------------------------------------------------------------------------
__device__ __nv_bfloat16 g_xh[(size_t)PM * PHID];    // x split bf16 (QK path)
__device__ __nv_bfloat16 g_xl[(size_t)PM * PHID];
__device__ __half        g_xh2[(size_t)PM * PHID];   // x split fp16 (V path)
__device__ __half        g_xl2[(size_t)PM * PHID];
__device__ __nv_bfloat16 g_qh[(size_t)PM * PHID];
__device__ __nv_bfloat16 g_ql[(size_t)PM * PHID];
__device__ __nv_bfloat16 g_kh[(size_t)PM * PHID];
__device__ __nv_bfloat16 g_kl[(size_t)PM * PHID];
__device__ __half        g_vhf[(size_t)PM * PHID];   // V, fp16
__device__ __half        g_ch2[(size_t)PM * PHID];   // ctx split fp16
__device__ __half        g_cl2[(size_t)PM * PHID];

// transposed weights [N,K]
__device__ __nv_bfloat16 g_wqh[(size_t)PHID * PHID];
__device__ __nv_bfloat16 g_wql[(size_t)PHID * PHID];
__device__ __nv_bfloat16 g_wkh[(size_t)PHID * PHID];
__device__ __nv_bfloat16 g_wkl[(size_t)PHID * PHID];
__device__ __half        g_wvt[(size_t)PHID * PHID]; // Wv^T single fp16
__device__ __half        g_wot[(size_t)PHID * PHID]; // Wo^T single fp16

// ---------------------------------------------------------------------------
// Helpers
// ---------------------------------------------------------------------------
__device__ __forceinline__ uint32_t smem_u32(const void* p) {
    uint32_t a;
    asm("{ .reg .u64 t; cvta.to.shared.u64 t, %1; cvt.u32.u64 %0, t; }"
        : "=r"(a) : "l"(p));
    return a;
}

__device__ __forceinline__ void cp16(uint32_t s, const void* g) {
    asm volatile("cp.async.cg.shared.global [%0], [%1], 16;" :: "r"(s), "l"(g));
}
#define CP_COMMIT() asm volatile("cp.async.commit_group;" ::: "memory")
#define CP_WAIT(n)  asm volatile("cp.async.wait_group %0;" :: "n"(n) : "memory")

__device__ __forceinline__ void ldm_x4(uint32_t* r, uint32_t addr) {
    asm volatile("ldmatrix.sync.aligned.m8n8.x4.shared.b16 {%0,%1,%2,%3}, [%4];"
                 : "=r"(r[0]), "=r"(r[1]), "=r"(r[2]), "=r"(r[3]) : "r"(addr));
}
__device__ __forceinline__ void ldm_x4t(uint32_t* r, uint32_t addr) {
    asm volatile("ldmatrix.sync.aligned.m8n8.x4.trans.shared.b16 {%0,%1,%2,%3}, [%4];"
                 : "=r"(r[0]), "=r"(r[1]), "=r"(r[2]), "=r"(r[3]) : "r"(addr));
}
__device__ __forceinline__ void mma_bf16(float* c, const uint32_t* a, const uint32_t* b) {
    asm volatile(
        "mma.sync.aligned.m16n8k16.row.col.f32.bf16.bf16.f32 "
        "{%0,%1,%2,%3}, {%4,%5,%6,%7}, {%8,%9}, {%0,%1,%2,%3};"
        : "+f"(c[0]), "+f"(c[1]), "+f"(c[2]), "+f"(c[3])
        : "r"(a[0]), "r"(a[1]), "r"(a[2]), "r"(a[3]), "r"(b[0]), "r"(b[1]));
}
__device__ __forceinline__ void mma_f16(float* c, const uint32_t* a, const uint32_t* b) {
    asm volatile(
        "mma.sync.aligned.m16n8k16.row.col.f32.f16.f16.f32 "
        "{%0,%1,%2,%3}, {%4,%5,%6,%7}, {%8,%9}, {%0,%1,%2,%3};"
        : "+f"(c[0]), "+f"(c[1]), "+f"(c[2]), "+f"(c[3])
        : "r"(a[0]), "r"(a[1]), "r"(a[2]), "r"(a[3]), "r"(b[0]), "r"(b[1]));
}

__device__ __forceinline__ float ex2f(float x) {
    float r;
    asm("ex2.approx.f32 %0, %1;" : "=f"(r) : "f"(x));
    return r;
}

// pack two fp32 exponent args into f16x2 and take 2^x on both at once
__device__ __forceinline__ uint32_t h2ex2(float y0, float y1) {
    uint32_t h, p;
    asm("cvt.rn.f16x2.f32 %0, %1, %2;" : "=r"(h) : "f"(y1), "f"(y0));
    asm("ex2.approx.f16x2 %0, %1;" : "=r"(p) : "r"(h));
    return p;
}

// Fast RNE split of two floats into (hi bf16x2, lo bf16x2).
__device__ __forceinline__ void packsplit(float a, float b, uint32_t& hp, uint32_t& lp) {
    asm("cvt.rn.bf16x2.f32 %0, %1, %2;" : "=r"(hp) : "f"(b), "f"(a));
    float ah = __uint_as_float(hp << 16);
    float bh = __uint_as_float(hp & 0xFFFF0000u);
    float la = a - ah;
    float lb = b - bh;
    asm("cvt.rn.bf16x2.f32 %0, %1, %2;" : "=r"(lp) : "f"(lb), "f"(la));
}

// RNE split of two floats into (hi f16x2, lo f16x2).
__device__ __forceinline__ void packsplit_f16(float a, float b, uint32_t& hp, uint32_t& lp) {
    __half2 h = __floats2half2_rn(a, b);
    float la = a - __half2float(__low2half(h));
    float lb = b - __half2float(__high2half(h));
    __half2 l = __floats2half2_rn(la, lb);
    hp = *reinterpret_cast<uint32_t*>(&h);
    lp = *reinterpret_cast<uint32_t*>(&l);
}

// ---------------------------------------------------------------------------
// Conversion kernels
// ---------------------------------------------------------------------------
__global__ void split_x_kernel(const float* __restrict__ in,
                               __nv_bfloat16* __restrict__ hb,
                               __nv_bfloat16* __restrict__ lb,
                               __half* __restrict__ hf,
                               __half* __restrict__ lf, int n4)
{
    int i = blockIdx.x * blockDim.x + threadIdx.x;
    if (i >= n4) return;
    float4 v = ((const float4*)in)[i];
    uint32_t h0, l0, h1, l1;
    packsplit(v.x, v.y, h0, l0);
    packsplit(v.z, v.w, h1, l1);
    ((uint32_t*)hb)[2*i]   = h0;
    ((uint32_t*)hb)[2*i+1] = h1;
    ((uint32_t*)lb)[2*i]   = l0;
    ((uint32_t*)lb)[2*i+1] = l1;
    packsplit_f16(v.x, v.y, h0, l0);
    packsplit_f16(v.z, v.w, h1, l1);
    ((uint32_t*)hf)[2*i]   = h0;
    ((uint32_t*)hf)[2*i+1] = h1;
    ((uint32_t*)lf)[2*i]   = l0;
    ((uint32_t*)lf)[2*i+1] = l1;
}

// One launch transposes all 4 weight matrices.  z=0,1 -> bf16 split (Wq, Wk);
// z=2,3 -> single fp16 (Wv, Wo).
__global__ void transpose_all_kernel(
    const float* __restrict__ Wq, const float* __restrict__ Wk,
    const float* __restrict__ Wv, const float* __restrict__ Wo,
    __nv_bfloat16* __restrict__ Tqh, __nv_bfloat16* __restrict__ Tql,
    __nv_bfloat16* __restrict__ Tkh, __nv_bfloat16* __restrict__ Tkl,
    __half* __restrict__ Tv, __half* __restrict__ To)
{
    __shared__ float t[32][33];
    int z = blockIdx.z;
    const float* W = (z == 0) ? Wq : (z == 1) ? Wk : (z == 2) ? Wv : Wo;
    int n0 = blockIdx.x * 32, k0 = blockIdx.y * 32;
    int tx = threadIdx.x, ty0 = threadIdx.y;   // 32 x 8
#pragma unroll
    for (int j = 0; j < 32; j += 8)
        t[ty0 + j][tx] = W[(size_t)(k0 + ty0 + j) * PHID + n0 + tx];
    __syncthreads();
#pragma unroll
    for (int j = 0; j < 32; j += 8) {
        int n = ty0 + j;
        float v = t[tx][n];
        size_t o = (size_t)(n0 + n) * PHID + k0 + tx;
        if (z < 2) {
            __nv_bfloat16 h = __float2bfloat16(v);
            __nv_bfloat16 l = __float2bfloat16(v - __bfloat162float(h));
            if (z == 0) { Tqh[o] = h; Tql[o] = l; }
            else        { Tkh[o] = h; Tkl[o] = l; }
        } else {
            __half h = __float2half_rn(v);
            if (z == 2) Tv[o] = h; else To[o] = h;
        }
    }
}

// ---------------------------------------------------------------------------
// GEMM tile configs
// ---------------------------------------------------------------------------
#define LDT   40
#define TILE_B (128 * LDT * 2)   // 10240
#define OFF_AH 0
#define OFF_AL (TILE_B)
#define OFF_BH (2 * TILE_B)
#define OFF_BL (3 * TILE_B)

#define STAGE2_B (3 * TILE_B)    // 30720 (fp16 2-combo: Ah, Al, B)
#define GSMEM2 (3 * STAGE2_B)    // 92160 (3-stage pipeline)

// gemm_qk 4-stage BK=16 ring: tile = 128 rows x 48B (16 bf16 + 8 pad)
#define QK_TILE  6144
#define QK_AH    0
#define QK_AL    (QK_TILE)
#define QK_BH    (2 * QK_TILE)
#define QK_BL    (3 * QK_TILE)
#define QK_STAGE (4 * QK_TILE)   // 24576
#define QK_SMEM  (4 * QK_STAGE)  // 98304

// ---------------------------------------------------------------------------
// Q/K projection GEMM (split-bf16, 3 combos): sel = blockIdx.x>>4 in {0,1}.
// 4-stage BK=16 ring, ONE __syncthreads per chunk, 3-chunk prefetch.
// ---------------------------------------------------------------------------
__global__ __launch_bounds__(256, 2) void gemm_qk(
    const __nv_bfloat16* __restrict__ Ah, const __nv_bfloat16* __restrict__ Al,
    const __nv_bfloat16* __restrict__ Wqh, const __nv_bfloat16* __restrict__ Wql,
    const __nv_bfloat16* __restrict__ Wkh, const __nv_bfloat16* __restrict__ Wkl,
    const float* __restrict__ bq, const float* __restrict__ bk,
    __nv_bfloat16* __restrict__ Qh, __nv_bfloat16* __restrict__ Ql,
    __nv_bfloat16* __restrict__ Kh, __nv_bfloat16* __restrict__ Kl)
{
    extern __shared__ char smem[];
    const uint32_t sb = smem_u32(smem);
    const int tid  = threadIdx.x;
    const int lane = tid & 31;
    const int warp = tid >> 5;
    const int wm = warp >> 2;
    const int wn = warp & 3;
    const int sel = blockIdx.x >> 4;            // 0=Q 1=K
    const int n0  = (blockIdx.x & 15) * 128;
    const int m0  = blockIdx.y * 128;

    const __nv_bfloat16* Bh = sel ? Wkh : Wqh;
    const __nv_bfloat16* Bl = sel ? Wkl : Wql;
    const float* bias = sel ? bk : bq;
    const float scale = sel ? 1.0f : QSCALE;

    const __nv_bfloat16* pAh = Ah + (size_t)m0 * PHID;
    const __nv_bfloat16* pAl = Al + (size_t)m0 * PHID;
    const __nv_bfloat16* pBh = Bh + (size_t)n0 * PHID;
    const __nv_bfloat16* pBl = Bl + (size_t)n0 * PHID;

    // loader: 256 threads, one 16B chunk per tile each
    const int r0 = tid >> 1;               // 0..127
    const int ce = (tid & 1) * 8;          // elem col within 16
    const uint32_t so = (uint32_t)(r0 * 48 + (tid & 1) * 16);

    const uint32_t a_off = (uint32_t)((wm * 64 + (lane & 15)) * 48 + ((lane >> 4) << 4));
    const uint32_t b4_off = (uint32_t)((wn * 32 + ((lane >> 4) << 3) + (lane & 7)) * 48
                                       + ((lane & 8) ? 16 : 0));

    float acc[4][4][4];
#pragma unroll
    for (int mi = 0; mi < 4; mi++)
#pragma unroll
        for (int ni = 0; ni < 4; ni++)
#pragma unroll
            for (int j = 0; j < 4; j++) acc[mi][ni][j] = 0.0f;

    auto load_stage = [&](int stage, int kc) {
        const uint32_t st = sb + stage * QK_STAGE;
        const size_t g = (size_t)r0 * PHID + kc * 16 + ce;
        cp16(st + QK_AH + so, pAh + g);
        cp16(st + QK_AL + so, pAl + g);
        cp16(st + QK_BH + so, pBh + g);
        cp16(st + QK_BL + so, pBl + g);
    };

    auto compute_stage = [&](int stage) {
        const uint32_t st = sb + stage * QK_STAGE;
        uint32_t bh0[4], bh1[4], bl0[4], bl1[4], a[4][4];
        ldm_x4(bh0, st + QK_BH + b4_off);
        ldm_x4(bh1, st + QK_BH + b4_off + 768);
        ldm_x4(bl0, st + QK_BL + b4_off);
        ldm_x4(bl1, st + QK_BL + b4_off + 768);
#pragma unroll
        for (int mi = 0; mi < 4; mi++)
            ldm_x4(a[mi], st + QK_AH + a_off + mi * 768);
#pragma unroll
        for (int mi = 0; mi < 4; mi++) {
            mma_bf16(acc[mi][0], a[mi], bh0);
            mma_bf16(acc[mi][1], a[mi], bh0 + 2);
            mma_bf16(acc[mi][2], a[mi], bh1);
            mma_bf16(acc[mi][3], a[mi], bh1 + 2);
        }
#pragma unroll
        for (int mi = 0; mi < 4; mi++) {
            mma_bf16(acc[mi][0], a[mi], bl0);
            mma_bf16(acc[mi][1], a[mi], bl0 + 2);
            mma_bf16(acc[mi][2], a[mi], bl1);
            mma_bf16(acc[mi][3], a[mi], bl1 + 2);
        }
#pragma unroll
        for (int mi = 0; mi < 4; mi++)
            ldm_x4(a[mi], st + QK_AL + a_off + mi * 768);
#pragma unroll
        for (int mi = 0; mi < 4; mi++) {
            mma_bf16(acc[mi][0], a[mi], bh0);
            mma_bf16(acc[mi][1], a[mi], bh0 + 2);
            mma_bf16(acc[mi][2], a[mi], bh1);
            mma_bf16(acc[mi][3], a[mi], bh1 + 2);
        }
    };

    load_stage(0, 0);
    CP_COMMIT();
    load_stage(1, 1);
    CP_COMMIT();
    load_stage(2, 2);
    CP_COMMIT();
    const int NKC = PHID / 16;   // 128
    for (int kc = 0; kc < NKC; kc++) {
        if (kc < NKC - 2)      { CP_WAIT(2); }
        else if (kc == NKC - 2){ CP_WAIT(1); }
        else                   { CP_WAIT(0); }
        __syncthreads();
        compute_stage(kc & 3);
        if (kc + 3 < NKC) {
            load_stage((kc + 3) & 3, kc + 3);
            CP_COMMIT();
        }
    }

    __nv_bfloat16* Oh = sel ? Kh : Qh;
    __nv_bfloat16* Ol = sel ? Kl : Ql;
#pragma unroll
    for (int mi = 0; mi < 4; mi++) {
        const int row = m0 + wm * 64 + mi * 16 + (lane >> 2);
#pragma unroll
        for (int ni = 0; ni < 4; ni++) {
            const int col = n0 + wn * 32 + ni * 8 + (lane & 3) * 2;
            const float b0 = bias[col], b1 = bias[col + 1];
            float v00 = (acc[mi][ni][0] + b0) * scale;
            float v01 = (acc[mi][ni][1] + b1) * scale;
            float v10 = (acc[mi][ni][2] + b0) * scale;
            float v11 = (acc[mi][ni][3] + b1) * scale;
            uint32_t hp, lp;
            packsplit(v00, v01, hp, lp);
            *(uint32_t*)(Oh + (size_t)row * PHID + col) = hp;
            *(uint32_t*)(Ol + (size_t)row * PHID + col) = lp;
            packsplit(v10, v11, hp, lp);
            *(uint32_t*)(Oh + (size_t)(row + 8) * PHID + col) = hp;
            *(uint32_t*)(Ol + (size_t)(row + 8) * PHID + col) = lp;
        }
    }
}

// ---------------------------------------------------------------------------
// fp16 2-combo GEMM: C = (Ah + Al) @ B^T + bias.  3-stage pipeline,
// ONE __syncthreads per K-chunk.
// ---------------------------------------------------------------------------
__global__ __launch_bounds__(256, 2) void gemm_f16_2c(
    const __half* __restrict__ Ah, const __half* __restrict__ Al,
    const __half* __restrict__ Bt,
    const float* __restrict__ bias, float* __restrict__ Cf,
    __half* __restrict__ Co)
{
    extern __shared__ char smem[];
    const uint32_t sb = smem_u32(smem);
    const int tid  = threadIdx.x;
    const int lane = tid & 31;
    const int warp = tid >> 5;
    const int wm = warp >> 2;
    const int wn = warp & 3;
    const int m0 = blockIdx.y * 128;
    const int n0 = blockIdx.x * 128;

    const __half* pAh = Ah + (size_t)m0 * PHID;
    const __half* pAl = Al + (size_t)m0 * PHID;
    const __half* pB  = Bt + (size_t)n0 * PHID;

    const int r0 = tid >> 2;
    const int c0 = (tid & 3) * 8;
    const uint32_t so0 = (uint32_t)(r0 * 80 + (tid & 3) * 16);
    const uint32_t so1 = (uint32_t)((r0 + 64) * 80 + (tid & 3) * 16);

    const uint32_t a_off = (uint32_t)((wm * 64 + (lane & 15)) * 80 + ((lane >> 4) << 4));
    const uint32_t b4_off = (uint32_t)((wn * 32 + ((lane >> 4) << 3) + (lane & 7)) * 80
                                       + ((lane & 8) ? 16 : 0));

    float acc[4][4][4];
#pragma unroll
    for (int mi = 0; mi < 4; mi++)
#pragma unroll
        for (int ni = 0; ni < 4; ni++)
#pragma unroll
            for (int j = 0; j < 4; j++) acc[mi][ni][j] = 0.0f;

    auto load_stage = [&](int stage, int kc) {
        const uint32_t st = sb + stage * STAGE2_B;
        const size_t g0 = (size_t)r0 * PHID + kc * 32 + c0;
        const size_t g1 = (size_t)(r0 + 64) * PHID + kc * 32 + c0;
        cp16(st + OFF_AH + so0, pAh + g0);
        cp16(st + OFF_AH + so1, pAh + g1);
        cp16(st + OFF_AL + so0, pAl + g0);
        cp16(st + OFF_AL + so1, pAl + g1);
        cp16(st + OFF_BH + so0, pB + g0);
        cp16(st + OFF_BH + so1, pB + g1);
    };

    auto compute_stage = [&](int stage) {
        const uint32_t st = sb + stage * STAGE2_B;
#pragma unroll
        for (int ks = 0; ks < 2; ks++) {
            const uint32_t k32 = ks * 32;
            uint32_t bf[4][2], a[4][4];
            ldm_x4(&bf[0][0], st + OFF_BH + b4_off + k32);
            ldm_x4(&bf[2][0], st + OFF_BH + b4_off + 1280 + k32);
#pragma unroll
            for (int mi = 0; mi < 4; mi++)
                ldm_x4(a[mi], st + OFF_AH + a_off + mi * 1280 + k32);
#pragma unroll
            for (int mi = 0; mi < 4; mi++)
#pragma unroll
                for (int ni = 0; ni < 4; ni++)
                    mma_f16(acc[mi][ni], a[mi], bf[ni]);
#pragma unroll
            for (int mi = 0; mi < 4; mi++)
                ldm_x4(a[mi], st + OFF_AL + a_off + mi * 1280 + k32);
#pragma unroll
            for (int mi = 0; mi < 4; mi++)
#pragma unroll
                for (int ni = 0; ni < 4; ni++)
                    mma_f16(acc[mi][ni], a[mi], bf[ni]);
        }
    };

    load_stage(0, 0);
    CP_COMMIT();
    load_stage(1, 1);
    CP_COMMIT();
    const int NKC = PHID / 32;   // 64
    for (int kc = 0; kc < NKC; kc++) {
        if (kc < NKC - 1) { CP_WAIT(1); } else { CP_WAIT(0); }
        __syncthreads();
        compute_stage(kc % 3);
        if (kc + 2 < NKC) {
            load_stage((kc + 2) % 3, kc + 2);
            CP_COMMIT();
        }
    }

#pragma unroll
    for (int mi = 0; mi < 4; mi++) {
        const int row = m0 + wm * 64 + mi * 16 + (lane >> 2);
#pragma unroll
        for (int ni = 0; ni < 4; ni++) {
            const int col = n0 + wn * 32 + ni * 8 + (lane & 3) * 2;
            const float b0 = bias[col], b1 = bias[col + 1];
            float v00 = acc[mi][ni][0] + b0;
            float v01 = acc[mi][ni][1] + b1;
            float v10 = acc[mi][ni][2] + b0;
            float v11 = acc[mi][ni][3] + b1;
            if (Cf) {
                *(float2*)(Cf + (size_t)row * PHID + col)       = make_float2(v00, v01);
                *(float2*)(Cf + (size_t)(row + 8) * PHID + col) = make_float2(v10, v11);
            } else {
                __half2 p0 = __floats2half2_rn(v00, v01);
                __half2 p1 = __floats2half2_rn(v10, v11);
                *(uint32_t*)(Co + (size_t)row * PHID + col) =
                    *reinterpret_cast<uint32_t*>(&p0);
                *(uint32_t*)(Co + (size_t)(row + 8) * PHID + col) =
                    *reinterpret_cast<uint32_t*>(&p1);
            }
        }
    }
}

// ---------------------------------------------------------------------------
// Tensor-core flash attention: QK split-bf16 (3 combos), PV fp16 (1 combo),
// P exp/pack interleaved INTO the PV MMA loop (scalar/tensor pipe overlap),
// row sums via ones-MMA.  ctx out: split fp16.  3 K/V stages, 1 barrier/tile.
// ---------------------------------------------------------------------------
#define AT_LDB  272
#define AT_QH   0
#define AT_QL   (128 * AT_LDB)            // 34816
#define AT_ST0  (2 * 128 * AT_LDB)        // 69632
#define AT_TILE (64 * AT_LDB)             // 17408
#define AT_STAGE (3 * AT_TILE)            // 52224
#define AT_SMEM (AT_ST0 + 3 * AT_STAGE)   // 226304

__global__ __launch_bounds__(256, 1) void attn_mma(
    const __nv_bfloat16* __restrict__ Qh, const __nv_bfloat16* __restrict__ Ql,
    const __nv_bfloat16* __restrict__ Kh, const __nv_bfloat16* __restrict__ Kl,
    const __half* __restrict__ Vh,
    const float* __restrict__ Bias,
    __half* __restrict__ Ch, __half* __restrict__ Cl)
{
    extern __shared__ char smem[];
    const uint32_t sb = smem_u32(smem);
    const int tid = threadIdx.x;
    const int lane = tid & 31;
    const int warp = tid >> 5;
    const int bh = blockIdx.y;
    const int b  = bh >> 4;
    const int h  = bh & 15;
    const int q0 = blockIdx.x * 128;
    const float L2E = 1.44269504f;

    const size_t base = (size_t)b * PS * PHID + (size_t)h * PD;
    const __nv_bfloat16* pQh = Qh + base + (size_t)q0 * PHID;
    const __nv_bfloat16* pQl = Ql + base + (size_t)q0 * PHID;
    const __nv_bfloat16* pKh = Kh + base;
    const __nv_bfloat16* pKl = Kl + base;
    const __half* pVh = Vh + base;

    // Q loader
    {
        const int r = tid >> 1;
        const int ce = (tid & 1) * 64;
        const uint32_t so = (uint32_t)(r * AT_LDB + (tid & 1) * 128);
#pragma unroll
        for (int i = 0; i < 8; i++) {
            cp16(sb + AT_QH + so + i * 16, pQh + (size_t)r * PHID + ce + i * 8);
            cp16(sb + AT_QL + so + i * 16, pQl + (size_t)r * PHID + ce + i * 8);
        }
    }

    // K/V stage loader (3 tiles: Kh, Kl, Vh)
    const int kvr  = tid >> 2;
    const int kvce = (tid & 3) * 32;
    const uint32_t kvso = (uint32_t)(kvr * AT_LDB + (tid & 3) * 64);
    auto load_stage = [&](int stage, int t) {
        const uint32_t st = sb + AT_ST0 + stage * AT_STAGE;
        const size_t g = (size_t)(t * 64 + kvr) * PHID + kvce;
#pragma unroll
        for (int i = 0; i < 4; i++) {
            cp16(st + kvso + i * 16,               pKh + g + i * 8);
            cp16(st + AT_TILE + kvso + i * 16,     pKl + g + i * 8);
            cp16(st + 2 * AT_TILE + kvso + i * 16, pVh + g + i * 8);
        }
    };

    load_stage(0, 0);
    CP_COMMIT();
    load_stage(1, 1);
    CP_COMMIT();

    const uint32_t q_off = (uint32_t)((warp * 16 + (lane & 15)) * AT_LDB + ((lane >> 4) << 4));
    const uint32_t k4_off = (uint32_t)((((lane >> 4) << 3) + (lane & 7)) * AT_LDB
                                       + ((lane & 8) ? 16 : 0));
    const uint32_t v4_off = (uint32_t)((((lane >> 3) & 1) * 8 + (lane & 7)) * AT_LDB
                                       + (lane >> 4) * 16);

    const float* biasR0 = Bias + ((size_t)bh * PS + q0 + warp * 16 + (lane >> 2)) * PS;
    const float* biasR1 = biasR0 + 8 * PS;
    const int bcol = (lane & 3) * 2;

    float o[16][4];
#pragma unroll
    for (int nd = 0; nd < 16; nd++)
#pragma unroll
        for (int j = 0; j < 4; j++) o[nd][j] = 0.0f;
    float lacc[4] = {0.0f, 0.0f, 0.0f, 0.0f};
    float m0 = -1e30f, m1 = -1e30f;
    const uint32_t ONESB[2] = {0x3C003C00u, 0x3C003C00u};

    // bias prefetch registers
    float2 nb0[8], nb1[8];
#pragma unroll
    for (int nf = 0; nf < 8; nf++) {
        nb0[nf] = *(const float2*)(biasR0 + nf * 8 + bcol);
        nb1[nf] = *(const float2*)(biasR1 + nf * 8 + bcol);
    }

    const int NT = PS / 64;   // 32
    for (int t = 0; t < NT; t++) {
        if (t < NT - 1) { CP_WAIT(1); } else { CP_WAIT(0); }
        __syncthreads();

        const uint32_t st = sb + AT_ST0 + (t % 3) * AT_STAGE;

        // consume prefetched bias, then prefetch next tile's bias
        float sc[8][4];
#pragma unroll
        for (int nf = 0; nf < 8; nf++) {
            sc[nf][0] = nb0[nf].x; sc[nf][1] = nb0[nf].y;
            sc[nf][2] = nb1[nf].x; sc[nf][3] = nb1[nf].y;
        }
        if (t + 1 < NT) {
            const int k1 = (t + 1) * 64;
#pragma unroll
            for (int nf = 0; nf < 8; nf++) {
                nb0[nf] = *(const float2*)(biasR0 + k1 + nf * 8 + bcol);
                nb1[nf] = *(const float2*)(biasR1 + k1 + nf * 8 + bcol);
            }
        }

        // ---- scores += Q K^T (split 3-combo), K via x4 pairs ----
#pragma unroll
        for (int ks = 0; ks < 8; ks++) {
            uint32_t qa[4], qla[4];
            ldm_x4(qa,  sb + AT_QH + q_off + ks * 32);
            ldm_x4(qla, sb + AT_QL + q_off + ks * 32);
#pragma unroll
            for (int nf2 = 0; nf2 < 4; nf2++) {
                uint32_t kbh[4], kbl[4];
                ldm_x4(kbh, st + k4_off + nf2 * 16 * AT_LDB + ks * 32);
                ldm_x4(kbl, st + AT_TILE + k4_off + nf2 * 16 * AT_LDB + ks * 32);
                mma_bf16(sc[2*nf2],   qa,  kbh);
                mma_bf16(sc[2*nf2+1], qa,  kbh + 2);
                mma_bf16(sc[2*nf2],   qa,  kbl);
                mma_bf16(sc[2*nf2+1], qa,  kbl + 2);
                mma_bf16(sc[2*nf2],   qla, kbh);
                mma_bf16(sc[2*nf2+1], qla, kbh + 2);
            }
        }

        // ---- online softmax: max ----
        float mx0 = sc[0][0], mx1 = sc[0][2];
#pragma unroll
        for (int nf = 0; nf < 8; nf++) {
            mx0 = fmaxf(mx0, fmaxf(sc[nf][0], sc[nf][1]));
            mx1 = fmaxf(mx1, fmaxf(sc[nf][2], sc[nf][3]));
        }
        mx0 = fmaxf(mx0, __shfl_xor_sync(0xffffffffu, mx0, 1));
        mx0 = fmaxf(mx0, __shfl_xor_sync(0xffffffffu, mx0, 2));
        mx1 = fmaxf(mx1, __shfl_xor_sync(0xffffffffu, mx1, 1));
        mx1 = fmaxf(mx1, __shfl_xor_sync(0xffffffffu, mx1, 2));
        const float mn0 = fmaxf(m0, mx0), mn1 = fmaxf(m1, mx1);
        const float mL0 = mn0 * L2E, mL1 = mn1 * L2E;
        const float al0 = ex2f((m0 - mn0) * L2E);
        const float al1 = ex2f((m1 - mn1) * L2E);
        m0 = mn0; m1 = mn1;

        // ---- rescale o and l accumulators (skip when max unchanged) ----
        if (al0 != 1.0f || al1 != 1.0f) {
#pragma unroll
            for (int nd = 0; nd < 16; nd++) {
                o[nd][0] *= al0; o[nd][1] *= al0;
                o[nd][2] *= al1; o[nd][3] *= al1;
            }
            lacc[0] *= al0; lacc[1] *= al0;
            lacc[2] *= al1; lacc[3] *= al1;
        }

        // ---- PV with P exp/pack interleaved per key-group:
        //      scalar exp of group j2 issues while group j2-1's MMAs drain ----
#pragma unroll
        for (int j2 = 0; j2 < 4; j2++) {
            const int f0 = 2 * j2, f1 = f0 + 1;
            uint32_t pf[4];
            pf[0] = h2ex2(fmaf(sc[f0][0], L2E, -mL0), fmaf(sc[f0][1], L2E, -mL0));
            pf[1] = h2ex2(fmaf(sc[f0][2], L2E, -mL1), fmaf(sc[f0][3], L2E, -mL1));
            pf[2] = h2ex2(fmaf(sc[f1][0], L2E, -mL0), fmaf(sc[f1][1], L2E, -mL0));
            pf[3] = h2ex2(fmaf(sc[f1][2], L2E, -mL1), fmaf(sc[f1][3], L2E, -mL1));
            mma_f16(lacc, pf, ONESB);
            const uint32_t vrow = st + 2 * AT_TILE + v4_off + j2 * 16 * AT_LDB;
#pragma unroll
            for (int nd2 = 0; nd2 < 8; nd2++) {
                uint32_t vbh[4];
                ldm_x4t(vbh, vrow + nd2 * 32);
                mma_f16(o[2*nd2],   pf, vbh);
                mma_f16(o[2*nd2+1], pf, vbh + 2);
            }
        }

        if (t + 2 < NT) {
            load_stage((t + 2) % 3, t + 2);
            CP_COMMIT();
        }
    }

    // ---- epilogue: normalize, split fp16, store ctx ----
    const float inv0 = 1.0f / lacc[0], inv1 = 1.0f / lacc[2];
    const int rg0 = q0 + warp * 16 + (lane >> 2);
    __half* och = Ch + base;
    __half* ocl = Cl + base;
#pragma unroll
    for (int nd = 0; nd < 16; nd++) {
        const int col = nd * 8 + (lane & 3) * 2;
        uint32_t hp, lp;
        packsplit_f16(o[nd][0] * inv0, o[nd][1] * inv0, hp, lp);
        *(uint32_t*)(och + (size_t)rg0 * PHID + col) = hp;
        *(uint32_t*)(ocl + (size_t)rg0 * PHID + col) = lp;
        packsplit_f16(o[nd][2] * inv1, o[nd][3] * inv1, hp, lp);
        *(uint32_t*)(och + (size_t)(rg0 + 8) * PHID + col) = hp;
        *(uint32_t*)(ocl + (size_t)(rg0 + 8) * PHID + col) = lp;
    }
}

// ---------------------------------------------------------------------------
extern "C" void kernel_launch(void* const* d_in, const int* in_sizes, int n_in,
                              void* d_out, int out_size)
{
    (void)in_sizes; (void)n_in; (void)out_size;
    const float* x    = (const float*)d_in[0];
    const float* bias = (const float*)d_in[1];
    const float* Wq   = (const float*)d_in[2];
    const float* bq   = (const float*)d_in[3];
    const float* Wk   = (const float*)d_in[4];
    const float* bk   = (const float*)d_in[5];
    const float* Wv   = (const float*)d_in[6];
    const float* bv   = (const float*)d_in[7];
    const float* Wo   = (const float*)d_in[8];
    const float* bo   = (const float*)d_in[9];
    float* out = (float*)d_out;

    __nv_bfloat16 *xh, *xl, *qh, *ql, *kh, *kl;
    __half *xh2, *xl2, *vhf, *ch2, *cl2, *wvt, *wot;
    __nv_bfloat16 *wqh, *wql, *wkh, *wkl;
    cudaGetSymbolAddress((void**)&xh, g_xh);
    cudaGetSymbolAddress((void**)&xl, g_xl);
    cudaGetSymbolAddress((void**)&xh2, g_xh2);
    cudaGetSymbolAddress((void**)&xl2, g_xl2);
    cudaGetSymbolAddress((void**)&qh, g_qh);
    cudaGetSymbolAddress((void**)&ql, g_ql);
    cudaGetSymbolAddress((void**)&kh, g_kh);
    cudaGetSymbolAddress((void**)&kl, g_kl);
    cudaGetSymbolAddress((void**)&vhf, g_vhf);
    cudaGetSymbolAddress((void**)&ch2, g_ch2);
    cudaGetSymbolAddress((void**)&cl2, g_cl2);
    cudaGetSymbolAddress((void**)&wqh, g_wqh);
    cudaGetSymbolAddress((void**)&wql, g_wql);
    cudaGetSymbolAddress((void**)&wkh, g_wkh);
    cudaGetSymbolAddress((void**)&wkl, g_wkl);
    cudaGetSymbolAddress((void**)&wvt, g_wvt);
    cudaGetSymbolAddress((void**)&wot, g_wot);

    static bool attr_set = false;
    if (!attr_set) {
        cudaFuncSetAttribute(gemm_qk,
                             cudaFuncAttributeMaxDynamicSharedMemorySize, QK_SMEM);
        cudaFuncSetAttribute(gemm_f16_2c,
                             cudaFuncAttributeMaxDynamicSharedMemorySize, GSMEM2);
        cudaFuncSetAttribute(attn_mma,
                             cudaFuncAttributeMaxDynamicSharedMemorySize, AT_SMEM);
        attr_set = true;
    }

    // 1) conversions
    {
        int n4 = PM * PHID / 4;
        split_x_kernel<<<(n4 + 255) / 256, 256>>>(x, xh, xl, xh2, xl2, n4);
        dim3 tg(PHID / 32, PHID / 32, 4);
        dim3 tb(32, 8);
        transpose_all_kernel<<<tg, tb>>>(Wq, Wk, Wv, Wo,
                                         wqh, wql, wkh, wkl, wvt, wot);
    }

    // 2) projections
    dim3 qkgrid(2 * PHID / 128, PM / 128);    // (32, 32)
    gemm_qk<<<qkgrid, 256, QK_SMEM>>>(xh, xl, wqh, wql, wkh, wkl,
                                      bq, bk, qh, ql, kh, kl);
    dim3 vgrid(PHID / 128, PM / 128);         // (16, 32)
    gemm_f16_2c<<<vgrid, 256, GSMEM2>>>(xh2, xl2, wvt, bv, nullptr, vhf);

    // 3) tensor-core attention -> split fp16 ctx
    dim3 agrid(PS / 128, PB * PH);            // (16, 32)
    attn_mma<<<agrid, 256, AT_SMEM>>>(qh, ql, kh, kl, vhf, bias, ch2, cl2);

    // 4) output projection -> fp32 out
    gemm_f16_2c<<<vgrid, 256, GSMEM2>>>(ch2, cl2, wot, bo, out, nullptr);
}

// round 14
// speedup vs baseline: 4.2821x; 1.0162x over previous
#include <cuda_runtime.h>
#include <cuda_bf16.h>
#include <cuda_fp16.h>
#include <math.h>
#include <stdint.h>

// Problem constants
#define PB   2
#define PS   2048
#define PHID 2048
#define PH   16
#define PD   128
#define PM   (PB * PS)          // 4096 rows
#define QSCALE 11.313708498984760f   // sqrt(128)

// ---------------------------------------------------------------------------
// Scratch (no cudaMalloc allowed)
// ---------------------------------------------------------------------------
__device__ __nv_bfloat16 g_xh[(size_t)PM * PHID];    // x split bf16 (QK path)
__device__ __nv_bfloat16 g_xl[(size_t)PM * PHID];
__device__ __half        g_xh2[(size_t)PM * PHID];   // x split fp16 (V path)
__device__ __half        g_xl2[(size_t)PM * PHID];
__device__ __nv_bfloat16 g_qh[(size_t)PM * PHID];
__device__ __nv_bfloat16 g_ql[(size_t)PM * PHID];
__device__ __nv_bfloat16 g_kh[(size_t)PM * PHID];
__device__ __nv_bfloat16 g_kl[(size_t)PM * PHID];
__device__ __half        g_vhf[(size_t)PM * PHID];   // V, fp16
__device__ __half        g_ch2[(size_t)PM * PHID];   // ctx split fp16
__device__ __half        g_cl2[(size_t)PM * PHID];

// transposed weights [N,K]
__device__ __nv_bfloat16 g_wqh[(size_t)PHID * PHID];
__device__ __nv_bfloat16 g_wql[(size_t)PHID * PHID];
__device__ __nv_bfloat16 g_wkh[(size_t)PHID * PHID];
__device__ __nv_bfloat16 g_wkl[(size_t)PHID * PHID];
__device__ __half        g_wvt[(size_t)PHID * PHID]; // Wv^T single fp16
__device__ __half        g_wot[(size_t)PHID * PHID]; // Wo^T single fp16

// ---------------------------------------------------------------------------
// Helpers
// ---------------------------------------------------------------------------
__device__ __forceinline__ uint32_t smem_u32(const void* p) {
    uint32_t a;
    asm("{ .reg .u64 t; cvta.to.shared.u64 t, %1; cvt.u32.u64 %0, t; }"
        : "=r"(a) : "l"(p));
    return a;
}

__device__ __forceinline__ void cp16(uint32_t s, const void* g) {
    asm volatile("cp.async.cg.shared.global [%0], [%1], 16;" :: "r"(s), "l"(g));
}
#define CP_COMMIT() asm volatile("cp.async.commit_group;" ::: "memory")
#define CP_WAIT(n)  asm volatile("cp.async.wait_group %0;" :: "n"(n) : "memory")

__device__ __forceinline__ void ldm_x4(uint32_t* r, uint32_t addr) {
    asm volatile("ldmatrix.sync.aligned.m8n8.x4.shared.b16 {%0,%1,%2,%3}, [%4];"
                 : "=r"(r[0]), "=r"(r[1]), "=r"(r[2]), "=r"(r[3]) : "r"(addr));
}
__device__ __forceinline__ void ldm_x4t(uint32_t* r, uint32_t addr) {
    asm volatile("ldmatrix.sync.aligned.m8n8.x4.trans.shared.b16 {%0,%1,%2,%3}, [%4];"
                 : "=r"(r[0]), "=r"(r[1]), "=r"(r[2]), "=r"(r[3]) : "r"(addr));
}
__device__ __forceinline__ void mma_bf16(float* c, const uint32_t* a, const uint32_t* b) {
    asm volatile(
        "mma.sync.aligned.m16n8k16.row.col.f32.bf16.bf16.f32 "
        "{%0,%1,%2,%3}, {%4,%5,%6,%7}, {%8,%9}, {%0,%1,%2,%3};"
        : "+f"(c[0]), "+f"(c[1]), "+f"(c[2]), "+f"(c[3])
        : "r"(a[0]), "r"(a[1]), "r"(a[2]), "r"(a[3]), "r"(b[0]), "r"(b[1]));
}
__device__ __forceinline__ void mma_f16(float* c, const uint32_t* a, const uint32_t* b) {
    asm volatile(
        "mma.sync.aligned.m16n8k16.row.col.f32.f16.f16.f32 "
        "{%0,%1,%2,%3}, {%4,%5,%6,%7}, {%8,%9}, {%0,%1,%2,%3};"
        : "+f"(c[0]), "+f"(c[1]), "+f"(c[2]), "+f"(c[3])
        : "r"(a[0]), "r"(a[1]), "r"(a[2]), "r"(a[3]), "r"(b[0]), "r"(b[1]));
}

__device__ __forceinline__ float ex2f(float x) {
    float r;
    asm("ex2.approx.f32 %0, %1;" : "=f"(r) : "f"(x));
    return r;
}

// pack two fp32 exponent args into f16x2 and take 2^x on both at once
__device__ __forceinline__ uint32_t h2ex2(float y0, float y1) {
    uint32_t h, p;
    asm("cvt.rn.f16x2.f32 %0, %1, %2;" : "=r"(h) : "f"(y1), "f"(y0));
    asm("ex2.approx.f16x2 %0, %1;" : "=r"(p) : "r"(h));
    return p;
}

// Fast RNE split of two floats into (hi bf16x2, lo bf16x2).
__device__ __forceinline__ void packsplit(float a, float b, uint32_t& hp, uint32_t& lp) {
    asm("cvt.rn.bf16x2.f32 %0, %1, %2;" : "=r"(hp) : "f"(b), "f"(a));
    float ah = __uint_as_float(hp << 16);
    float bh = __uint_as_float(hp & 0xFFFF0000u);
    float la = a - ah;
    float lb = b - bh;
    asm("cvt.rn.bf16x2.f32 %0, %1, %2;" : "=r"(lp) : "f"(lb), "f"(la));
}

// RNE split of two floats into (hi f16x2, lo f16x2).
__device__ __forceinline__ void packsplit_f16(float a, float b, uint32_t& hp, uint32_t& lp) {
    __half2 h = __floats2half2_rn(a, b);
    float la = a - __half2float(__low2half(h));
    float lb = b - __half2float(__high2half(h));
    __half2 l = __floats2half2_rn(la, lb);
    hp = *reinterpret_cast<uint32_t*>(&h);
    lp = *reinterpret_cast<uint32_t*>(&l);
}

// ---------------------------------------------------------------------------
// Conversion kernels
// ---------------------------------------------------------------------------
__global__ void split_x_kernel(const float* __restrict__ in,
                               __nv_bfloat16* __restrict__ hb,
                               __nv_bfloat16* __restrict__ lb,
                               __half* __restrict__ hf,
                               __half* __restrict__ lf, int n4)
{
    int i = blockIdx.x * blockDim.x + threadIdx.x;
    if (i >= n4) return;
    float4 v = ((const float4*)in)[i];
    uint32_t h0, l0, h1, l1;
    packsplit(v.x, v.y, h0, l0);
    packsplit(v.z, v.w, h1, l1);
    ((uint32_t*)hb)[2*i]   = h0;
    ((uint32_t*)hb)[2*i+1] = h1;
    ((uint32_t*)lb)[2*i]   = l0;
    ((uint32_t*)lb)[2*i+1] = l1;
    packsplit_f16(v.x, v.y, h0, l0);
    packsplit_f16(v.z, v.w, h1, l1);
    ((uint32_t*)hf)[2*i]   = h0;
    ((uint32_t*)hf)[2*i+1] = h1;
    ((uint32_t*)lf)[2*i]   = l0;
    ((uint32_t*)lf)[2*i+1] = l1;
}

// One launch transposes all 4 weight matrices.  z=0,1 -> bf16 split (Wq, Wk);
// z=2,3 -> single fp16 (Wv, Wo).
__global__ void transpose_all_kernel(
    const float* __restrict__ Wq, const float* __restrict__ Wk,
    const float* __restrict__ Wv, const float* __restrict__ Wo,
    __nv_bfloat16* __restrict__ Tqh, __nv_bfloat16* __restrict__ Tql,
    __nv_bfloat16* __restrict__ Tkh, __nv_bfloat16* __restrict__ Tkl,
    __half* __restrict__ Tv, __half* __restrict__ To)
{
    __shared__ float t[32][33];
    int z = blockIdx.z;
    const float* W = (z == 0) ? Wq : (z == 1) ? Wk : (z == 2) ? Wv : Wo;
    int n0 = blockIdx.x * 32, k0 = blockIdx.y * 32;
    int tx = threadIdx.x, ty0 = threadIdx.y;   // 32 x 8
#pragma unroll
    for (int j = 0; j < 32; j += 8)
        t[ty0 + j][tx] = W[(size_t)(k0 + ty0 + j) * PHID + n0 + tx];
    __syncthreads();
#pragma unroll
    for (int j = 0; j < 32; j += 8) {
        int n = ty0 + j;
        float v = t[tx][n];
        size_t o = (size_t)(n0 + n) * PHID + k0 + tx;
        if (z < 2) {
            __nv_bfloat16 h = __float2bfloat16(v);
            __nv_bfloat16 l = __float2bfloat16(v - __bfloat162float(h));
            if (z == 0) { Tqh[o] = h; Tql[o] = l; }
            else        { Tkh[o] = h; Tkl[o] = l; }
        } else {
            __half h = __float2half_rn(v);
            if (z == 2) Tv[o] = h; else To[o] = h;
        }
    }
}

// ---------------------------------------------------------------------------
// GEMM tile configs
// ---------------------------------------------------------------------------
#define LDT   40
#define TILE_B (128 * LDT * 2)   // 10240
#define OFF_AH 0
#define OFF_AL (TILE_B)
#define OFF_BH (2 * TILE_B)
#define OFF_BL (3 * TILE_B)

#define STAGE2_B (3 * TILE_B)    // 30720 (fp16 2-combo: Ah, Al, B)
#define GSMEM2 (3 * STAGE2_B)    // 92160 (3-stage pipeline)

// gemm_qk 4-stage BK=16 ring: tile = 128 rows x 48B (16 bf16 + 8 pad)
#define QK_TILE  6144
#define QK_AH    0
#define QK_AL    (QK_TILE)
#define QK_BH    (2 * QK_TILE)
#define QK_BL    (3 * QK_TILE)
#define QK_STAGE (4 * QK_TILE)   // 24576
#define QK_SMEM  (4 * QK_STAGE)  // 98304

// ---------------------------------------------------------------------------
// Q/K projection GEMM (split-bf16, 3 combos): sel = blockIdx.x>>4 in {0,1}.
// 4-stage BK=16 ring, ONE __syncthreads per chunk, 3-chunk prefetch.
// ---------------------------------------------------------------------------
__global__ __launch_bounds__(256, 2) void gemm_qk(
    const __nv_bfloat16* __restrict__ Ah, const __nv_bfloat16* __restrict__ Al,
    const __nv_bfloat16* __restrict__ Wqh, const __nv_bfloat16* __restrict__ Wql,
    const __nv_bfloat16* __restrict__ Wkh, const __nv_bfloat16* __restrict__ Wkl,
    const float* __restrict__ bq, const float* __restrict__ bk,
    __nv_bfloat16* __restrict__ Qh, __nv_bfloat16* __restrict__ Ql,
    __nv_bfloat16* __restrict__ Kh, __nv_bfloat16* __restrict__ Kl)
{
    extern __shared__ char smem[];
    const uint32_t sb = smem_u32(smem);
    const int tid  = threadIdx.x;
    const int lane = tid & 31;
    const int warp = tid >> 5;
    const int wm = warp >> 2;
    const int wn = warp & 3;
    const int sel = blockIdx.x >> 4;            // 0=Q 1=K
    const int n0  = (blockIdx.x & 15) * 128;
    const int m0  = blockIdx.y * 128;

    const __nv_bfloat16* Bh = sel ? Wkh : Wqh;
    const __nv_bfloat16* Bl = sel ? Wkl : Wql;
    const float* bias = sel ? bk : bq;
    const float scale = sel ? 1.0f : QSCALE;

    const __nv_bfloat16* pAh = Ah + (size_t)m0 * PHID;
    const __nv_bfloat16* pAl = Al + (size_t)m0 * PHID;
    const __nv_bfloat16* pBh = Bh + (size_t)n0 * PHID;
    const __nv_bfloat16* pBl = Bl + (size_t)n0 * PHID;

    // loader: 256 threads, one 16B chunk per tile each
    const int r0 = tid >> 1;               // 0..127
    const int ce = (tid & 1) * 8;          // elem col within 16
    const uint32_t so = (uint32_t)(r0 * 48 + (tid & 1) * 16);

    const uint32_t a_off = (uint32_t)((wm * 64 + (lane & 15)) * 48 + ((lane >> 4) << 4));
    const uint32_t b4_off = (uint32_t)((wn * 32 + ((lane >> 4) << 3) + (lane & 7)) * 48
                                       + ((lane & 8) ? 16 : 0));

    float acc[4][4][4];
#pragma unroll
    for (int mi = 0; mi < 4; mi++)
#pragma unroll
        for (int ni = 0; ni < 4; ni++)
#pragma unroll
            for (int j = 0; j < 4; j++) acc[mi][ni][j] = 0.0f;

    auto load_stage = [&](int stage, int kc) {
        const uint32_t st = sb + stage * QK_STAGE;
        const size_t g = (size_t)r0 * PHID + kc * 16 + ce;
        cp16(st + QK_AH + so, pAh + g);
        cp16(st + QK_AL + so, pAl + g);
        cp16(st + QK_BH + so, pBh + g);
        cp16(st + QK_BL + so, pBl + g);
    };

    auto compute_stage = [&](int stage) {
        const uint32_t st = sb + stage * QK_STAGE;
        uint32_t bh0[4], bh1[4], bl0[4], bl1[4], a[4][4];
        ldm_x4(bh0, st + QK_BH + b4_off);
        ldm_x4(bh1, st + QK_BH + b4_off + 768);
        ldm_x4(bl0, st + QK_BL + b4_off);
        ldm_x4(bl1, st + QK_BL + b4_off + 768);
#pragma unroll
        for (int mi = 0; mi < 4; mi++)
            ldm_x4(a[mi], st + QK_AH + a_off + mi * 768);
#pragma unroll
        for (int mi = 0; mi < 4; mi++) {
            mma_bf16(acc[mi][0], a[mi], bh0);
            mma_bf16(acc[mi][1], a[mi], bh0 + 2);
            mma_bf16(acc[mi][2], a[mi], bh1);
            mma_bf16(acc[mi][3], a[mi], bh1 + 2);
        }
#pragma unroll
        for (int mi = 0; mi < 4; mi++) {
            mma_bf16(acc[mi][0], a[mi], bl0);
            mma_bf16(acc[mi][1], a[mi], bl0 + 2);
            mma_bf16(acc[mi][2], a[mi], bl1);
            mma_bf16(acc[mi][3], a[mi], bl1 + 2);
        }
#pragma unroll
        for (int mi = 0; mi < 4; mi++)
            ldm_x4(a[mi], st + QK_AL + a_off + mi * 768);
#pragma unroll
        for (int mi = 0; mi < 4; mi++) {
            mma_bf16(acc[mi][0], a[mi], bh0);
            mma_bf16(acc[mi][1], a[mi], bh0 + 2);
            mma_bf16(acc[mi][2], a[mi], bh1);
            mma_bf16(acc[mi][3], a[mi], bh1 + 2);
        }
    };

    load_stage(0, 0);
    CP_COMMIT();
    load_stage(1, 1);
    CP_COMMIT();
    load_stage(2, 2);
    CP_COMMIT();
    const int NKC = PHID / 16;   // 128
    for (int kc = 0; kc < NKC; kc++) {
        if (kc < NKC - 2)      { CP_WAIT(2); }
        else if (kc == NKC - 2){ CP_WAIT(1); }
        else                   { CP_WAIT(0); }
        __syncthreads();
        compute_stage(kc & 3);
        if (kc + 3 < NKC) {
            load_stage((kc + 3) & 3, kc + 3);
            CP_COMMIT();
        }
    }

    __nv_bfloat16* Oh = sel ? Kh : Qh;
    __nv_bfloat16* Ol = sel ? Kl : Ql;
#pragma unroll
    for (int mi = 0; mi < 4; mi++) {
        const int row = m0 + wm * 64 + mi * 16 + (lane >> 2);
#pragma unroll
        for (int ni = 0; ni < 4; ni++) {
            const int col = n0 + wn * 32 + ni * 8 + (lane & 3) * 2;
            const float b0 = bias[col], b1 = bias[col + 1];
            float v00 = (acc[mi][ni][0] + b0) * scale;
            float v01 = (acc[mi][ni][1] + b1) * scale;
            float v10 = (acc[mi][ni][2] + b0) * scale;
            float v11 = (acc[mi][ni][3] + b1) * scale;
            uint32_t hp, lp;
            packsplit(v00, v01, hp, lp);
            *(uint32_t*)(Oh + (size_t)row * PHID + col) = hp;
            *(uint32_t*)(Ol + (size_t)row * PHID + col) = lp;
            packsplit(v10, v11, hp, lp);
            *(uint32_t*)(Oh + (size_t)(row + 8) * PHID + col) = hp;
            *(uint32_t*)(Ol + (size_t)(row + 8) * PHID + col) = lp;
        }
    }
}

// ---------------------------------------------------------------------------
// fp16 2-combo GEMM: C = (Ah + Al) @ B^T + bias.  3-stage pipeline,
// ONE __syncthreads per K-chunk.
// ---------------------------------------------------------------------------
__global__ __launch_bounds__(256, 2) void gemm_f16_2c(
    const __half* __restrict__ Ah, const __half* __restrict__ Al,
    const __half* __restrict__ Bt,
    const float* __restrict__ bias, float* __restrict__ Cf,
    __half* __restrict__ Co)
{
    extern __shared__ char smem[];
    const uint32_t sb = smem_u32(smem);
    const int tid  = threadIdx.x;
    const int lane = tid & 31;
    const int warp = tid >> 5;
    const int wm = warp >> 2;
    const int wn = warp & 3;
    const int m0 = blockIdx.y * 128;
    const int n0 = blockIdx.x * 128;

    const __half* pAh = Ah + (size_t)m0 * PHID;
    const __half* pAl = Al + (size_t)m0 * PHID;
    const __half* pB  = Bt + (size_t)n0 * PHID;

    const int r0 = tid >> 2;
    const int c0 = (tid & 3) * 8;
    const uint32_t so0 = (uint32_t)(r0 * 80 + (tid & 3) * 16);
    const uint32_t so1 = (uint32_t)((r0 + 64) * 80 + (tid & 3) * 16);

    const uint32_t a_off = (uint32_t)((wm * 64 + (lane & 15)) * 80 + ((lane >> 4) << 4));
    const uint32_t b4_off = (uint32_t)((wn * 32 + ((lane >> 4) << 3) + (lane & 7)) * 80
                                       + ((lane & 8) ? 16 : 0));

    float acc[4][4][4];
#pragma unroll
    for (int mi = 0; mi < 4; mi++)
#pragma unroll
        for (int ni = 0; ni < 4; ni++)
#pragma unroll
            for (int j = 0; j < 4; j++) acc[mi][ni][j] = 0.0f;

    auto load_stage = [&](int stage, int kc) {
        const uint32_t st = sb + stage * STAGE2_B;
        const size_t g0 = (size_t)r0 * PHID + kc * 32 + c0;
        const size_t g1 = (size_t)(r0 + 64) * PHID + kc * 32 + c0;
        cp16(st + OFF_AH + so0, pAh + g0);
        cp16(st + OFF_AH + so1, pAh + g1);
        cp16(st + OFF_AL + so0, pAl + g0);
        cp16(st + OFF_AL + so1, pAl + g1);
        cp16(st + OFF_BH + so0, pB + g0);
        cp16(st + OFF_BH + so1, pB + g1);
    };

    auto compute_stage = [&](int stage) {
        const uint32_t st = sb + stage * STAGE2_B;
#pragma unroll
        for (int ks = 0; ks < 2; ks++) {
            const uint32_t k32 = ks * 32;
            uint32_t bf[4][2], a[4][4];
            ldm_x4(&bf[0][0], st + OFF_BH + b4_off + k32);
            ldm_x4(&bf[2][0], st + OFF_BH + b4_off + 1280 + k32);
#pragma unroll
            for (int mi = 0; mi < 4; mi++)
                ldm_x4(a[mi], st + OFF_AH + a_off + mi * 1280 + k32);
#pragma unroll
            for (int mi = 0; mi < 4; mi++)
#pragma unroll
                for (int ni = 0; ni < 4; ni++)
                    mma_f16(acc[mi][ni], a[mi], bf[ni]);
#pragma unroll
            for (int mi = 0; mi < 4; mi++)
                ldm_x4(a[mi], st + OFF_AL + a_off + mi * 1280 + k32);
#pragma unroll
            for (int mi = 0; mi < 4; mi++)
#pragma unroll
                for (int ni = 0; ni < 4; ni++)
                    mma_f16(acc[mi][ni], a[mi], bf[ni]);
        }
    };

    load_stage(0, 0);
    CP_COMMIT();
    load_stage(1, 1);
    CP_COMMIT();
    const int NKC = PHID / 32;   // 64
    for (int kc = 0; kc < NKC; kc++) {
        if (kc < NKC - 1) { CP_WAIT(1); } else { CP_WAIT(0); }
        __syncthreads();
        compute_stage(kc % 3);
        if (kc + 2 < NKC) {
            load_stage((kc + 2) % 3, kc + 2);
            CP_COMMIT();
        }
    }

#pragma unroll
    for (int mi = 0; mi < 4; mi++) {
        const int row = m0 + wm * 64 + mi * 16 + (lane >> 2);
#pragma unroll
        for (int ni = 0; ni < 4; ni++) {
            const int col = n0 + wn * 32 + ni * 8 + (lane & 3) * 2;
            const float b0 = bias[col], b1 = bias[col + 1];
            float v00 = acc[mi][ni][0] + b0;
            float v01 = acc[mi][ni][1] + b1;
            float v10 = acc[mi][ni][2] + b0;
            float v11 = acc[mi][ni][3] + b1;
            if (Cf) {
                *(float2*)(Cf + (size_t)row * PHID + col)       = make_float2(v00, v01);
                *(float2*)(Cf + (size_t)(row + 8) * PHID + col) = make_float2(v10, v11);
            } else {
                __half2 p0 = __floats2half2_rn(v00, v01);
                __half2 p1 = __floats2half2_rn(v10, v11);
                *(uint32_t*)(Co + (size_t)row * PHID + col) =
                    *reinterpret_cast<uint32_t*>(&p0);
                *(uint32_t*)(Co + (size_t)(row + 8) * PHID + col) =
                    *reinterpret_cast<uint32_t*>(&p1);
            }
        }
    }
}

// ---------------------------------------------------------------------------
// Tensor-core flash attention, 2 CTAs/SM: CTA = 128 threads (4 warps),
// 64 q-rows, 32-key K/V tiles, 3-stage ring, 1 barrier per tile.
// QK split-bf16 (3 combos), PV fp16 (1 combo), P via f16x2 MUFU exp,
// row sums via ones-MMA, ctx out split fp16.
// smem: Q 64x272x2 = 34816 + 3 stages x (3 x 32 x 272) = 78336 -> 113152 B.
// ---------------------------------------------------------------------------
#define A2_LDB  272
#define A2_QH   0
#define A2_QL   (64 * A2_LDB)             // 17408
#define A2_ST0  (2 * 64 * A2_LDB)         // 34816
#define A2_TILE (32 * A2_LDB)             // 8704
#define A2_STAGE (3 * A2_TILE)            // 26112
#define A2_SMEM (A2_ST0 + 3 * A2_STAGE)   // 113152

__global__ __launch_bounds__(128, 2) void attn_mma(
    const __nv_bfloat16* __restrict__ Qh, const __nv_bfloat16* __restrict__ Ql,
    const __nv_bfloat16* __restrict__ Kh, const __nv_bfloat16* __restrict__ Kl,
    const __half* __restrict__ Vh,
    const float* __restrict__ Bias,
    __half* __restrict__ Ch, __half* __restrict__ Cl)
{
    extern __shared__ char smem[];
    const uint32_t sb = smem_u32(smem);
    const int tid = threadIdx.x;
    const int lane = tid & 31;
    const int warp = tid >> 5;          // 0..3
    const int bh = blockIdx.y;
    const int b  = bh >> 4;
    const int h  = bh & 15;
    const int q0 = blockIdx.x * 64;
    const float L2E = 1.44269504f;

    const size_t base = (size_t)b * PS * PHID + (size_t)h * PD;
    const __nv_bfloat16* pQh = Qh + base + (size_t)q0 * PHID;
    const __nv_bfloat16* pQl = Ql + base + (size_t)q0 * PHID;
    const __nv_bfloat16* pKh = Kh + base;
    const __nv_bfloat16* pKl = Kl + base;
    const __half* pVh = Vh + base;

    // Q loader: 64 rows x 16 chunks x 2 tensors, 128 threads -> 8 each/tensor
    {
        const int r = tid >> 1;                 // 0..63
        const int ce = (tid & 1) * 64;
        const uint32_t so = (uint32_t)(r * A2_LDB + (tid & 1) * 128);
#pragma unroll
        for (int i = 0; i < 8; i++) {
            cp16(sb + A2_QH + so + i * 16, pQh + (size_t)r * PHID + ce + i * 8);
            cp16(sb + A2_QL + so + i * 16, pQl + (size_t)r * PHID + ce + i * 8);
        }
    }

    // K/V stage loader (3 tiles of 32 rows: Kh, Kl, Vh)
    const int kvr  = tid >> 2;                  // 0..31
    const int kvce = (tid & 3) * 32;
    const uint32_t kvso = (uint32_t)(kvr * A2_LDB + (tid & 3) * 64);
    auto load_stage = [&](int stage, int t) {
        const uint32_t st = sb + A2_ST0 + stage * A2_STAGE;
        const size_t g = (size_t)(t * 32 + kvr) * PHID + kvce;
#pragma unroll
        for (int i = 0; i < 4; i++) {
            cp16(st + kvso + i * 16,               pKh + g + i * 8);
            cp16(st + A2_TILE + kvso + i * 16,     pKl + g + i * 8);
            cp16(st + 2 * A2_TILE + kvso + i * 16, pVh + g + i * 8);
        }
    };

    load_stage(0, 0);
    CP_COMMIT();
    load_stage(1, 1);
    CP_COMMIT();

    const uint32_t q_off = (uint32_t)((warp * 16 + (lane & 15)) * A2_LDB + ((lane >> 4) << 4));
    const uint32_t k4_off = (uint32_t)((((lane >> 4) << 3) + (lane & 7)) * A2_LDB
                                       + ((lane & 8) ? 16 : 0));
    const uint32_t v4_off = (uint32_t)((((lane >> 3) & 1) * 8 + (lane & 7)) * A2_LDB
                                       + (lane >> 4) * 16);

    const float* biasR0 = Bias + ((size_t)bh * PS + q0 + warp * 16 + (lane >> 2)) * PS;
    const float* biasR1 = biasR0 + 8 * PS;
    const int bcol = (lane & 3) * 2;

    float o[16][4];
#pragma unroll
    for (int nd = 0; nd < 16; nd++)
#pragma unroll
        for (int j = 0; j < 4; j++) o[nd][j] = 0.0f;
    float lacc[4] = {0.0f, 0.0f, 0.0f, 0.0f};
    float m0 = -1e30f, m1 = -1e30f;
    const uint32_t ONESB[2] = {0x3C003C00u, 0x3C003C00u};

    // bias prefetch registers (32 keys per tile -> 4 nf)
    float2 nb0[4], nb1[4];
#pragma unroll
    for (int nf = 0; nf < 4; nf++) {
        nb0[nf] = *(const float2*)(biasR0 + nf * 8 + bcol);
        nb1[nf] = *(const float2*)(biasR1 + nf * 8 + bcol);
    }

    const int NT = PS / 32;   // 64 tiles
    for (int t = 0; t < NT; t++) {
        if (t < NT - 1) { CP_WAIT(1); } else { CP_WAIT(0); }
        __syncthreads();

        const uint32_t st = sb + A2_ST0 + (t % 3) * A2_STAGE;

        // consume prefetched bias, then prefetch next tile's bias
        float sc[4][4];
#pragma unroll
        for (int nf = 0; nf < 4; nf++) {
            sc[nf][0] = nb0[nf].x; sc[nf][1] = nb0[nf].y;
            sc[nf][2] = nb1[nf].x; sc[nf][3] = nb1[nf].y;
        }
        if (t + 1 < NT) {
            const int k1 = (t + 1) * 32;
#pragma unroll
            for (int nf = 0; nf < 4; nf++) {
                nb0[nf] = *(const float2*)(biasR0 + k1 + nf * 8 + bcol);
                nb1[nf] = *(const float2*)(biasR1 + k1 + nf * 8 + bcol);
            }
        }

        // ---- scores += Q K^T (split 3-combo), K via x4 pairs ----
#pragma unroll
        for (int ks = 0; ks < 8; ks++) {
            uint32_t qa[4], qla[4];
            ldm_x4(qa,  sb + A2_QH + q_off + ks * 32);
            ldm_x4(qla, sb + A2_QL + q_off + ks * 32);
#pragma unroll
            for (int nf2 = 0; nf2 < 2; nf2++) {
                uint32_t kbh[4], kbl[4];
                ldm_x4(kbh, st + k4_off + nf2 * 16 * A2_LDB + ks * 32);
                ldm_x4(kbl, st + A2_TILE + k4_off + nf2 * 16 * A2_LDB + ks * 32);
                mma_bf16(sc[2*nf2],   qa,  kbh);
                mma_bf16(sc[2*nf2+1], qa,  kbh + 2);
                mma_bf16(sc[2*nf2],   qa,  kbl);
                mma_bf16(sc[2*nf2+1], qa,  kbl + 2);
                mma_bf16(sc[2*nf2],   qla, kbh);
                mma_bf16(sc[2*nf2+1], qla, kbh + 2);
            }
        }

        // ---- online softmax: max ----
        float mx0 = sc[0][0], mx1 = sc[0][2];
#pragma unroll
        for (int nf = 0; nf < 4; nf++) {
            mx0 = fmaxf(mx0, fmaxf(sc[nf][0], sc[nf][1]));
            mx1 = fmaxf(mx1, fmaxf(sc[nf][2], sc[nf][3]));
        }
        mx0 = fmaxf(mx0, __shfl_xor_sync(0xffffffffu, mx0, 1));
        mx0 = fmaxf(mx0, __shfl_xor_sync(0xffffffffu, mx0, 2));
        mx1 = fmaxf(mx1, __shfl_xor_sync(0xffffffffu, mx1, 1));
        mx1 = fmaxf(mx1, __shfl_xor_sync(0xffffffffu, mx1, 2));
        const float mn0 = fmaxf(m0, mx0), mn1 = fmaxf(m1, mx1);
        const float mL0 = mn0 * L2E, mL1 = mn1 * L2E;
        const float al0 = ex2f((m0 - mn0) * L2E);
        const float al1 = ex2f((m1 - mn1) * L2E);
        m0 = mn0; m1 = mn1;

        // ---- rescale o and l accumulators (skip when max unchanged) ----
        if (al0 != 1.0f || al1 != 1.0f) {
#pragma unroll
            for (int nd = 0; nd < 16; nd++) {
                o[nd][0] *= al0; o[nd][1] *= al0;
                o[nd][2] *= al1; o[nd][3] *= al1;
            }
            lacc[0] *= al0; lacc[1] *= al0;
            lacc[2] *= al1; lacc[3] *= al1;
        }

        // ---- PV: P exp/pack per 16-key group, then its MMAs ----
#pragma unroll
        for (int j2 = 0; j2 < 2; j2++) {
            const int f0 = 2 * j2, f1 = f0 + 1;
            uint32_t pf[4];
            pf[0] = h2ex2(fmaf(sc[f0][0], L2E, -mL0), fmaf(sc[f0][1], L2E, -mL0));
            pf[1] = h2ex2(fmaf(sc[f0][2], L2E, -mL1), fmaf(sc[f0][3], L2E, -mL1));
            pf[2] = h2ex2(fmaf(sc[f1][0], L2E, -mL0), fmaf(sc[f1][1], L2E, -mL0));
            pf[3] = h2ex2(fmaf(sc[f1][2], L2E, -mL1), fmaf(sc[f1][3], L2E, -mL1));
            mma_f16(lacc, pf, ONESB);
            const uint32_t vrow = st + 2 * A2_TILE + v4_off + j2 * 16 * A2_LDB;
#pragma unroll
            for (int nd2 = 0; nd2 < 8; nd2++) {
                uint32_t vbh[4];
                ldm_x4t(vbh, vrow + nd2 * 32);
                mma_f16(o[2*nd2],   pf, vbh);
                mma_f16(o[2*nd2+1], pf, vbh + 2);
            }
        }

        if (t + 2 < NT) {
            load_stage((t + 2) % 3, t + 2);
            CP_COMMIT();
        }
    }

    // ---- epilogue: normalize, split fp16, store ctx ----
    const float inv0 = 1.0f / lacc[0], inv1 = 1.0f / lacc[2];
    const int rg0 = q0 + warp * 16 + (lane >> 2);
    __half* och = Ch + base;
    __half* ocl = Cl + base;
#pragma unroll
    for (int nd = 0; nd < 16; nd++) {
        const int col = nd * 8 + (lane & 3) * 2;
        uint32_t hp, lp;
        packsplit_f16(o[nd][0] * inv0, o[nd][1] * inv0, hp, lp);
        *(uint32_t*)(och + (size_t)rg0 * PHID + col) = hp;
        *(uint32_t*)(ocl + (size_t)rg0 * PHID + col) = lp;
        packsplit_f16(o[nd][2] * inv1, o[nd][3] * inv1, hp, lp);
        *(uint32_t*)(och + (size_t)(rg0 + 8) * PHID + col) = hp;
        *(uint32_t*)(ocl + (size_t)(rg0 + 8) * PHID + col) = lp;
    }
}

// ---------------------------------------------------------------------------
extern "C" void kernel_launch(void* const* d_in, const int* in_sizes, int n_in,
                              void* d_out, int out_size)
{
    (void)in_sizes; (void)n_in; (void)out_size;
    const float* x    = (const float*)d_in[0];
    const float* bias = (const float*)d_in[1];
    const float* Wq   = (const float*)d_in[2];
    const float* bq   = (const float*)d_in[3];
    const float* Wk   = (const float*)d_in[4];
    const float* bk   = (const float*)d_in[5];
    const float* Wv   = (const float*)d_in[6];
    const float* bv   = (const float*)d_in[7];
    const float* Wo   = (const float*)d_in[8];
    const float* bo   = (const float*)d_in[9];
    float* out = (float*)d_out;

    __nv_bfloat16 *xh, *xl, *qh, *ql, *kh, *kl;
    __half *xh2, *xl2, *vhf, *ch2, *cl2, *wvt, *wot;
    __nv_bfloat16 *wqh, *wql, *wkh, *wkl;
    cudaGetSymbolAddress((void**)&xh, g_xh);
    cudaGetSymbolAddress((void**)&xl, g_xl);
    cudaGetSymbolAddress((void**)&xh2, g_xh2);
    cudaGetSymbolAddress((void**)&xl2, g_xl2);
    cudaGetSymbolAddress((void**)&qh, g_qh);
    cudaGetSymbolAddress((void**)&ql, g_ql);
    cudaGetSymbolAddress((void**)&kh, g_kh);
    cudaGetSymbolAddress((void**)&kl, g_kl);
    cudaGetSymbolAddress((void**)&vhf, g_vhf);
    cudaGetSymbolAddress((void**)&ch2, g_ch2);
    cudaGetSymbolAddress((void**)&cl2, g_cl2);
    cudaGetSymbolAddress((void**)&wqh, g_wqh);
    cudaGetSymbolAddress((void**)&wql, g_wql);
    cudaGetSymbolAddress((void**)&wkh, g_wkh);
    cudaGetSymbolAddress((void**)&wkl, g_wkl);
    cudaGetSymbolAddress((void**)&wvt, g_wvt);
    cudaGetSymbolAddress((void**)&wot, g_wot);

    static bool attr_set = false;
    if (!attr_set) {
        cudaFuncSetAttribute(gemm_qk,
                             cudaFuncAttributeMaxDynamicSharedMemorySize, QK_SMEM);
        cudaFuncSetAttribute(gemm_f16_2c,
                             cudaFuncAttributeMaxDynamicSharedMemorySize, GSMEM2);
        cudaFuncSetAttribute(attn_mma,
                             cudaFuncAttributeMaxDynamicSharedMemorySize, A2_SMEM);
        attr_set = true;
    }

    // 1) conversions
    {
        int n4 = PM * PHID / 4;
        split_x_kernel<<<(n4 + 255) / 256, 256>>>(x, xh, xl, xh2, xl2, n4);
        dim3 tg(PHID / 32, PHID / 32, 4);
        dim3 tb(32, 8);
        transpose_all_kernel<<<tg, tb>>>(Wq, Wk, Wv, Wo,
                                         wqh, wql, wkh, wkl, wvt, wot);
    }

    // 2) projections
    dim3 qkgrid(2 * PHID / 128, PM / 128);    // (32, 32)
    gemm_qk<<<qkgrid, 256, QK_SMEM>>>(xh, xl, wqh, wql, wkh, wkl,
                                      bq, bk, qh, ql, kh, kl);
    dim3 vgrid(PHID / 128, PM / 128);         // (16, 32)
    gemm_f16_2c<<<vgrid, 256, GSMEM2>>>(xh2, xl2, wvt, bv, nullptr, vhf);

    // 3) tensor-core attention (2 CTAs/SM) -> split fp16 ctx
    dim3 agrid(PS / 64, PB * PH);             // (32, 32)
    attn_mma<<<agrid, 128, A2_SMEM>>>(qh, ql, kh, kl, vhf, bias, ch2, cl2);

    // 4) output projection -> fp32 out
    gemm_f16_2c<<<vgrid, 256, GSMEM2>>>(ch2, cl2, wot, bo, out, nullptr);
}